// round 7
// baseline (speedup 1.0000x reference)
#include <cuda_runtime.h>
#include <math.h>
#include <stdint.h>

// ---------------- problem constants ----------------
namespace {
constexpr int NN   = 30000;   // nodes
constexpr int NE   = 480000;  // edges
constexpr int C    = 128;     // channels (= F)
constexpr int KG   = 8;       // gaussians
constexpr int LL   = 4;       // layers
constexpr int H    = 256;     // LSTM hidden
constexpr int H4   = 1024;    // 4*H
constexpr int NHID = 512;
constexpr int NOUT = 256;
constexpr int NB   = 1024;    // graphs
}

// ---------------- scratch (device globals; no allocations allowed) -------
__device__ __align__(256) float d_h[NN * C];
__device__ __align__(256) float d_hl[LL][NN * C];
__device__ __align__(256) float d_hlt[5][NN * C];     // tf32-valued x,h1..h4
__device__ __align__(256) float d_S[NN * KG * C];
__device__ __align__(256) float d_gt[LL][KG * C * C];
__device__ __align__(256) float d_ew[LL][NE * KG];
__device__ __align__(256) float d_bns[C];
__device__ __align__(256) float d_bnq[C];
__device__ __align__(256) float d_lh[2][2][NN * H];   // tf32-valued, [pp][dir]
__device__ __align__(256) float d_lc[2][NN * H];
__device__ __align__(256) float d_af[5 * NN];
__device__ __align__(256) float d_ab[5 * NN];
__device__ __align__(256) float d_nrep[NN * C];
__device__ __align__(256) float d_cnt[NB];
__device__ __align__(256) float d_hg[NB * C];
__device__ __align__(256) float d_z1[NB * NHID];
__device__ __align__(256) float d_z2[NB * NOUT];
// tf32-valued LSTM weights + fused biases
__device__ __align__(256) float d_wiht[2 * H4 * C];
__device__ __align__(256) float d_whht[2 * H4 * H];
__device__ __align__(256) float d_bsum[2 * H4];
// CSR scratch
__device__ __align__(256) int d_indeg[NN];
__device__ __align__(256) int d_rowptr[NN + 1];
__device__ __align__(256) int d_curp[NN];
__device__ __align__(256) int d_eid[NE];
__device__ __align__(256) int d_esrc[NE];

// ---------------- TF32 helpers ----------------
__device__ __forceinline__ uint32_t f2tf(float f) {
    uint32_t u;
    asm("cvt.rna.tf32.f32 %0, %1;" : "=r"(u) : "f"(f));
    return u;
}
__device__ __forceinline__ uint32_t tfw(uint32_t rawbits) {
    return f2tf(__uint_as_float(rawbits));
}
__device__ __forceinline__ void mma8(float* c, const uint32_t* a, const uint32_t* b) {
    asm volatile(
        "mma.sync.aligned.m16n8k8.row.col.f32.tf32.tf32.f32 "
        "{%0,%1,%2,%3}, {%4,%5,%6,%7}, {%8,%9}, {%0,%1,%2,%3};"
        : "+f"(c[0]), "+f"(c[1]), "+f"(c[2]), "+f"(c[3])
        : "r"(a[0]), "r"(a[1]), "r"(a[2]), "r"(a[3]), "r"(b[0]), "r"(b[1]));
}
__device__ __forceinline__ void cpa16(uint32_t sdst, const void* gsrc, int srcsz) {
    asm volatile("cp.async.ca.shared.global [%0], [%1], 16, %2;\n"
                 :: "r"(sdst), "l"(gsrc), "r"(srcsz));
}
__device__ __forceinline__ void cpa_commit() { asm volatile("cp.async.commit_group;\n"); }
__device__ __forceinline__ void cpa_wait1()  { asm volatile("cp.async.wait_group 1;\n"); }
__device__ __forceinline__ float sigf(float x) { return 1.f / (1.f + expf(-x)); }

// ---------------- generic TF32 GEMM (cp.async 2-stage, dual-K) ----------
struct GA {
    const float* A;
    const float* B;
    const float* A2;
    const float* B2;
    float* Cm;
};

template <bool TB, bool ACC, bool RELU_, bool BIAS_>
__global__ __launch_bounds__(256) void tgemm(
    GA g0, GA g1, const float* __restrict__ bias, int M, int Nm, int Kd, int Kd2)
{
    __shared__ uint32_t As[2][128 * 20];
    __shared__ uint32_t Bs[2][2560];

    const GA ga = blockIdx.z ? g1 : g0;
    const float* __restrict__ A  = ga.A;
    const float* __restrict__ B  = ga.B;
    const float* __restrict__ A2 = ga.A2;
    const float* __restrict__ B2 = ga.B2;
    float* __restrict__ Cm = ga.Cm;

    const int tid  = threadIdx.x;
    const int lane = tid & 31;
    const int wid  = tid >> 5;
    const int wm   = wid & 3;
    const int wn   = wid >> 2;
    const int gid  = lane >> 2;
    const int tig  = lane & 3;
    const int row0 = blockIdx.y * 128, col0 = blockIdx.x * 128;

    const int nt1 = Kd >> 4;
    const int nt  = nt1 + (Kd2 >> 4);

    float acc[2][8][4];
#pragma unroll
    for (int mi = 0; mi < 2; mi++)
#pragma unroll
        for (int ni = 0; ni < 8; ni++)
#pragma unroll
            for (int r = 0; r < 4; r++) acc[mi][ni][r] = 0.f;

    const int lr0 = tid >> 2, lc4 = (tid & 3) * 4;

    auto loadTile = [&](int t, int st) {
        const float* Ap; const float* Bp; int Kc, k0;
        if (t < nt1) { Ap = A;  Bp = B;  Kc = Kd;  k0 = t << 4; }
        else         { Ap = A2; Bp = B2; Kc = Kd2; k0 = (t - nt1) << 4; }
#pragma unroll
        for (int it = 0; it < 2; it++) {
            int rr = lr0 + it * 64;
            int gr = row0 + rr;
            uint32_t dst = (uint32_t)__cvta_generic_to_shared(&As[st][rr * 20 + lc4]);
            cpa16(dst, Ap + (size_t)gr * Kc + k0 + lc4, gr < M ? 16 : 0);
        }
        if (TB) {
#pragma unroll
            for (int it = 0; it < 2; it++) {
                int rr = lr0 + it * 64;
                uint32_t dst = (uint32_t)__cvta_generic_to_shared(&Bs[st][rr * 20 + lc4]);
                cpa16(dst, Bp + (size_t)(col0 + rr) * Kc + k0 + lc4, 16);
            }
        } else {
#pragma unroll
            for (int it = 0; it < 2; it++) {
                int idx = tid + it * 256;
                int kk = idx >> 5, n4 = (idx & 31) * 4;
                uint32_t dst = (uint32_t)__cvta_generic_to_shared(&Bs[st][kk * 136 + n4]);
                cpa16(dst, Bp + (size_t)(k0 + kk) * Nm + col0 + n4, 16);
            }
        }
    };

    loadTile(0, 0);
    cpa_commit();

    for (int t = 0; t < nt; t++) {
        if (t + 1 < nt) loadTile(t + 1, (t + 1) & 1);
        cpa_commit();
        cpa_wait1();
        __syncthreads();

        const int st = t & 1;
#pragma unroll
        for (int kk = 0; kk < 16; kk += 8) {
            uint32_t a[2][4], b[8][2];
#pragma unroll
            for (int mi = 0; mi < 2; mi++) {
                int mr = wm * 32 + mi * 16;
                a[mi][0] = tfw(As[st][(mr + gid)     * 20 + kk + tig]);
                a[mi][1] = tfw(As[st][(mr + gid + 8) * 20 + kk + tig]);
                a[mi][2] = tfw(As[st][(mr + gid)     * 20 + kk + tig + 4]);
                a[mi][3] = tfw(As[st][(mr + gid + 8) * 20 + kk + tig + 4]);
            }
#pragma unroll
            for (int ni = 0; ni < 8; ni++) {
                int nr = wn * 64 + ni * 8;
                if (TB) {
                    b[ni][0] = tfw(Bs[st][(nr + gid) * 20 + kk + tig]);
                    b[ni][1] = tfw(Bs[st][(nr + gid) * 20 + kk + tig + 4]);
                } else {
                    b[ni][0] = tfw(Bs[st][(kk + tig)     * 136 + nr + gid]);
                    b[ni][1] = tfw(Bs[st][(kk + tig + 4) * 136 + nr + gid]);
                }
            }
#pragma unroll
            for (int mi = 0; mi < 2; mi++)
#pragma unroll
                for (int ni = 0; ni < 8; ni++)
                    mma8(acc[mi][ni], a[mi], b[ni]);
        }
        __syncthreads();
    }

#pragma unroll
    for (int mi = 0; mi < 2; mi++) {
#pragma unroll
        for (int half = 0; half < 2; half++) {
            int r = row0 + wm * 32 + mi * 16 + gid + half * 8;
            if (r >= M) continue;
#pragma unroll
            for (int ni = 0; ni < 8; ni++) {
                int cI = col0 + wn * 64 + ni * 8 + tig * 2;
                float v0 = acc[mi][ni][half * 2 + 0];
                float v1 = acc[mi][ni][half * 2 + 1];
                float* cp = Cm + (size_t)r * Nm + cI;
                if (ACC)   { v0 += cp[0]; v1 += cp[1]; }
                if (BIAS_) { v0 += bias[cI]; v1 += bias[cI + 1]; }
                if (RELU_) { v0 = fmaxf(v0, 0.f); v1 = fmaxf(v1, 0.f); }
                cp[0] = v0; cp[1] = v1;
            }
        }
    }
}

// ---------------- fused LSTM step: 128x256 tile, 512 threads ------------
// gates = xs@Wih^T + lh_prev@Whh^T ; cell + attention dot in epilogue.
// grid = (H/64, ceil(NN/128), 2). dynamic smem 61440B.
__global__ __launch_bounds__(512) void tlstm(
    const float* __restrict__ xf, const float* __restrict__ xb,
    const float* __restrict__ attw, int K2, int s)
{
    extern __shared__ uint32_t sraw[];   // 61440 B
    uint32_t* Asb = sraw;                // 2 stages x 2560 (128 rows stride 20)
    uint32_t* Bsb = sraw + 5120;         // 2 stages x 5120 (256 rows stride 20)
    float* gbuf = (float*)sraw;          // epilogue reuse: [32][261]

    const int dir  = blockIdx.z;
    const int c0   = blockIdx.x * 64;    // hidden slice base (64 per block)
    const int row0 = blockIdx.y * 128;
    const int pb   = s & 1;

    const float* A  = dir ? xb : xf;
    const float* B  = d_wiht + (size_t)dir * H4 * C;
    const float* A2 = d_lh[pb][dir];
    const float* B2 = d_whht + (size_t)dir * H4 * H;

    const int tid  = threadIdx.x;
    const int lane = tid & 31;
    const int wid  = tid >> 5;       // 0..15
    const int wm   = wid & 1;        // 2 warps along M (64 rows each)
    const int wn   = wid >> 1;       // 8 warps along N (32 cols each)
    const int gid  = lane >> 2;
    const int tig  = lane & 3;

    const int nt1 = C >> 4;              // 8
    const int nt  = nt1 + (K2 >> 4);     // 8 or 24

    float acc[4][4][4];
#pragma unroll
    for (int mi = 0; mi < 4; mi++)
#pragma unroll
        for (int ni = 0; ni < 4; ni++)
#pragma unroll
            for (int r = 0; r < 4; r++) acc[mi][ni][r] = 0.f;

    auto loadTile = [&](int t, int st) {
        const float* Ap; const float* Bp; int Kc, k0;
        if (t < nt1) { Ap = A;  Bp = B;  Kc = C; k0 = t << 4; }
        else         { Ap = A2; Bp = B2; Kc = H; k0 = (t - nt1) << 4; }
        {   // A tile: 128 rows x 16k -> 512 float4, 1/thread
            int rr = tid >> 2, lc4 = (tid & 3) * 4;
            int gr = row0 + rr;
            uint32_t dst = (uint32_t)__cvta_generic_to_shared(&Asb[st * 2560 + rr * 20 + lc4]);
            cpa16(dst, Ap + (size_t)gr * Kc + k0 + lc4, gr < NN ? 16 : 0);
        }
#pragma unroll
        for (int it = 0; it < 2; it++) {   // B tile: 256 rows x 16k -> 1024 float4
            int idx = tid + it * 512;
            int rr = idx >> 2, lc4 = (idx & 3) * 4;
            int brow = ((rr >> 6) << 8) + c0 + (rr & 63);   // gate*256 + c0 + jl
            uint32_t dst = (uint32_t)__cvta_generic_to_shared(&Bsb[st * 5120 + rr * 20 + lc4]);
            cpa16(dst, Bp + (size_t)brow * Kc + k0 + lc4, 16);
        }
    };

    loadTile(0, 0);
    cpa_commit();

    for (int t = 0; t < nt; t++) {
        if (t + 1 < nt) loadTile(t + 1, (t + 1) & 1);
        cpa_commit();
        cpa_wait1();
        __syncthreads();

        const int st = t & 1;
#pragma unroll
        for (int kk = 0; kk < 16; kk += 8) {
            uint32_t a[4][4], b[4][2];
#pragma unroll
            for (int mi = 0; mi < 4; mi++) {
                int mr = wm * 64 + mi * 16;
                a[mi][0] = Asb[st * 2560 + (mr + gid)     * 20 + kk + tig];
                a[mi][1] = Asb[st * 2560 + (mr + gid + 8) * 20 + kk + tig];
                a[mi][2] = Asb[st * 2560 + (mr + gid)     * 20 + kk + tig + 4];
                a[mi][3] = Asb[st * 2560 + (mr + gid + 8) * 20 + kk + tig + 4];
            }
#pragma unroll
            for (int ni = 0; ni < 4; ni++) {
                int nr = wn * 32 + ni * 8;
                b[ni][0] = Bsb[st * 5120 + (nr + gid) * 20 + kk + tig];
                b[ni][1] = Bsb[st * 5120 + (nr + gid) * 20 + kk + tig + 4];
            }
#pragma unroll
            for (int mi = 0; mi < 4; mi++)
#pragma unroll
                for (int ni = 0; ni < 4; ni++)
                    mma8(acc[mi][ni], a[mi], b[ni]);
        }
        __syncthreads();
    }

    // ---- fused epilogue: four 32-row passes through smem ----
    const float* bs = d_bsum + (size_t)dir * H4;
    float* lc  = d_lc[dir];
    float* lhw = d_lh[1 - pb][dir];
    const int t_idx = dir ? (4 - s) : s;
    float* aout = (dir ? d_ab : d_af) + t_idx * NN;

#pragma unroll
    for (int p = 0; p < 4; p++) {
        __syncthreads();
        if (wm == (p >> 1)) {
            int m2b = (p & 1) * 2;
#pragma unroll
            for (int m2 = 0; m2 < 2; m2++) {
                int mi = m2b + m2;
#pragma unroll
                for (int half = 0; half < 2; half++) {
                    int rloc = m2 * 16 + gid + half * 8;
#pragma unroll
                    for (int ni = 0; ni < 4; ni++) {
                        int col = wn * 32 + ni * 8 + tig * 2;
                        gbuf[rloc * 261 + col]     = acc[mi][ni][half * 2 + 0];
                        gbuf[rloc * 261 + col + 1] = acc[mi][ni][half * 2 + 1];
                    }
                }
            }
        }
        __syncthreads();

        int rr = tid >> 4;                 // 0..31
        int n  = row0 + p * 32 + rr;
        bool valid = n < NN;
        float part = 0.f;
        if (valid) {
            int jj = (tid & 15) * 4;
#pragma unroll
            for (int q = 0; q < 4; q++) {
                int jl = jj + q;           // 0..63
                int j  = c0 + jl;
                float gi = gbuf[rr * 261 +   0 + jl] + bs[0 * H + j];
                float gf = gbuf[rr * 261 +  64 + jl] + bs[1 * H + j];
                float gg = gbuf[rr * 261 + 128 + jl] + bs[2 * H + j];
                float go = gbuf[rr * 261 + 192 + jl] + bs[3 * H + j];
                size_t ix = (size_t)n * H + j;
                float cprev = (K2 > 0) ? lc[ix] : 0.f;
                float cc = sigf(gf) * cprev + sigf(gi) * tanhf(gg);
                lc[ix] = cc;
                float hh = sigf(go) * tanhf(cc);
                lhw[ix] = __uint_as_float(f2tf(hh));
                part = fmaf(hh, attw[dir * H + j], part);
            }
        }
        part += __shfl_down_sync(0xffffffffu, part, 8, 16);
        part += __shfl_down_sync(0xffffffffu, part, 4, 16);
        part += __shfl_down_sync(0xffffffffu, part, 2, 16);
        part += __shfl_down_sync(0xffffffffu, part, 1, 16);
        if (valid && (tid & 15) == 0) atomicAdd(&aout[n], part);
    }
}

// ---------------- small kernels ----------------
__global__ void k_zero(float* p, int n) {
    int i = blockIdx.x * blockDim.x + threadIdx.x;
    if (i < n) p[i] = 0.f;
}
__global__ void k_zeroi(int* p, int n) {
    int i = blockIdx.x * blockDim.x + threadIdx.x;
    if (i < n) p[i] = 0;
}

__global__ void k_degi(const int* __restrict__ dst) {
    int e = blockIdx.x * blockDim.x + threadIdx.x;
    if (e < NE) atomicAdd(&d_indeg[dst[e]], 1);
}

__global__ void k_scan() {
    const int T = 1024;
    __shared__ int buf[T];
    __shared__ int carry_s;
    int t = threadIdx.x;
    if (t == 0) carry_s = 0;
    __syncthreads();
    for (int base = 0; base < NN; base += T) {
        int v = (base + t < NN) ? d_indeg[base + t] : 0;
        buf[t] = v;
        __syncthreads();
        for (int off = 1; off < T; off <<= 1) {
            int add = (t >= off) ? buf[t - off] : 0;
            __syncthreads();
            buf[t] += add;
            __syncthreads();
        }
        int carry = carry_s;
        __syncthreads();
        if (base + t < NN) {
            d_rowptr[base + t] = carry + buf[t] - v;
            d_curp[base + t]   = carry + buf[t] - v;
        }
        if (t == T - 1) carry_s = carry + buf[t];
        __syncthreads();
    }
    if (t == 0) d_rowptr[NN] = carry_s;
}

__global__ void k_place(const int* __restrict__ src, const int* __restrict__ dst) {
    int e = blockIdx.x * blockDim.x + threadIdx.x;
    if (e >= NE) return;
    int slot = atomicAdd(&d_curp[dst[e]], 1);
    d_eid[slot]  = e;
    d_esrc[slot] = src[e];
}

__global__ void k_gt(const float* __restrict__ g) {
    int i = blockIdx.x * blockDim.x + threadIdx.x;
    if (i >= LL * C * KG * C) return;
    int l  = i / (C * KG * C);
    int r  = (i / (KG * C)) % C;
    int kc = i % (KG * C);
    int k = kc / C, c = kc % C;
    d_gt[l][(k * C + r) * C + c] = g[i];
}

// pre-convert LSTM weights; fuse biases; cvt x
__global__ void k_cvtw(const float* __restrict__ wih, const float* __restrict__ whh,
                       const float* __restrict__ bih, const float* __restrict__ bhh,
                       const float* __restrict__ x) {
    int i = blockIdx.x * blockDim.x + threadIdx.x;
    if (i < 2 * H4 * C) d_wiht[i] = __uint_as_float(f2tf(wih[i]));
    if (i < 2 * H4 * H) d_whht[i] = __uint_as_float(f2tf(whh[i]));
    if (i < 2 * H4)     d_bsum[i] = bih[i] + bhh[i];
    if (i < NN * C)     d_hlt[0][i] = __uint_as_float(f2tf(x[i]));
}

// all-layer gaussian weights in one launch
__global__ void k_ewall(const float* __restrict__ ea,
                        const float* __restrict__ mu,
                        const float* __restrict__ sg) {
    int e = blockIdx.x * blockDim.x + threadIdx.x;
    if (e >= NE) return;
    float a0 = ea[e * 2 + 0], a1 = ea[e * 2 + 1];
#pragma unroll
    for (int l = 0; l < LL; l++) {
        const float* mul = mu + l * KG * 2;
        const float* sgl = sg + l * KG * 2;
#pragma unroll
        for (int k = 0; k < KG; k++) {
            float dx = a0 - mul[k * 2 + 0];
            float dy = a1 - mul[k * 2 + 1];
            float s0 = sgl[k * 2 + 0], s1 = sgl[k * 2 + 1];
            float w = expf(-0.5f * (dx * dx / (1e-15f + s0 * s0) +
                                    dy * dy / (1e-15f + s1 * s1)));
            d_ew[l][(size_t)e * KG + k] = w;
        }
    }
}

__global__ void k_sacc(const float* __restrict__ hin, int layer) {
    int n = (blockIdx.x * blockDim.x + threadIdx.x) >> 5;
    int l = threadIdx.x & 31;
    if (n >= NN) return;
    const float* ewl = d_ew[layer];
    int beg = d_rowptr[n], end = d_rowptr[n + 1];
    float acc[KG][4];
#pragma unroll
    for (int k = 0; k < KG; k++)
#pragma unroll
        for (int q = 0; q < 4; q++) acc[k][q] = 0.f;

    for (int p = beg; p < end; p++) {
        int e = d_eid[p], s = d_esrc[p];
        float wv = (l < KG) ? ewl[(size_t)e * KG + l] : 0.f;
        const float* hrp = hin + (size_t)s * C;
        float hv0 = hrp[l], hv1 = hrp[l + 32], hv2 = hrp[l + 64], hv3 = hrp[l + 96];
#pragma unroll
        for (int k = 0; k < KG; k++) {
            float wk = __shfl_sync(0xffffffffu, wv, k);
            acc[k][0] = fmaf(wk, hv0, acc[k][0]);
            acc[k][1] = fmaf(wk, hv1, acc[k][1]);
            acc[k][2] = fmaf(wk, hv2, acc[k][2]);
            acc[k][3] = fmaf(wk, hv3, acc[k][3]);
        }
    }
    float inv = 1.f / fmaxf((float)(end - beg), 1.f);
    float* Sp = &d_S[(size_t)n * (KG * C)];
#pragma unroll
    for (int k = 0; k < KG; k++) {
        Sp[k * C + l +  0] = acc[k][0] * inv;
        Sp[k * C + l + 32] = acc[k][1] * inv;
        Sp[k * C + l + 64] = acc[k][2] * inv;
        Sp[k * C + l + 96] = acc[k][3] * inv;
    }
}

__global__ void k_bnred() {  // <<<128,128>>>
    int c = threadIdx.x;
    float s = 0.f, q = 0.f;
    for (int r = blockIdx.x; r < NN; r += gridDim.x) {
        float v = d_h[(size_t)r * C + c];
        s += v; q += v * v;
    }
    atomicAdd(&d_bns[c], s);
    atomicAdd(&d_bnq[c], q);
}

__global__ void k_bnapp(const float* __restrict__ gamma,
                        const float* __restrict__ beta,
                        float* __restrict__ out_hl,
                        float* __restrict__ out_hlt, int relu) {
    int i = blockIdx.x * blockDim.x + threadIdx.x;
    if (i >= NN * C) return;
    int c = i % C;
    float mean = d_bns[c] / (float)NN;
    float var  = d_bnq[c] / (float)NN - mean * mean;
    float v = (d_h[i] - mean) * rsqrtf(var + 1e-5f) * gamma[c] + beta[c];
    if (relu) v = fmaxf(v, 0.f);
    d_h[i] = v;
    out_hl[i]  = v;
    out_hlt[i] = __uint_as_float(f2tf(v));
}

__global__ void k_nrep(const float* __restrict__ x) {
    int n = blockIdx.x;
    int c = threadIdx.x;
    __shared__ float p[5];
    if (c == 0) {
        float a[5], m = -1e30f;
#pragma unroll
        for (int t = 0; t < 5; t++) {
            a[t] = d_af[t * NN + n] + d_ab[t * NN + n];
            m = fmaxf(m, a[t]);
        }
        float s = 0.f;
#pragma unroll
        for (int t = 0; t < 5; t++) { a[t] = expf(a[t] - m); s += a[t]; }
#pragma unroll
        for (int t = 0; t < 5; t++) p[t] = a[t] / s;
    }
    __syncthreads();
    float r = p[0] * x[(size_t)n * C + c];
#pragma unroll
    for (int t = 1; t < 5; t++) r = fmaf(p[t], d_hl[t - 1][(size_t)n * C + c], r);
    d_nrep[(size_t)n * C + c] = r;
}

__global__ void k_cnt(const int* __restrict__ batch) {
    int n = blockIdx.x * blockDim.x + threadIdx.x;
    if (n < NN) atomicAdd(&d_cnt[batch[n]], 1.f);
}

__global__ void k_pool(const int* __restrict__ batch) {
    int i = blockIdx.x * blockDim.x + threadIdx.x;
    if (i >= NN * C) return;
    int n = i / C, c = i % C;
    atomicAdd(&d_hg[(size_t)batch[n] * C + c], d_nrep[i]);
}

__global__ void k_pdiv() {
    int i = blockIdx.x * blockDim.x + threadIdx.x;
    if (i >= NB * C) return;
    d_hg[i] /= fmaxf(d_cnt[i / C], 1.f);
}

__global__ void k_ln(const float* __restrict__ g, const float* __restrict__ b,
                     float* __restrict__ out) {
    int row = blockIdx.x, t = threadIdx.x;
    __shared__ float sm[NOUT];
    float v = d_z2[(size_t)row * NOUT + t];
    sm[t] = v;
    __syncthreads();
    for (int o = NOUT / 2; o > 0; o >>= 1) {
        if (t < o) sm[t] += sm[t + o];
        __syncthreads();
    }
    float mean = sm[0] / (float)NOUT;
    __syncthreads();
    float dv = v - mean;
    sm[t] = dv * dv;
    __syncthreads();
    for (int o = NOUT / 2; o > 0; o >>= 1) {
        if (t < o) sm[t] += sm[t + o];
        __syncthreads();
    }
    float var = sm[0] / (float)NOUT;
    out[(size_t)row * NOUT + t] = dv * rsqrtf(var + 1e-5f) * g[t] + b[t];
}

// ---------------- host ----------------
static float* symf(const void* s) {
    void* p = nullptr;
    cudaGetSymbolAddress(&p, s);
    return (float*)p;
}
static int* symi(const void* s) {
    void* p = nullptr;
    cudaGetSymbolAddress(&p, s);
    return (int*)p;
}

extern "C" void kernel_launch(void* const* d_in, const int* in_sizes, int n_in,
                              void* d_out, int out_size) {
    const float* x     = (const float*)d_in[0];
    const int*   ei    = (const int*)d_in[1];
    const int*   src   = ei;
    const int*   dst   = ei + NE;
    const float* ea    = (const float*)d_in[2];
    const int*   batch = (const int*)d_in[3];
    const float* g     = (const float*)d_in[4];
    const float* root  = (const float*)d_in[5];
    const float* bias  = (const float*)d_in[6];
    const float* mu    = (const float*)d_in[7];
    const float* sigma = (const float*)d_in[8];
    const float* bng   = (const float*)d_in[9];
    const float* bnb   = (const float*)d_in[10];
    const float* wih   = (const float*)d_in[11];
    const float* whh   = (const float*)d_in[12];
    const float* bih   = (const float*)d_in[13];
    const float* bhh   = (const float*)d_in[14];
    const float* attw  = (const float*)d_in[15];
    const float* p1w   = (const float*)d_in[17];
    const float* p1b   = (const float*)d_in[18];
    const float* p2w   = (const float*)d_in[19];
    const float* p2b   = (const float*)d_in[20];
    const float* lng   = (const float*)d_in[21];
    const float* lnb   = (const float*)d_in[22];
    float* out = (float*)d_out;

    float* h   = symf(d_h);
    float* hl  = symf(d_hl);
    float* hlt = symf(d_hlt);
    float* S   = symf(d_S);
    float* gt  = symf(d_gt);
    float* bns = symf(d_bns);
    float* bnq = symf(d_bnq);
    float* af  = symf(d_af);
    float* ab  = symf(d_ab);
    float* cnt = symf(d_cnt);
    float* hg  = symf(d_hg);
    float* z1  = symf(d_z1);
    float* z2  = symf(d_z2);
    int* indeg = symi(d_indeg);

    const int TPB = 256;
    const dim3 blk(TPB);
    const int gridNC = (NN * C + TPB - 1) / TPB;
    const int rowsN  = (NN + 127) / 128;
    const int TLSTM_SMEM = 61440;

    static int smem_set = 0;
    if (!smem_set) {
        cudaFuncSetAttribute(tlstm, cudaFuncAttributeMaxDynamicSharedMemorySize,
                             TLSTM_SMEM);
        smem_set = 1;
    }

    // -------- CSR build + weight prep --------
    k_zeroi<<<(NN + TPB - 1) / TPB, blk>>>(indeg, NN);
    k_degi<<<(NE + TPB - 1) / TPB, blk>>>(dst);
    k_scan<<<1, 1024>>>();
    k_place<<<(NE + TPB - 1) / TPB, blk>>>(src, dst);
    k_gt<<<(LL * C * KG * C + TPB - 1) / TPB, blk>>>(g);
    k_cvtw<<<(NN * C + TPB - 1) / TPB, blk>>>(wih, whh, bih, bhh, x);
    k_ewall<<<(NE + TPB - 1) / TPB, blk>>>(ea, mu, sigma);

    // -------- GMMConv layers --------
    const float* hin = x;
    for (int i = 0; i < LL; i++) {
        k_sacc<<<(NN * 32 + TPB - 1) / TPB, blk>>>(hin, i);
        GA gl = {S, gt + (size_t)i * KG * C * C, hin, root + (size_t)i * C * C, h};
        tgemm<false, false, false, true>
            <<<dim3(1, rowsN, 1), blk>>>(gl, gl, bias + i * C, NN, C, KG * C, C);
        k_zero<<<1, C>>>(bns, C);
        k_zero<<<1, C>>>(bnq, C);
        k_bnred<<<128, 128>>>();
        k_bnapp<<<gridNC, blk>>>(bng + i * C, bnb + i * C,
                                 hl + (size_t)i * NN * C,
                                 hlt + (size_t)(i + 1) * NN * C,
                                 (i < LL - 1) ? 1 : 0);
        hin = h;
    }

    // -------- bidirectional LSTM JumpingKnowledge (fused GEMM+cell) -------
    k_zero<<<(5 * NN + TPB - 1) / TPB, blk>>>(af, 5 * NN);
    k_zero<<<(5 * NN + TPB - 1) / TPB, blk>>>(ab, 5 * NN);
    for (int s = 0; s < 5; s++) {
        int tf = s, tb = 4 - s;
        const float* xf = hlt + (size_t)tf * NN * C;
        const float* xb = hlt + (size_t)tb * NN * C;
        tlstm<<<dim3(H / 64, rowsN, 2), 512, TLSTM_SMEM>>>(xf, xb, attw,
                                                           (s > 0) ? H : 0, s);
    }

    // attention softmax + weighted node representation
    k_nrep<<<NN, C>>>(x);

    // global mean pool
    k_zero<<<(NB + TPB - 1) / TPB, blk>>>(cnt, NB);
    k_zero<<<(NB * C + TPB - 1) / TPB, blk>>>(hg, NB * C);
    k_cnt<<<(NN + TPB - 1) / TPB, blk>>>(batch);
    k_pool<<<gridNC, blk>>>(batch);
    k_pdiv<<<(NB * C + TPB - 1) / TPB, blk>>>();

    // MLP + LayerNorm
    GA gp1 = {hg, p1w, nullptr, nullptr, z1};
    tgemm<false, false, true, true>
        <<<dim3(NHID / 128, NB / 128, 1), blk>>>(gp1, gp1, p1b, NB, NHID, C, 0);
    GA gp2 = {z1, p2w, nullptr, nullptr, z2};
    tgemm<false, false, false, true>
        <<<dim3(NOUT / 128, NB / 128, 1), blk>>>(gp2, gp2, p2b, NB, NOUT, NHID, 0);
    k_ln<<<NB, NOUT>>>(lng, lnb, out);
}

// round 8
// speedup vs baseline: 1.0401x; 1.0401x over previous
#include <cuda_runtime.h>
#include <math.h>
#include <stdint.h>

// ---------------- problem constants ----------------
namespace {
constexpr int NN   = 30000;   // nodes
constexpr int NE   = 480000;  // edges
constexpr int C    = 128;     // channels (= F)
constexpr int KG   = 8;       // gaussians
constexpr int LL   = 4;       // layers
constexpr int H    = 256;     // LSTM hidden
constexpr int H4   = 1024;    // 4*H
constexpr int NHID = 512;
constexpr int NOUT = 256;
constexpr int NB   = 1024;    // graphs
}

// ---------------- scratch (device globals; no allocations allowed) -------
__device__ __align__(256) float d_h[NN * C];
__device__ __align__(256) float d_hr[NN * C];
__device__ __align__(256) float d_hl[LL][NN * C];
__device__ __align__(256) float d_hlt[5][NN * C];     // tf32-valued x,h1..h4
__device__ __align__(256) float d_S[NN * KG * C];
__device__ __align__(256) float d_gt[LL][KG * C * C];
__device__ __align__(256) float d_ew[LL][NE * KG];
__device__ __align__(256) float d_bns[C];
__device__ __align__(256) float d_bnq[C];
__device__ __align__(256) float d_lh[2][2][NN * H];   // tf32-valued, [pp][dir]
__device__ __align__(256) float d_lc[2][NN * H];
__device__ __align__(256) float d_af[5 * NN];
__device__ __align__(256) float d_ab[5 * NN];
__device__ __align__(256) float d_nrep[NN * C];
__device__ __align__(256) float d_cnt[NB];
__device__ __align__(256) float d_hg[NB * C];
__device__ __align__(256) float d_z1[NB * NHID];
__device__ __align__(256) float d_z2[NB * NOUT];
// tf32-valued LSTM weights + fused biases
__device__ __align__(256) float d_wiht[2 * H4 * C];
__device__ __align__(256) float d_whht[2 * H4 * H];
__device__ __align__(256) float d_bsum[2 * H4];
// CSR scratch
__device__ __align__(256) int d_indeg[NN];
__device__ __align__(256) int d_rowptr[NN + 1];
__device__ __align__(256) int d_curp[NN];
__device__ __align__(256) int d_eid[NE];
__device__ __align__(256) int d_esrc[NE];

// ---------------- TF32 helpers ----------------
__device__ __forceinline__ uint32_t f2tf(float f) {
    uint32_t u;
    asm("cvt.rna.tf32.f32 %0, %1;" : "=r"(u) : "f"(f));
    return u;
}
__device__ __forceinline__ uint32_t tfw(uint32_t rawbits) {
    return f2tf(__uint_as_float(rawbits));
}
__device__ __forceinline__ void mma8(float* c, const uint32_t* a, const uint32_t* b) {
    asm volatile(
        "mma.sync.aligned.m16n8k8.row.col.f32.tf32.tf32.f32 "
        "{%0,%1,%2,%3}, {%4,%5,%6,%7}, {%8,%9}, {%0,%1,%2,%3};"
        : "+f"(c[0]), "+f"(c[1]), "+f"(c[2]), "+f"(c[3])
        : "r"(a[0]), "r"(a[1]), "r"(a[2]), "r"(a[3]), "r"(b[0]), "r"(b[1]));
}
__device__ __forceinline__ void cpa16(uint32_t sdst, const void* gsrc, int srcsz) {
    asm volatile("cp.async.ca.shared.global [%0], [%1], 16, %2;\n"
                 :: "r"(sdst), "l"(gsrc), "r"(srcsz));
}
__device__ __forceinline__ void cpa_commit() { asm volatile("cp.async.commit_group;\n"); }
__device__ __forceinline__ void cpa_wait1()  { asm volatile("cp.async.wait_group 1;\n"); }
__device__ __forceinline__ void cpa_wait2()  { asm volatile("cp.async.wait_group 2;\n"); }
__device__ __forceinline__ float sigf(float x) { return 1.f / (1.f + expf(-x)); }

// ---------------- generic TF32 GEMM (cp.async 2-stage, dual-K, lda) ------
// B layout: [Kd][Nm] row-major (stride Nm). A: [M x Kd] with row stride lda.
struct GA {
    const float* A;
    const float* B;
    const float* A2;
    const float* B2;
    float* Cm;
    const float* bias;   // nullptr -> no bias
    int Kd;
    int Kd2;
    int lda;
    int lda2;
};

template <bool ACC, bool RELU_>
__global__ __launch_bounds__(256) void tgemm(GA g0, GA g1, int M, int Nm)
{
    __shared__ uint32_t As[2][128 * 20];
    __shared__ uint32_t Bs[2][2560];     // [k][n] stride 136

    const GA ga = blockIdx.z ? g1 : g0;
    const float* __restrict__ A  = ga.A;
    const float* __restrict__ B  = ga.B;
    const float* __restrict__ A2 = ga.A2;
    const float* __restrict__ B2 = ga.B2;
    float* __restrict__ Cm = ga.Cm;
    const float* __restrict__ bias = ga.bias;
    const int Kd = ga.Kd, Kd2 = ga.Kd2, lda = ga.lda, lda2 = ga.lda2;

    const int tid  = threadIdx.x;
    const int lane = tid & 31;
    const int wid  = tid >> 5;
    const int wm   = wid & 3;
    const int wn   = wid >> 2;
    const int gid  = lane >> 2;
    const int tig  = lane & 3;
    const int row0 = blockIdx.y * 128, col0 = blockIdx.x * 128;

    const int nt1 = Kd >> 4;
    const int nt  = nt1 + (Kd2 >> 4);

    float acc[2][8][4];
#pragma unroll
    for (int mi = 0; mi < 2; mi++)
#pragma unroll
        for (int ni = 0; ni < 8; ni++)
#pragma unroll
            for (int r = 0; r < 4; r++) acc[mi][ni][r] = 0.f;

    const int lr0 = tid >> 2, lc4 = (tid & 3) * 4;

    auto loadTile = [&](int t, int st) {
        const float* Ap; const float* Bp; int ld, k0;
        if (t < nt1) { Ap = A;  Bp = B;  ld = lda;  k0 = t << 4; }
        else         { Ap = A2; Bp = B2; ld = lda2; k0 = (t - nt1) << 4; }
#pragma unroll
        for (int it = 0; it < 2; it++) {
            int rr = lr0 + it * 64;
            int gr = row0 + rr;
            uint32_t dst = (uint32_t)__cvta_generic_to_shared(&As[st][rr * 20 + lc4]);
            cpa16(dst, Ap + (size_t)gr * ld + k0 + lc4, gr < M ? 16 : 0);
        }
#pragma unroll
        for (int it = 0; it < 2; it++) {
            int idx = tid + it * 256;
            int kk = idx >> 5, n4 = (idx & 31) * 4;
            uint32_t dst = (uint32_t)__cvta_generic_to_shared(&Bs[st][kk * 136 + n4]);
            cpa16(dst, Bp + (size_t)(k0 + kk) * Nm + col0 + n4, 16);
        }
    };

    loadTile(0, 0);
    cpa_commit();

    for (int t = 0; t < nt; t++) {
        if (t + 1 < nt) loadTile(t + 1, (t + 1) & 1);
        cpa_commit();
        cpa_wait1();
        __syncthreads();

        const int st = t & 1;
#pragma unroll
        for (int kk = 0; kk < 16; kk += 8) {
            uint32_t a[2][4], b[8][2];
#pragma unroll
            for (int mi = 0; mi < 2; mi++) {
                int mr = wm * 32 + mi * 16;
                a[mi][0] = tfw(As[st][(mr + gid)     * 20 + kk + tig]);
                a[mi][1] = tfw(As[st][(mr + gid + 8) * 20 + kk + tig]);
                a[mi][2] = tfw(As[st][(mr + gid)     * 20 + kk + tig + 4]);
                a[mi][3] = tfw(As[st][(mr + gid + 8) * 20 + kk + tig + 4]);
            }
#pragma unroll
            for (int ni = 0; ni < 8; ni++) {
                int nr = wn * 64 + ni * 8;
                b[ni][0] = tfw(Bs[st][(kk + tig)     * 136 + nr + gid]);
                b[ni][1] = tfw(Bs[st][(kk + tig + 4) * 136 + nr + gid]);
            }
#pragma unroll
            for (int mi = 0; mi < 2; mi++)
#pragma unroll
                for (int ni = 0; ni < 8; ni++)
                    mma8(acc[mi][ni], a[mi], b[ni]);
        }
        __syncthreads();
    }

#pragma unroll
    for (int mi = 0; mi < 2; mi++) {
#pragma unroll
        for (int half = 0; half < 2; half++) {
            int r = row0 + wm * 32 + mi * 16 + gid + half * 8;
            if (r >= M) continue;
#pragma unroll
            for (int ni = 0; ni < 8; ni++) {
                int cI = col0 + wn * 64 + ni * 8 + tig * 2;
                float v0 = acc[mi][ni][half * 2 + 0];
                float v1 = acc[mi][ni][half * 2 + 1];
                float* cp = Cm + (size_t)r * Nm + cI;
                if (ACC)  { v0 += cp[0]; v1 += cp[1]; }
                if (bias) { v0 += bias[cI]; v1 += bias[cI + 1]; }
                if (RELU_) { v0 = fmaxf(v0, 0.f); v1 = fmaxf(v1, 0.f); }
                cp[0] = v0; cp[1] = v1;
            }
        }
    }
}

// ---------------- fused LSTM step: 128x128 tile, 3-stage cp.async --------
// gates = xs@Wih^T + lh_prev@Whh^T ; cell + attention dot in epilogue.
// grid = (H/32, ceil(NN/128), 2). dynamic smem 61440B (3 stages x 20KB).
__global__ __launch_bounds__(256) void tlstm(
    const float* __restrict__ xf, const float* __restrict__ xb,
    const float* __restrict__ attw, int K2, int s)
{
    extern __shared__ uint32_t sraw[];   // 15360 u32 = 61440 B
    // As stage st: sraw + st*2560 ; Bs stage st: sraw + 7680 + st*2560
    float* gbuf = (float*)sraw;          // epilogue reuse: [64][133] = 34KB

    const int dir  = blockIdx.z;
    const int c0   = blockIdx.x * 32;
    const int row0 = blockIdx.y * 128;
    const int pb   = s & 1;

    const float* A  = dir ? xb : xf;
    const float* B  = d_wiht + (size_t)dir * H4 * C;
    const float* A2 = d_lh[pb][dir];
    const float* B2 = d_whht + (size_t)dir * H4 * H;

    const int tid  = threadIdx.x;
    const int lane = tid & 31;
    const int wid  = tid >> 5;
    const int wm   = wid & 3;
    const int wn   = wid >> 2;
    const int gid  = lane >> 2;
    const int tig  = lane & 3;

    const int nt1 = C >> 4;              // 8
    const int nt  = nt1 + (K2 >> 4);     // 8 or 24

    float acc[2][8][4];
#pragma unroll
    for (int mi = 0; mi < 2; mi++)
#pragma unroll
        for (int ni = 0; ni < 8; ni++)
#pragma unroll
            for (int r = 0; r < 4; r++) acc[mi][ni][r] = 0.f;

    const int lr0 = tid >> 2, lc4 = (tid & 3) * 4;

    auto loadTile = [&](int t, int st) {
        const float* Ap; const float* Bp; int Kc, k0;
        if (t < nt1) { Ap = A;  Bp = B;  Kc = C; k0 = t << 4; }
        else         { Ap = A2; Bp = B2; Kc = H; k0 = (t - nt1) << 4; }
        uint32_t* Asb = sraw + st * 2560;
        uint32_t* Bsb = sraw + 7680 + st * 2560;
#pragma unroll
        for (int it = 0; it < 2; it++) {
            int rr = lr0 + it * 64;
            int gr = row0 + rr;
            uint32_t dst = (uint32_t)__cvta_generic_to_shared(&Asb[rr * 20 + lc4]);
            cpa16(dst, Ap + (size_t)gr * Kc + k0 + lc4, gr < NN ? 16 : 0);
        }
#pragma unroll
        for (int it = 0; it < 2; it++) {
            int rr = lr0 + it * 64;                       // tile col 0..127
            int brow = ((rr >> 5) << 8) + c0 + (rr & 31); // gate*256 + c0 + j'
            uint32_t dst = (uint32_t)__cvta_generic_to_shared(&Bsb[rr * 20 + lc4]);
            cpa16(dst, Bp + (size_t)brow * Kc + k0 + lc4, 16);
        }
    };

    loadTile(0, 0);
    cpa_commit();
    loadTile(1, 1);
    cpa_commit();

    for (int t = 0; t < nt; t++) {
        if (t + 2 < nt) loadTile(t + 2, (t + 2) % 3);
        cpa_commit();
        cpa_wait2();
        __syncthreads();

        const int st = t % 3;
        const uint32_t* Asb = sraw + st * 2560;
        const uint32_t* Bsb = sraw + 7680 + st * 2560;
#pragma unroll
        for (int kk = 0; kk < 16; kk += 8) {
            uint32_t a[2][4], b[8][2];
#pragma unroll
            for (int mi = 0; mi < 2; mi++) {
                int mr = wm * 32 + mi * 16;
                a[mi][0] = Asb[(mr + gid)     * 20 + kk + tig];
                a[mi][1] = Asb[(mr + gid + 8) * 20 + kk + tig];
                a[mi][2] = Asb[(mr + gid)     * 20 + kk + tig + 4];
                a[mi][3] = Asb[(mr + gid + 8) * 20 + kk + tig + 4];
            }
#pragma unroll
            for (int ni = 0; ni < 8; ni++) {
                int nr = wn * 64 + ni * 8;
                b[ni][0] = Bsb[(nr + gid) * 20 + kk + tig];
                b[ni][1] = Bsb[(nr + gid) * 20 + kk + tig + 4];
            }
#pragma unroll
            for (int mi = 0; mi < 2; mi++)
#pragma unroll
                for (int ni = 0; ni < 8; ni++)
                    mma8(acc[mi][ni], a[mi], b[ni]);
        }
        __syncthreads();
    }

    // ---- fused epilogue: two 64-row passes through smem ----
    const float* bs = d_bsum + (size_t)dir * H4;
    float* lc  = d_lc[dir];
    float* lhw = d_lh[1 - pb][dir];
    const int t_idx = dir ? (4 - s) : s;
    float* aout = (dir ? d_ab : d_af) + t_idx * NN;

#pragma unroll
    for (int p = 0; p < 2; p++) {
        __syncthreads();
        if ((wm >> 1) == p) {
#pragma unroll
            for (int mi = 0; mi < 2; mi++)
#pragma unroll
                for (int half = 0; half < 2; half++) {
                    int rloc = (wm & 1) * 32 + mi * 16 + gid + half * 8;
#pragma unroll
                    for (int ni = 0; ni < 8; ni++) {
                        int col = wn * 64 + ni * 8 + tig * 2;
                        gbuf[rloc * 133 + col]     = acc[mi][ni][half * 2 + 0];
                        gbuf[rloc * 133 + col + 1] = acc[mi][ni][half * 2 + 1];
                    }
                }
        }
        __syncthreads();

        int rr = tid >> 2;                 // 0..63
        int n  = row0 + p * 64 + rr;
        bool valid = n < NN;
        float part = 0.f;
        if (valid) {
            int jb = (tid & 3) * 8;
#pragma unroll
            for (int q = 0; q < 8; q++) {
                int jl = jb + q;           // 0..31
                int j  = c0 + jl;          // 0..255
                float gi = gbuf[rr * 133 +  0 + jl] + bs[0 * H + j];
                float gf = gbuf[rr * 133 + 32 + jl] + bs[1 * H + j];
                float gg = gbuf[rr * 133 + 64 + jl] + bs[2 * H + j];
                float go = gbuf[rr * 133 + 96 + jl] + bs[3 * H + j];
                size_t ix = (size_t)n * H + j;
                float cprev = (K2 > 0) ? lc[ix] : 0.f;
                float cc = sigf(gf) * cprev + sigf(gi) * tanhf(gg);
                lc[ix] = cc;
                float hh = sigf(go) * tanhf(cc);
                lhw[ix] = __uint_as_float(f2tf(hh));
                part = fmaf(hh, attw[dir * H + j], part);
            }
        }
        part += __shfl_down_sync(0xffffffffu, part, 2);
        part += __shfl_down_sync(0xffffffffu, part, 1);
        if (valid && (tid & 3) == 0) atomicAdd(&aout[n], part);
    }
}

// ---------------- small kernels ----------------
__global__ void k_zero(float* p, int n) {
    int i = blockIdx.x * blockDim.x + threadIdx.x;
    if (i < n) p[i] = 0.f;
}
__global__ void k_zeroi(int* p, int n) {
    int i = blockIdx.x * blockDim.x + threadIdx.x;
    if (i < n) p[i] = 0;
}

__global__ void k_degi(const int* __restrict__ dst) {
    int e = blockIdx.x * blockDim.x + threadIdx.x;
    if (e < NE) atomicAdd(&d_indeg[dst[e]], 1);
}

__global__ void k_scan() {
    const int T = 1024;
    __shared__ int buf[T];
    __shared__ int carry_s;
    int t = threadIdx.x;
    if (t == 0) carry_s = 0;
    __syncthreads();
    for (int base = 0; base < NN; base += T) {
        int v = (base + t < NN) ? d_indeg[base + t] : 0;
        buf[t] = v;
        __syncthreads();
        for (int off = 1; off < T; off <<= 1) {
            int add = (t >= off) ? buf[t - off] : 0;
            __syncthreads();
            buf[t] += add;
            __syncthreads();
        }
        int carry = carry_s;
        __syncthreads();
        if (base + t < NN) {
            d_rowptr[base + t] = carry + buf[t] - v;
            d_curp[base + t]   = carry + buf[t] - v;
        }
        if (t == T - 1) carry_s = carry + buf[t];
        __syncthreads();
    }
    if (t == 0) d_rowptr[NN] = carry_s;
}

__global__ void k_place(const int* __restrict__ src, const int* __restrict__ dst) {
    int e = blockIdx.x * blockDim.x + threadIdx.x;
    if (e >= NE) return;
    int slot = atomicAdd(&d_curp[dst[e]], 1);
    d_eid[slot]  = e;
    d_esrc[slot] = src[e];
}

__global__ void k_gt(const float* __restrict__ g) {
    int i = blockIdx.x * blockDim.x + threadIdx.x;
    if (i >= LL * C * KG * C) return;
    int l  = i / (C * KG * C);
    int r  = (i / (KG * C)) % C;
    int kc = i % (KG * C);
    int k = kc / C, c = kc % C;
    d_gt[l][(k * C + r) * C + c] = g[i];
}

// pre-convert LSTM weights; fuse biases; cvt x
__global__ void k_cvtw(const float* __restrict__ wih, const float* __restrict__ whh,
                       const float* __restrict__ bih, const float* __restrict__ bhh,
                       const float* __restrict__ x) {
    int i = blockIdx.x * blockDim.x + threadIdx.x;
    if (i < 2 * H4 * C) d_wiht[i] = __uint_as_float(f2tf(wih[i]));
    if (i < 2 * H4 * H) d_whht[i] = __uint_as_float(f2tf(whh[i]));
    if (i < 2 * H4)     d_bsum[i] = bih[i] + bhh[i];
    if (i < NN * C)     d_hlt[0][i] = __uint_as_float(f2tf(x[i]));
}

// all-layer gaussian weights in one launch
__global__ void k_ewall(const float* __restrict__ ea,
                        const float* __restrict__ mu,
                        const float* __restrict__ sg) {
    int e = blockIdx.x * blockDim.x + threadIdx.x;
    if (e >= NE) return;
    float a0 = ea[e * 2 + 0], a1 = ea[e * 2 + 1];
#pragma unroll
    for (int l = 0; l < LL; l++) {
        const float* mul = mu + l * KG * 2;
        const float* sgl = sg + l * KG * 2;
#pragma unroll
        for (int k = 0; k < KG; k++) {
            float dx = a0 - mul[k * 2 + 0];
            float dy = a1 - mul[k * 2 + 1];
            float s0 = sgl[k * 2 + 0], s1 = sgl[k * 2 + 1];
            float w = expf(-0.5f * (dx * dx / (1e-15f + s0 * s0) +
                                    dy * dy / (1e-15f + s1 * s1)));
            d_ew[l][(size_t)e * KG + k] = w;
        }
    }
}

__global__ void k_sacc(const float* __restrict__ hin, int layer) {
    int n = (blockIdx.x * blockDim.x + threadIdx.x) >> 5;
    int l = threadIdx.x & 31;
    if (n >= NN) return;
    const float* ewl = d_ew[layer];
    int beg = d_rowptr[n], end = d_rowptr[n + 1];
    float acc[KG][4];
#pragma unroll
    for (int k = 0; k < KG; k++)
#pragma unroll
        for (int q = 0; q < 4; q++) acc[k][q] = 0.f;

    for (int p = beg; p < end; p++) {
        int e = d_eid[p], s = d_esrc[p];
        float wv = (l < KG) ? ewl[(size_t)e * KG + l] : 0.f;
        const float* hrp = hin + (size_t)s * C;
        float hv0 = hrp[l], hv1 = hrp[l + 32], hv2 = hrp[l + 64], hv3 = hrp[l + 96];
#pragma unroll
        for (int k = 0; k < KG; k++) {
            float wk = __shfl_sync(0xffffffffu, wv, k);
            acc[k][0] = fmaf(wk, hv0, acc[k][0]);
            acc[k][1] = fmaf(wk, hv1, acc[k][1]);
            acc[k][2] = fmaf(wk, hv2, acc[k][2]);
            acc[k][3] = fmaf(wk, hv3, acc[k][3]);
        }
    }
    float inv = 1.f / fmaxf((float)(end - beg), 1.f);
    float* Sp = &d_S[(size_t)n * (KG * C)];
#pragma unroll
    for (int k = 0; k < KG; k++) {
        Sp[k * C + l +  0] = acc[k][0] * inv;
        Sp[k * C + l + 32] = acc[k][1] * inv;
        Sp[k * C + l + 64] = acc[k][2] * inv;
        Sp[k * C + l + 96] = acc[k][3] * inv;
    }
}

// BN stats over (h + hr)
__global__ void k_bnred() {  // <<<128,128>>>
    int c = threadIdx.x;
    float s = 0.f, q = 0.f;
    for (int r = blockIdx.x; r < NN; r += gridDim.x) {
        float v = d_h[(size_t)r * C + c] + d_hr[(size_t)r * C + c];
        s += v; q += v * v;
    }
    atomicAdd(&d_bns[c], s);
    atomicAdd(&d_bnq[c], q);
}

__global__ void k_bnapp(const float* __restrict__ gamma,
                        const float* __restrict__ beta,
                        float* __restrict__ out_hl,
                        float* __restrict__ out_hlt, int relu) {
    int i = blockIdx.x * blockDim.x + threadIdx.x;
    if (i >= NN * C) return;
    int c = i % C;
    float mean = d_bns[c] / (float)NN;
    float var  = d_bnq[c] / (float)NN - mean * mean;
    float v = (d_h[i] + d_hr[i] - mean) * rsqrtf(var + 1e-5f) * gamma[c] + beta[c];
    if (relu) v = fmaxf(v, 0.f);
    d_h[i] = v;
    out_hl[i]  = v;
    out_hlt[i] = __uint_as_float(f2tf(v));
}

__global__ void k_nrep(const float* __restrict__ x) {
    int n = blockIdx.x;
    int c = threadIdx.x;
    __shared__ float p[5];
    if (c == 0) {
        float a[5], m = -1e30f;
#pragma unroll
        for (int t = 0; t < 5; t++) {
            a[t] = d_af[t * NN + n] + d_ab[t * NN + n];
            m = fmaxf(m, a[t]);
        }
        float s = 0.f;
#pragma unroll
        for (int t = 0; t < 5; t++) { a[t] = expf(a[t] - m); s += a[t]; }
#pragma unroll
        for (int t = 0; t < 5; t++) p[t] = a[t] / s;
    }
    __syncthreads();
    float r = p[0] * x[(size_t)n * C + c];
#pragma unroll
    for (int t = 1; t < 5; t++) r = fmaf(p[t], d_hl[t - 1][(size_t)n * C + c], r);
    d_nrep[(size_t)n * C + c] = r;
}

__global__ void k_cnt(const int* __restrict__ batch) {
    int n = blockIdx.x * blockDim.x + threadIdx.x;
    if (n < NN) atomicAdd(&d_cnt[batch[n]], 1.f);
}

__global__ void k_pool(const int* __restrict__ batch) {
    int i = blockIdx.x * blockDim.x + threadIdx.x;
    if (i >= NN * C) return;
    int n = i / C, c = i % C;
    atomicAdd(&d_hg[(size_t)batch[n] * C + c], d_nrep[i]);
}

__global__ void k_pdiv() {
    int i = blockIdx.x * blockDim.x + threadIdx.x;
    if (i >= NB * C) return;
    d_hg[i] /= fmaxf(d_cnt[i / C], 1.f);
}

__global__ void k_ln(const float* __restrict__ g, const float* __restrict__ b,
                     float* __restrict__ out) {
    int row = blockIdx.x, t = threadIdx.x;
    __shared__ float sm[NOUT];
    float v = d_z2[(size_t)row * NOUT + t];
    sm[t] = v;
    __syncthreads();
    for (int o = NOUT / 2; o > 0; o >>= 1) {
        if (t < o) sm[t] += sm[t + o];
        __syncthreads();
    }
    float mean = sm[0] / (float)NOUT;
    __syncthreads();
    float dv = v - mean;
    sm[t] = dv * dv;
    __syncthreads();
    for (int o = NOUT / 2; o > 0; o >>= 1) {
        if (t < o) sm[t] += sm[t + o];
        __syncthreads();
    }
    float var = sm[0] / (float)NOUT;
    out[(size_t)row * NOUT + t] = dv * rsqrtf(var + 1e-5f) * g[t] + b[t];
}

// ---------------- host ----------------
static float* symf(const void* s) {
    void* p = nullptr;
    cudaGetSymbolAddress(&p, s);
    return (float*)p;
}
static int* symi(const void* s) {
    void* p = nullptr;
    cudaGetSymbolAddress(&p, s);
    return (int*)p;
}

extern "C" void kernel_launch(void* const* d_in, const int* in_sizes, int n_in,
                              void* d_out, int out_size) {
    const float* x     = (const float*)d_in[0];
    const int*   ei    = (const int*)d_in[1];
    const int*   src   = ei;
    const int*   dst   = ei + NE;
    const float* ea    = (const float*)d_in[2];
    const int*   batch = (const int*)d_in[3];
    const float* g     = (const float*)d_in[4];
    const float* root  = (const float*)d_in[5];
    const float* bias  = (const float*)d_in[6];
    const float* mu    = (const float*)d_in[7];
    const float* sigma = (const float*)d_in[8];
    const float* bng   = (const float*)d_in[9];
    const float* bnb   = (const float*)d_in[10];
    const float* wih   = (const float*)d_in[11];
    const float* whh   = (const float*)d_in[12];
    const float* bih   = (const float*)d_in[13];
    const float* bhh   = (const float*)d_in[14];
    const float* attw  = (const float*)d_in[15];
    const float* p1w   = (const float*)d_in[17];
    const float* p1b   = (const float*)d_in[18];
    const float* p2w   = (const float*)d_in[19];
    const float* p2b   = (const float*)d_in[20];
    const float* lng   = (const float*)d_in[21];
    const float* lnb   = (const float*)d_in[22];
    float* out = (float*)d_out;

    float* h   = symf(d_h);
    float* hr  = symf(d_hr);
    float* hl  = symf(d_hl);
    float* hlt = symf(d_hlt);
    float* S   = symf(d_S);
    float* gt  = symf(d_gt);
    float* bns = symf(d_bns);
    float* bnq = symf(d_bnq);
    float* af  = symf(d_af);
    float* ab  = symf(d_ab);
    float* cnt = symf(d_cnt);
    float* hg  = symf(d_hg);
    float* z1  = symf(d_z1);
    float* z2  = symf(d_z2);
    int* indeg = symi(d_indeg);

    const int TPB = 256;
    const dim3 blk(TPB);
    const int gridNC = (NN * C + TPB - 1) / TPB;
    const int rowsN  = (NN + 127) / 128;
    const int TLSTM_SMEM = 61440;

    static int smem_set = 0;
    if (!smem_set) {
        cudaFuncSetAttribute(tlstm, cudaFuncAttributeMaxDynamicSharedMemorySize,
                             TLSTM_SMEM);
        smem_set = 1;
    }

    // -------- CSR build + weight prep --------
    k_zeroi<<<(NN + TPB - 1) / TPB, blk>>>(indeg, NN);
    k_degi<<<(NE + TPB - 1) / TPB, blk>>>(dst);
    k_scan<<<1, 1024>>>();
    k_place<<<(NE + TPB - 1) / TPB, blk>>>(src, dst);
    k_gt<<<(LL * C * KG * C + TPB - 1) / TPB, blk>>>(g);
    k_cvtw<<<(NN * C + TPB - 1) / TPB, blk>>>(wih, whh, bih, bhh, x);
    k_ewall<<<(NE + TPB - 1) / TPB, blk>>>(ea, mu, sigma);

    // -------- GMMConv layers (K-split over blockIdx.z) --------
    const float* hin = x;
    for (int i = 0; i < LL; i++) {
        k_sacc<<<(NN * 32 + TPB - 1) / TPB, blk>>>(hin, i);
        const float* gti = gt + (size_t)i * KG * C * C;
        // z=0: hr = S[:, :512] @ gT[:512]  + bias   (reads only S)
        GA g0 = {S, gti, nullptr, nullptr,
                 hr, bias + i * C, 512, 0, KG * C, 0};
        // z=1: h  = S[:, 512:] @ gT[512:] + hin @ root  (owns in-place hin read)
        GA g1 = {S + 512, gti + (size_t)512 * C, hin, root + (size_t)i * C * C,
                 h, nullptr, 512, C, KG * C, C};
        tgemm<false, false><<<dim3(1, rowsN, 2), blk>>>(g0, g1, NN, C);
        k_zero<<<1, C>>>(bns, C);
        k_zero<<<1, C>>>(bnq, C);
        k_bnred<<<128, 128>>>();
        k_bnapp<<<gridNC, blk>>>(bng + i * C, bnb + i * C,
                                 hl + (size_t)i * NN * C,
                                 hlt + (size_t)(i + 1) * NN * C,
                                 (i < LL - 1) ? 1 : 0);
        hin = h;
    }

    // -------- bidirectional LSTM JumpingKnowledge (fused GEMM+cell) -------
    k_zero<<<(5 * NN + TPB - 1) / TPB, blk>>>(af, 5 * NN);
    k_zero<<<(5 * NN + TPB - 1) / TPB, blk>>>(ab, 5 * NN);
    for (int s = 0; s < 5; s++) {
        int tf = s, tb = 4 - s;
        const float* xf = hlt + (size_t)tf * NN * C;
        const float* xb = hlt + (size_t)tb * NN * C;
        tlstm<<<dim3(H / 32, rowsN, 2), blk, TLSTM_SMEM>>>(xf, xb, attw,
                                                           (s > 0) ? H : 0, s);
    }

    // attention softmax + weighted node representation
    k_nrep<<<NN, C>>>(x);

    // global mean pool
    k_zero<<<(NB + TPB - 1) / TPB, blk>>>(cnt, NB);
    k_zero<<<(NB * C + TPB - 1) / TPB, blk>>>(hg, NB * C);
    k_cnt<<<(NN + TPB - 1) / TPB, blk>>>(batch);
    k_pool<<<gridNC, blk>>>(batch);
    k_pdiv<<<(NB * C + TPB - 1) / TPB, blk>>>();

    // MLP + LayerNorm
    GA gp1 = {hg, p1w, nullptr, nullptr, z1, p1b, C, 0, C, 0};
    tgemm<false, true><<<dim3(NHID / 128, NB / 128, 1), blk>>>(gp1, gp1, NB, NHID);
    GA gp2 = {z1, p2w, nullptr, nullptr, z2, p2b, NHID, 0, NHID, 0};
    tgemm<false, false><<<dim3(NOUT / 128, NB / 128, 1), blk>>>(gp2, gp2, NB, NOUT);
    k_ln<<<NB, NOUT>>>(lng, lnb, out);
}

// round 9
// speedup vs baseline: 1.4785x; 1.4215x over previous
#include <cuda_runtime.h>
#include <cuda_fp16.h>
#include <math.h>
#include <stdint.h>

// ---------------- problem constants ----------------
namespace {
constexpr int NN   = 30000;   // nodes
constexpr int NE   = 480000;  // edges
constexpr int C    = 128;     // channels (= F)
constexpr int KG   = 8;       // gaussians
constexpr int LL   = 4;       // layers
constexpr int H    = 256;     // LSTM hidden
constexpr int H4   = 1024;    // 4*H
constexpr int NHID = 512;
constexpr int NOUT = 256;
constexpr int NB   = 1024;    // graphs
}

// ---------------- scratch (device globals; no allocations allowed) -------
__device__ __align__(256) float  d_h[NN * C];
__device__ __align__(256) float  d_hl[LL][NN * C];
__device__ __align__(256) __half d_hlth[5][NN * C];      // half x,h1..h4
__device__ __align__(256) __half d_Sh[NN * KG * C];
__device__ __align__(256) __half d_gth[LL * C * KG * C]; // [l][c][k*128+f]
__device__ __align__(256) __half d_rooth[LL * C * C];    // [l][c][f]
__device__ __align__(256) float  d_ew[LL][NE * KG];
__device__ __align__(256) float  d_bns[C];
__device__ __align__(256) float  d_bnq[C];
__device__ __align__(256) __half d_lhh[2][2][NN * H];    // [pingpong][dir]
__device__ __align__(256) float  d_lc[2][NN * H];
__device__ __align__(256) float  d_af[5 * NN];
__device__ __align__(256) float  d_ab[5 * NN];
__device__ __align__(256) float  d_nrep[NN * C];
__device__ __align__(256) float  d_cnt[NB];
__device__ __align__(256) float  d_hg[NB * C];
__device__ __align__(256) __half d_hgh[NB * C];
__device__ __align__(256) __half d_z1h[NB * NHID];
__device__ __align__(256) float  d_z2[NB * NOUT];
// half LSTM weights ([n][k] layout) + fused biases, half MLP weights
__device__ __align__(256) __half d_wihh[2 * H4 * C];
__device__ __align__(256) __half d_whhh[2 * H4 * H];
__device__ __align__(256) float  d_bsum[2 * H4];
__device__ __align__(256) __half d_p1wh[NHID * C];       // [n][k]
__device__ __align__(256) __half d_p2wh[NOUT * NHID];    // [n][k]
// CSR scratch
__device__ __align__(256) int d_indeg[NN];
__device__ __align__(256) int d_rowptr[NN + 1];
__device__ __align__(256) int d_curp[NN];
__device__ __align__(256) int d_eid[NE];
__device__ __align__(256) int d_esrc[NE];

// ---------------- helpers ----------------
__device__ __forceinline__ void mma16h(float* c, const uint32_t* a, const uint32_t* b) {
    asm volatile(
        "mma.sync.aligned.m16n8k16.row.col.f32.f16.f16.f32 "
        "{%0,%1,%2,%3}, {%4,%5,%6,%7}, {%8,%9}, {%0,%1,%2,%3};"
        : "+f"(c[0]), "+f"(c[1]), "+f"(c[2]), "+f"(c[3])
        : "r"(a[0]), "r"(a[1]), "r"(a[2]), "r"(a[3]), "r"(b[0]), "r"(b[1]));
}
__device__ __forceinline__ void cpa16(uint32_t sdst, const void* gsrc, int srcsz) {
    asm volatile("cp.async.ca.shared.global [%0], [%1], 16, %2;\n"
                 :: "r"(sdst), "l"(gsrc), "r"(srcsz));
}
__device__ __forceinline__ void cpa_commit() { asm volatile("cp.async.commit_group;\n"); }
__device__ __forceinline__ void cpa_wait1()  { asm volatile("cp.async.wait_group 1;\n"); }
__device__ __forceinline__ float sigf(float x) { return 1.f / (1.f + expf(-x)); }

// ---------------- FP16 tensor GEMM (cp.async 2-stage, dual-K, TB form) ----
// C[M,Nm] = A[M,Kd] @ B[Nm,Kd]^T (+ A2[M,Kd2] @ B2[Nm,Kd2]^T) (+bias)(relu)
// BK = 32 halves. Tile 128x128, 256 threads. smem rows: 16 data words + 4 pad.
struct GH {
    const __half* A;
    const __half* B;
    const __half* A2;
    const __half* B2;
    void* Cm;            // float* or __half* (OUTH)
    const float* bias;   // nullptr -> none
    int Kd;
    int Kd2;
};

template <bool RELU_, bool OUTH>
__global__ __launch_bounds__(256) void tgemm_h(GH ga, int M, int Nm)
{
    __shared__ uint32_t As[2][2560];   // [row][20]
    __shared__ uint32_t Bs[2][2560];

    const __half* __restrict__ A  = ga.A;
    const __half* __restrict__ B  = ga.B;
    const __half* __restrict__ A2 = ga.A2;
    const __half* __restrict__ B2 = ga.B2;
    const float* __restrict__ bias = ga.bias;
    const int Kd = ga.Kd, Kd2 = ga.Kd2;

    const int tid  = threadIdx.x;
    const int lane = tid & 31;
    const int wid  = tid >> 5;
    const int wm   = wid & 3;
    const int wn   = wid >> 2;
    const int gid  = lane >> 2;
    const int tig  = lane & 3;
    const int row0 = blockIdx.y * 128, col0 = blockIdx.x * 128;

    const int nt1 = Kd >> 5;
    const int nt  = nt1 + (Kd2 >> 5);

    float acc[2][8][4];
#pragma unroll
    for (int mi = 0; mi < 2; mi++)
#pragma unroll
        for (int ni = 0; ni < 8; ni++)
#pragma unroll
            for (int r = 0; r < 4; r++) acc[mi][ni][r] = 0.f;

    auto loadTile = [&](int t, int st) {
        const __half* Ap; const __half* Bp; int Kc, k0;
        if (t < nt1) { Ap = A;  Bp = B;  Kc = Kd;  k0 = t << 5; }
        else         { Ap = A2; Bp = B2; Kc = Kd2; k0 = (t - nt1) << 5; }
#pragma unroll
        for (int it = 0; it < 2; it++) {
            int idx = tid + it * 256;
            int rr = idx >> 2, part = idx & 3;
            int gr = row0 + rr;
            uint32_t dst = (uint32_t)__cvta_generic_to_shared(&As[st][rr * 20 + part * 4]);
            cpa16(dst, Ap + (size_t)gr * Kc + k0 + part * 8, gr < M ? 16 : 0);
        }
#pragma unroll
        for (int it = 0; it < 2; it++) {
            int idx = tid + it * 256;
            int rr = idx >> 2, part = idx & 3;
            uint32_t dst = (uint32_t)__cvta_generic_to_shared(&Bs[st][rr * 20 + part * 4]);
            cpa16(dst, Bp + (size_t)(col0 + rr) * Kc + k0 + part * 8, 16);
        }
    };

    loadTile(0, 0);
    cpa_commit();

    for (int t = 0; t < nt; t++) {
        if (t + 1 < nt) loadTile(t + 1, (t + 1) & 1);
        cpa_commit();
        cpa_wait1();
        __syncthreads();

        const int st = t & 1;
#pragma unroll
        for (int kk = 0; kk < 2; kk++) {
            uint32_t a[2][4], b[8][2];
#pragma unroll
            for (int mi = 0; mi < 2; mi++) {
                int mr = wm * 32 + mi * 16;
                a[mi][0] = As[st][(mr + gid)     * 20 + kk * 8 + tig];
                a[mi][1] = As[st][(mr + gid + 8) * 20 + kk * 8 + tig];
                a[mi][2] = As[st][(mr + gid)     * 20 + kk * 8 + 4 + tig];
                a[mi][3] = As[st][(mr + gid + 8) * 20 + kk * 8 + 4 + tig];
            }
#pragma unroll
            for (int ni = 0; ni < 8; ni++) {
                int nr = wn * 64 + ni * 8;
                b[ni][0] = Bs[st][(nr + gid) * 20 + kk * 8 + tig];
                b[ni][1] = Bs[st][(nr + gid) * 20 + kk * 8 + 4 + tig];
            }
#pragma unroll
            for (int mi = 0; mi < 2; mi++)
#pragma unroll
                for (int ni = 0; ni < 8; ni++)
                    mma16h(acc[mi][ni], a[mi], b[ni]);
        }
        __syncthreads();
    }

#pragma unroll
    for (int mi = 0; mi < 2; mi++) {
#pragma unroll
        for (int half_ = 0; half_ < 2; half_++) {
            int r = row0 + wm * 32 + mi * 16 + gid + half_ * 8;
            if (r >= M) continue;
#pragma unroll
            for (int ni = 0; ni < 8; ni++) {
                int cI = col0 + wn * 64 + ni * 8 + tig * 2;
                float v0 = acc[mi][ni][half_ * 2 + 0];
                float v1 = acc[mi][ni][half_ * 2 + 1];
                if (bias) { v0 += bias[cI]; v1 += bias[cI + 1]; }
                if (RELU_) { v0 = fmaxf(v0, 0.f); v1 = fmaxf(v1, 0.f); }
                if (OUTH) {
                    __half2* cp = (__half2*)((__half*)ga.Cm + (size_t)r * Nm + cI);
                    *cp = __floats2half2_rn(v0, v1);
                } else {
                    float* cp = (float*)ga.Cm + (size_t)r * Nm + cI;
                    cp[0] = v0; cp[1] = v1;
                }
            }
        }
    }
}

// ---------------- fused LSTM step (FP16): GEMM + cell + attention dot ----
// Tile 128 rows x (4 gates x 32 hidden). grid = (H/32, ceil(NN/128), 2).
// dynamic smem 40960B (mainloop 2x(A 10240 + B 10240)); epilogue reuses it.
__global__ __launch_bounds__(256) void tlstm(
    const __half* __restrict__ xf, const __half* __restrict__ xb,
    const float* __restrict__ attw, int K2, int s)
{
    extern __shared__ uint32_t sraw[];   // 10240 words = 40960 B
    // As stage st: sraw + st*2560 ; Bs stage st: sraw + 5120 + st*2560
    float* gbuf = (float*)sraw;          // epilogue: [64][133] = 34048 B

    const int dir  = blockIdx.z;
    const int c0   = blockIdx.x * 32;
    const int row0 = blockIdx.y * 128;
    const int pb   = s & 1;

    const __half* A  = dir ? xb : xf;
    const __half* B  = d_wihh + (size_t)dir * H4 * C;
    const __half* A2 = d_lhh[pb][dir];
    const __half* B2 = d_whhh + (size_t)dir * H4 * H;

    const int tid  = threadIdx.x;
    const int lane = tid & 31;
    const int wid  = tid >> 5;
    const int wm   = wid & 3;
    const int wn   = wid >> 2;
    const int gid  = lane >> 2;
    const int tig  = lane & 3;

    const int nt1 = C >> 5;              // 4
    const int nt  = nt1 + (K2 >> 5);     // 4 or 12

    float acc[2][8][4];
#pragma unroll
    for (int mi = 0; mi < 2; mi++)
#pragma unroll
        for (int ni = 0; ni < 8; ni++)
#pragma unroll
            for (int r = 0; r < 4; r++) acc[mi][ni][r] = 0.f;

    auto loadTile = [&](int t, int st) {
        const __half* Ap; const __half* Bp; int Kc, k0;
        if (t < nt1) { Ap = A;  Bp = B;  Kc = C; k0 = t << 5; }
        else         { Ap = A2; Bp = B2; Kc = H; k0 = (t - nt1) << 5; }
        uint32_t* Asb = sraw + st * 2560;
        uint32_t* Bsb = sraw + 5120 + st * 2560;
#pragma unroll
        for (int it = 0; it < 2; it++) {
            int idx = tid + it * 256;
            int rr = idx >> 2, part = idx & 3;
            int gr = row0 + rr;
            uint32_t dst = (uint32_t)__cvta_generic_to_shared(&Asb[rr * 20 + part * 4]);
            cpa16(dst, Ap + (size_t)gr * Kc + k0 + part * 8, gr < NN ? 16 : 0);
        }
#pragma unroll
        for (int it = 0; it < 2; it++) {
            int idx = tid + it * 256;
            int rr = idx >> 2, part = idx & 3;
            int brow = ((rr >> 5) << 8) + c0 + (rr & 31);   // gate*256 + c0 + j'
            uint32_t dst = (uint32_t)__cvta_generic_to_shared(&Bsb[rr * 20 + part * 4]);
            cpa16(dst, Bp + (size_t)brow * Kc + k0 + part * 8, 16);
        }
    };

    loadTile(0, 0);
    cpa_commit();

    for (int t = 0; t < nt; t++) {
        if (t + 1 < nt) loadTile(t + 1, (t + 1) & 1);
        cpa_commit();
        cpa_wait1();
        __syncthreads();

        const int st = t & 1;
        const uint32_t* Asb = sraw + st * 2560;
        const uint32_t* Bsb = sraw + 5120 + st * 2560;
#pragma unroll
        for (int kk = 0; kk < 2; kk++) {
            uint32_t a[2][4], b[8][2];
#pragma unroll
            for (int mi = 0; mi < 2; mi++) {
                int mr = wm * 32 + mi * 16;
                a[mi][0] = Asb[(mr + gid)     * 20 + kk * 8 + tig];
                a[mi][1] = Asb[(mr + gid + 8) * 20 + kk * 8 + tig];
                a[mi][2] = Asb[(mr + gid)     * 20 + kk * 8 + 4 + tig];
                a[mi][3] = Asb[(mr + gid + 8) * 20 + kk * 8 + 4 + tig];
            }
#pragma unroll
            for (int ni = 0; ni < 8; ni++) {
                int nr = wn * 64 + ni * 8;
                b[ni][0] = Bsb[(nr + gid) * 20 + kk * 8 + tig];
                b[ni][1] = Bsb[(nr + gid) * 20 + kk * 8 + 4 + tig];
            }
#pragma unroll
            for (int mi = 0; mi < 2; mi++)
#pragma unroll
                for (int ni = 0; ni < 8; ni++)
                    mma16h(acc[mi][ni], a[mi], b[ni]);
        }
        __syncthreads();
    }

    // ---- fused epilogue: two 64-row passes through smem ----
    const float* bs = d_bsum + (size_t)dir * H4;
    float* lc   = d_lc[dir];
    __half* lhw = d_lhh[1 - pb][dir];
    const int t_idx = dir ? (4 - s) : s;
    float* aout = (dir ? d_ab : d_af) + t_idx * NN;

#pragma unroll
    for (int p = 0; p < 2; p++) {
        __syncthreads();
        if ((wm >> 1) == p) {
#pragma unroll
            for (int mi = 0; mi < 2; mi++)
#pragma unroll
                for (int half_ = 0; half_ < 2; half_++) {
                    int rloc = (wm & 1) * 32 + mi * 16 + gid + half_ * 8;
#pragma unroll
                    for (int ni = 0; ni < 8; ni++) {
                        int col = wn * 64 + ni * 8 + tig * 2;
                        gbuf[rloc * 133 + col]     = acc[mi][ni][half_ * 2 + 0];
                        gbuf[rloc * 133 + col + 1] = acc[mi][ni][half_ * 2 + 1];
                    }
                }
        }
        __syncthreads();

        int rr = tid >> 2;                 // 0..63
        int n  = row0 + p * 64 + rr;
        bool valid = n < NN;
        float part = 0.f;
        if (valid) {
            int jb = (tid & 3) * 8;
#pragma unroll
            for (int q = 0; q < 8; q++) {
                int jl = jb + q;           // 0..31
                int j  = c0 + jl;          // 0..255
                float gi = gbuf[rr * 133 +  0 + jl] + bs[0 * H + j];
                float gf = gbuf[rr * 133 + 32 + jl] + bs[1 * H + j];
                float gg = gbuf[rr * 133 + 64 + jl] + bs[2 * H + j];
                float go = gbuf[rr * 133 + 96 + jl] + bs[3 * H + j];
                size_t ix = (size_t)n * H + j;
                float cprev = (K2 > 0) ? lc[ix] : 0.f;
                float cc = sigf(gf) * cprev + sigf(gi) * tanhf(gg);
                lc[ix] = cc;
                float hh = sigf(go) * tanhf(cc);
                lhw[ix] = __float2half_rn(hh);
                part = fmaf(hh, attw[dir * H + j], part);
            }
        }
        part += __shfl_down_sync(0xffffffffu, part, 2);
        part += __shfl_down_sync(0xffffffffu, part, 1);
        if (valid && (tid & 3) == 0) atomicAdd(&aout[n], part);
    }
}

// ---------------- small kernels ----------------
__global__ void k_zero(float* p, int n) {
    int i = blockIdx.x * blockDim.x + threadIdx.x;
    if (i < n) p[i] = 0.f;
}
__global__ void k_zeroi(int* p, int n) {
    int i = blockIdx.x * blockDim.x + threadIdx.x;
    if (i < n) p[i] = 0;
}

__global__ void k_degi(const int* __restrict__ dst) {
    int e = blockIdx.x * blockDim.x + threadIdx.x;
    if (e < NE) atomicAdd(&d_indeg[dst[e]], 1);
}

__global__ void k_scan() {
    const int T = 1024;
    __shared__ int buf[T];
    __shared__ int carry_s;
    int t = threadIdx.x;
    if (t == 0) carry_s = 0;
    __syncthreads();
    for (int base = 0; base < NN; base += T) {
        int v = (base + t < NN) ? d_indeg[base + t] : 0;
        buf[t] = v;
        __syncthreads();
        for (int off = 1; off < T; off <<= 1) {
            int add = (t >= off) ? buf[t - off] : 0;
            __syncthreads();
            buf[t] += add;
            __syncthreads();
        }
        int carry = carry_s;
        __syncthreads();
        if (base + t < NN) {
            d_rowptr[base + t] = carry + buf[t] - v;
            d_curp[base + t]   = carry + buf[t] - v;
        }
        if (t == T - 1) carry_s = carry + buf[t];
        __syncthreads();
    }
    if (t == 0) d_rowptr[NN] = carry_s;
}

__global__ void k_place(const int* __restrict__ src, const int* __restrict__ dst) {
    int e = blockIdx.x * blockDim.x + threadIdx.x;
    if (e >= NE) return;
    int slot = atomicAdd(&d_curp[dst[e]], 1);
    d_eid[slot]  = e;
    d_esrc[slot] = src[e];
}

// gT(half): [l][c][k*128+f] from g [l][f][k*128+c]; rootT(half): [l][c][f]
__global__ void k_gt_h(const float* __restrict__ g, const float* __restrict__ root) {
    int i = blockIdx.x * blockDim.x + threadIdx.x;
    if (i < LL * C * KG * C) {
        int l   = i >> 17;
        int rem = i & 131071;
        int cR  = rem >> 10;
        int kf  = rem & 1023;
        int k = kf >> 7, f = kf & 127;
        d_gth[i] = __float2half_rn(g[((size_t)(l * 128 + f)) * 1024 + k * 128 + cR]);
    }
    if (i < LL * C * C) {
        int l = i >> 14;
        int c = (i >> 7) & 127;
        int f = i & 127;
        d_rooth[i] = __float2half_rn(root[((size_t)(l * 128 + f)) * 128 + c]);
    }
}

// half LSTM/MLP weights, fused biases, x->half
__global__ void k_prep(const float* __restrict__ wih, const float* __restrict__ whh,
                       const float* __restrict__ bih, const float* __restrict__ bhh,
                       const float* __restrict__ x,
                       const float* __restrict__ p1w, const float* __restrict__ p2w) {
    int i = blockIdx.x * blockDim.x + threadIdx.x;
    if (i < NN * C)       d_hlth[0][i] = __float2half_rn(x[i]);
    if (i < 2 * H4 * C)   d_wihh[i] = __float2half_rn(wih[i]);
    if (i < 2 * H4 * H)   d_whhh[i] = __float2half_rn(whh[i]);
    if (i < 2 * H4)       d_bsum[i] = bih[i] + bhh[i];
    if (i < NHID * C)  {  // [n][c] from p1w [c][NHID]
        int n = i / C, c = i % C;
        d_p1wh[i] = __float2half_rn(p1w[(size_t)c * NHID + n]);
    }
    if (i < NOUT * NHID) {  // [n][k] from p2w [NHID][NOUT]
        int n = i / NHID, k = i % NHID;
        d_p2wh[i] = __float2half_rn(p2w[(size_t)k * NOUT + n]);
    }
}

// all-layer gaussian weights in one launch
__global__ void k_ewall(const float* __restrict__ ea,
                        const float* __restrict__ mu,
                        const float* __restrict__ sg) {
    int e = blockIdx.x * blockDim.x + threadIdx.x;
    if (e >= NE) return;
    float a0 = ea[e * 2 + 0], a1 = ea[e * 2 + 1];
#pragma unroll
    for (int l = 0; l < LL; l++) {
        const float* mul = mu + l * KG * 2;
        const float* sgl = sg + l * KG * 2;
#pragma unroll
        for (int k = 0; k < KG; k++) {
            float dx = a0 - mul[k * 2 + 0];
            float dy = a1 - mul[k * 2 + 1];
            float s0 = sgl[k * 2 + 0], s1 = sgl[k * 2 + 1];
            float w = expf(-0.5f * (dx * dx / (1e-15f + s0 * s0) +
                                    dy * dy / (1e-15f + s1 * s1)));
            d_ew[l][(size_t)e * KG + k] = w;
        }
    }
}

// S accumulation (warp per node) -> half output
__global__ void k_sacc(const float* __restrict__ hin, int layer) {
    int n = (blockIdx.x * blockDim.x + threadIdx.x) >> 5;
    int l = threadIdx.x & 31;
    if (n >= NN) return;
    const float* ewl = d_ew[layer];
    int beg = d_rowptr[n], end = d_rowptr[n + 1];
    float acc[KG][4];
#pragma unroll
    for (int k = 0; k < KG; k++)
#pragma unroll
        for (int q = 0; q < 4; q++) acc[k][q] = 0.f;

    for (int p = beg; p < end; p++) {
        int e = d_eid[p], s = d_esrc[p];
        float wv = (l < KG) ? ewl[(size_t)e * KG + l] : 0.f;
        const float* hrp = hin + (size_t)s * C;
        float hv0 = hrp[l], hv1 = hrp[l + 32], hv2 = hrp[l + 64], hv3 = hrp[l + 96];
#pragma unroll
        for (int k = 0; k < KG; k++) {
            float wk = __shfl_sync(0xffffffffu, wv, k);
            acc[k][0] = fmaf(wk, hv0, acc[k][0]);
            acc[k][1] = fmaf(wk, hv1, acc[k][1]);
            acc[k][2] = fmaf(wk, hv2, acc[k][2]);
            acc[k][3] = fmaf(wk, hv3, acc[k][3]);
        }
    }
    float inv = 1.f / fmaxf((float)(end - beg), 1.f);
    __half* Sp = &d_Sh[(size_t)n * (KG * C)];
#pragma unroll
    for (int k = 0; k < KG; k++) {
        Sp[k * C + l +  0] = __float2half_rn(acc[k][0] * inv);
        Sp[k * C + l + 32] = __float2half_rn(acc[k][1] * inv);
        Sp[k * C + l + 64] = __float2half_rn(acc[k][2] * inv);
        Sp[k * C + l + 96] = __float2half_rn(acc[k][3] * inv);
    }
}

__global__ void k_bnred() {  // <<<128,128>>>
    int c = threadIdx.x;
    float s = 0.f, q = 0.f;
    for (int r = blockIdx.x; r < NN; r += gridDim.x) {
        float v = d_h[(size_t)r * C + c];
        s += v; q += v * v;
    }
    atomicAdd(&d_bns[c], s);
    atomicAdd(&d_bnq[c], q);
}

__global__ void k_bnapp(const float* __restrict__ gamma,
                        const float* __restrict__ beta,
                        float* __restrict__ out_hl,
                        __half* __restrict__ out_hlt, int relu) {
    int i = blockIdx.x * blockDim.x + threadIdx.x;
    if (i >= NN * C) return;
    int c = i % C;
    float mean = d_bns[c] / (float)NN;
    float var  = d_bnq[c] / (float)NN - mean * mean;
    float v = (d_h[i] - mean) * rsqrtf(var + 1e-5f) * gamma[c] + beta[c];
    if (relu) v = fmaxf(v, 0.f);
    d_h[i] = v;
    out_hl[i]  = v;
    out_hlt[i] = __float2half_rn(v);
}

__global__ void k_nrep(const float* __restrict__ x) {
    int n = blockIdx.x;
    int c = threadIdx.x;
    __shared__ float p[5];
    if (c == 0) {
        float a[5], m = -1e30f;
#pragma unroll
        for (int t = 0; t < 5; t++) {
            a[t] = d_af[t * NN + n] + d_ab[t * NN + n];
            m = fmaxf(m, a[t]);
        }
        float s = 0.f;
#pragma unroll
        for (int t = 0; t < 5; t++) { a[t] = expf(a[t] - m); s += a[t]; }
#pragma unroll
        for (int t = 0; t < 5; t++) p[t] = a[t] / s;
    }
    __syncthreads();
    float r = p[0] * x[(size_t)n * C + c];
#pragma unroll
    for (int t = 1; t < 5; t++) r = fmaf(p[t], d_hl[t - 1][(size_t)n * C + c], r);
    d_nrep[(size_t)n * C + c] = r;
}

__global__ void k_cnt(const int* __restrict__ batch) {
    int n = blockIdx.x * blockDim.x + threadIdx.x;
    if (n < NN) atomicAdd(&d_cnt[batch[n]], 1.f);
}

__global__ void k_pool(const int* __restrict__ batch) {
    int i = blockIdx.x * blockDim.x + threadIdx.x;
    if (i >= NN * C) return;
    int n = i / C, c = i % C;
    atomicAdd(&d_hg[(size_t)batch[n] * C + c], d_nrep[i]);
}

__global__ void k_pdiv() {
    int i = blockIdx.x * blockDim.x + threadIdx.x;
    if (i >= NB * C) return;
    float v = d_hg[i] / fmaxf(d_cnt[i / C], 1.f);
    d_hg[i]  = v;
    d_hgh[i] = __float2half_rn(v);
}

__global__ void k_ln(const float* __restrict__ g, const float* __restrict__ b,
                     float* __restrict__ out) {
    int row = blockIdx.x, t = threadIdx.x;
    __shared__ float sm[NOUT];
    float v = d_z2[(size_t)row * NOUT + t];
    sm[t] = v;
    __syncthreads();
    for (int o = NOUT / 2; o > 0; o >>= 1) {
        if (t < o) sm[t] += sm[t + o];
        __syncthreads();
    }
    float mean = sm[0] / (float)NOUT;
    __syncthreads();
    float dv = v - mean;
    sm[t] = dv * dv;
    __syncthreads();
    for (int o = NOUT / 2; o > 0; o >>= 1) {
        if (t < o) sm[t] += sm[t + o];
        __syncthreads();
    }
    float var = sm[0] / (float)NOUT;
    out[(size_t)row * NOUT + t] = dv * rsqrtf(var + 1e-5f) * g[t] + b[t];
}

// ---------------- host ----------------
static float* symf(const void* s) {
    void* p = nullptr;
    cudaGetSymbolAddress(&p, s);
    return (float*)p;
}
static __half* symh(const void* s) {
    void* p = nullptr;
    cudaGetSymbolAddress(&p, s);
    return (__half*)p;
}
static int* symi(const void* s) {
    void* p = nullptr;
    cudaGetSymbolAddress(&p, s);
    return (int*)p;
}

extern "C" void kernel_launch(void* const* d_in, const int* in_sizes, int n_in,
                              void* d_out, int out_size) {
    const float* x     = (const float*)d_in[0];
    const int*   ei    = (const int*)d_in[1];
    const int*   src   = ei;
    const int*   dst   = ei + NE;
    const float* ea    = (const float*)d_in[2];
    const int*   batch = (const int*)d_in[3];
    const float* g     = (const float*)d_in[4];
    const float* root  = (const float*)d_in[5];
    const float* bias  = (const float*)d_in[6];
    const float* mu    = (const float*)d_in[7];
    const float* sigma = (const float*)d_in[8];
    const float* bng   = (const float*)d_in[9];
    const float* bnb   = (const float*)d_in[10];
    const float* wih   = (const float*)d_in[11];
    const float* whh   = (const float*)d_in[12];
    const float* bih   = (const float*)d_in[13];
    const float* bhh   = (const float*)d_in[14];
    const float* attw  = (const float*)d_in[15];
    const float* p1w   = (const float*)d_in[17];
    const float* p1b   = (const float*)d_in[18];
    const float* p2w   = (const float*)d_in[19];
    const float* p2b   = (const float*)d_in[20];
    const float* lng   = (const float*)d_in[21];
    const float* lnb   = (const float*)d_in[22];
    float* out = (float*)d_out;

    float*  h    = symf(d_h);
    float*  hl   = symf(d_hl);
    __half* hlth = symh(d_hlth);
    __half* Sh   = symh(d_Sh);
    __half* gth  = symh(d_gth);
    __half* rooth = symh(d_rooth);
    float*  bns  = symf(d_bns);
    float*  bnq  = symf(d_bnq);
    float*  af   = symf(d_af);
    float*  ab   = symf(d_ab);
    float*  cnt  = symf(d_cnt);
    float*  hg   = symf(d_hg);
    __half* hgh  = symh(d_hgh);
    __half* z1h  = symh(d_z1h);
    float*  z2   = symf(d_z2);
    __half* p1wh = symh(d_p1wh);
    __half* p2wh = symh(d_p2wh);
    int* indeg   = symi(d_indeg);

    const int TPB = 256;
    const dim3 blk(TPB);
    const int gridNC = (NN * C + TPB - 1) / TPB;
    const int rowsN  = (NN + 127) / 128;
    const int TLSTM_SMEM = 40960;

    static int smem_set = 0;
    if (!smem_set) {
        cudaFuncSetAttribute(tlstm, cudaFuncAttributeMaxDynamicSharedMemorySize,
                             TLSTM_SMEM);
        smem_set = 1;
    }

    // -------- CSR build + weight prep --------
    k_zeroi<<<(NN + TPB - 1) / TPB, blk>>>(indeg, NN);
    k_degi<<<(NE + TPB - 1) / TPB, blk>>>(dst);
    k_scan<<<1, 1024>>>();
    k_place<<<(NE + TPB - 1) / TPB, blk>>>(src, dst);
    k_gt_h<<<(LL * C * KG * C + TPB - 1) / TPB, blk>>>(g, root);
    k_prep<<<(NN * C + TPB - 1) / TPB, blk>>>(wih, whh, bih, bhh, x, p1w, p2w);
    k_ewall<<<(NE + TPB - 1) / TPB, blk>>>(ea, mu, sigma);

    // -------- GMMConv layers --------
    const float* hin = x;
    for (int i = 0; i < LL; i++) {
        k_sacc<<<(NN * 32 + TPB - 1) / TPB, blk>>>(hin, i);
        // h = S @ gT[i]^T + hlt[i] @ rootT[i]^T + bias (dual-K fp16 GEMM)
        GH gl = {Sh, gth + (size_t)i * C * KG * C,
                 hlth + (size_t)i * NN * C, rooth + (size_t)i * C * C,
                 h, bias + i * C, KG * C, C};
        tgemm_h<false, false><<<dim3(1, rowsN), blk>>>(gl, NN, C);
        k_zero<<<1, C>>>(bns, C);
        k_zero<<<1, C>>>(bnq, C);
        k_bnred<<<128, 128>>>();
        k_bnapp<<<gridNC, blk>>>(bng + i * C, bnb + i * C,
                                 hl + (size_t)i * NN * C,
                                 hlth + (size_t)(i + 1) * NN * C,
                                 (i < LL - 1) ? 1 : 0);
        hin = h;
    }

    // -------- bidirectional LSTM JumpingKnowledge (fused fp16 GEMM+cell) --
    k_zero<<<(5 * NN + TPB - 1) / TPB, blk>>>(af, 5 * NN);
    k_zero<<<(5 * NN + TPB - 1) / TPB, blk>>>(ab, 5 * NN);
    for (int s = 0; s < 5; s++) {
        int tf = s, tb = 4 - s;
        const __half* xf = hlth + (size_t)tf * NN * C;
        const __half* xb = hlth + (size_t)tb * NN * C;
        tlstm<<<dim3(H / 32, rowsN, 2), blk, TLSTM_SMEM>>>(xf, xb, attw,
                                                           (s > 0) ? H : 0, s);
    }

    // attention softmax + weighted node representation
    k_nrep<<<NN, C>>>(x);

    // global mean pool
    k_zero<<<(NB + TPB - 1) / TPB, blk>>>(cnt, NB);
    k_zero<<<(NB * C + TPB - 1) / TPB, blk>>>(hg, NB * C);
    k_cnt<<<(NN + TPB - 1) / TPB, blk>>>(batch);
    k_pool<<<gridNC, blk>>>(batch);
    k_pdiv<<<(NB * C + TPB - 1) / TPB, blk>>>();

    // MLP + LayerNorm (fp16 GEMMs)
    GH gp1 = {hgh, p1wh, nullptr, nullptr, z1h, p1b, C, 0};
    tgemm_h<true, true><<<dim3(NHID / 128, NB / 128), blk>>>(gp1, NB, NHID);
    GH gp2 = {z1h, p2wh, nullptr, nullptr, z2, p2b, NHID, 0};
    tgemm_h<false, false><<<dim3(NOUT / 128, NB / 128), blk>>>(gp2, NB, NOUT);
    k_ln<<<NB, NOUT>>>(lng, lnb, out);
}

// round 10
// speedup vs baseline: 1.6006x; 1.0825x over previous
#include <cuda_runtime.h>
#include <cuda_fp16.h>
#include <math.h>
#include <stdint.h>

// ---------------- problem constants ----------------
namespace {
constexpr int NN   = 30000;   // nodes
constexpr int NE   = 480000;  // edges
constexpr int C    = 128;     // channels (= F)
constexpr int KG   = 8;       // gaussians
constexpr int LL   = 4;       // layers
constexpr int H    = 256;     // LSTM hidden
constexpr int H4   = 1024;    // 4*H
constexpr int NHID = 512;
constexpr int NOUT = 256;
constexpr int NB   = 1024;    // graphs
}

// ---------------- scratch (device globals; no allocations allowed) -------
__device__ __align__(256) float  d_h[NN * C];
__device__ __align__(256) float  d_hl[LL][NN * C];
__device__ __align__(256) __half d_hlth[5][NN * C];      // half x,h1..h4
__device__ __align__(256) __half d_Sh[NN * KG * C];
__device__ __align__(256) __half d_gth[LL * C * KG * C]; // [l][c][k*128+f]
__device__ __align__(256) __half d_rooth[LL * C * C];    // [l][c][f]
__device__ __align__(256) __half d_ewh[LL][NE * KG];
__device__ __align__(256) float  d_bns[C];
__device__ __align__(256) float  d_bnq[C];
__device__ __align__(256) __half d_lhh[2][2][NN * H];    // [pingpong][dir]
__device__ __align__(256) float  d_lc[2][NN * H];
__device__ __align__(256) float  d_af[5 * NN];
__device__ __align__(256) float  d_ab[5 * NN];
__device__ __align__(256) float  d_cnt[NB];
__device__ __align__(256) float  d_hg[NB * C];
__device__ __align__(256) __half d_hgh[NB * C];
__device__ __align__(256) __half d_z1h[NB * NHID];
__device__ __align__(256) float  d_z2[NB * NOUT];
// half LSTM weights ([n][k] layout) + fused biases, half MLP weights
__device__ __align__(256) __half d_wihh[2 * H4 * C];
__device__ __align__(256) __half d_whhh[2 * H4 * H];
__device__ __align__(256) float  d_bsum[2 * H4];
__device__ __align__(256) __half d_p1wh[NHID * C];       // [n][k]
__device__ __align__(256) __half d_p2wh[NOUT * NHID];    // [n][k]
// CSR scratch
__device__ __align__(256) int d_indeg[NN];
__device__ __align__(256) int d_rowptr[NN + 1];
__device__ __align__(256) int d_curp[NN];
__device__ __align__(256) int d_eid[NE];
__device__ __align__(256) int d_esrc[NE];

// ---------------- helpers ----------------
__device__ __forceinline__ void mma16h(float* c, const uint32_t* a, const uint32_t* b) {
    asm volatile(
        "mma.sync.aligned.m16n8k16.row.col.f32.f16.f16.f32 "
        "{%0,%1,%2,%3}, {%4,%5,%6,%7}, {%8,%9}, {%0,%1,%2,%3};"
        : "+f"(c[0]), "+f"(c[1]), "+f"(c[2]), "+f"(c[3])
        : "r"(a[0]), "r"(a[1]), "r"(a[2]), "r"(a[3]), "r"(b[0]), "r"(b[1]));
}
__device__ __forceinline__ void cpa16(uint32_t sdst, const void* gsrc, int srcsz) {
    asm volatile("cp.async.ca.shared.global [%0], [%1], 16, %2;\n"
                 :: "r"(sdst), "l"(gsrc), "r"(srcsz));
}
__device__ __forceinline__ void cpa_commit() { asm volatile("cp.async.commit_group;\n"); }
__device__ __forceinline__ void cpa_wait1()  { asm volatile("cp.async.wait_group 1;\n"); }
__device__ __forceinline__ float sigf(float x) { return 1.f / (1.f + expf(-x)); }

// ---------------- FP16 tensor GEMM (cp.async 2-stage, dual-K, TB form) ----
struct GH {
    const __half* A;
    const __half* B;
    const __half* A2;
    const __half* B2;
    void* Cm;            // float* or __half* (OUTH)
    const float* bias;   // nullptr -> none
    int Kd;
    int Kd2;
};

template <bool RELU_, bool OUTH>
__global__ __launch_bounds__(256) void tgemm_h(GH ga, int M, int Nm)
{
    __shared__ uint32_t As[2][2560];   // [row][20]
    __shared__ uint32_t Bs[2][2560];

    const __half* __restrict__ A  = ga.A;
    const __half* __restrict__ B  = ga.B;
    const __half* __restrict__ A2 = ga.A2;
    const __half* __restrict__ B2 = ga.B2;
    const float* __restrict__ bias = ga.bias;
    const int Kd = ga.Kd, Kd2 = ga.Kd2;

    const int tid  = threadIdx.x;
    const int lane = tid & 31;
    const int wid  = tid >> 5;
    const int wm   = wid & 3;
    const int wn   = wid >> 2;
    const int gid  = lane >> 2;
    const int tig  = lane & 3;
    const int row0 = blockIdx.y * 128, col0 = blockIdx.x * 128;

    const int nt1 = Kd >> 5;
    const int nt  = nt1 + (Kd2 >> 5);

    float acc[2][8][4];
#pragma unroll
    for (int mi = 0; mi < 2; mi++)
#pragma unroll
        for (int ni = 0; ni < 8; ni++)
#pragma unroll
            for (int r = 0; r < 4; r++) acc[mi][ni][r] = 0.f;

    auto loadTile = [&](int t, int st) {
        const __half* Ap; const __half* Bp; int Kc, k0;
        if (t < nt1) { Ap = A;  Bp = B;  Kc = Kd;  k0 = t << 5; }
        else         { Ap = A2; Bp = B2; Kc = Kd2; k0 = (t - nt1) << 5; }
#pragma unroll
        for (int it = 0; it < 2; it++) {
            int idx = tid + it * 256;
            int rr = idx >> 2, part = idx & 3;
            int gr = row0 + rr;
            uint32_t dst = (uint32_t)__cvta_generic_to_shared(&As[st][rr * 20 + part * 4]);
            cpa16(dst, Ap + (size_t)gr * Kc + k0 + part * 8, gr < M ? 16 : 0);
        }
#pragma unroll
        for (int it = 0; it < 2; it++) {
            int idx = tid + it * 256;
            int rr = idx >> 2, part = idx & 3;
            uint32_t dst = (uint32_t)__cvta_generic_to_shared(&Bs[st][rr * 20 + part * 4]);
            cpa16(dst, Bp + (size_t)(col0 + rr) * Kc + k0 + part * 8, 16);
        }
    };

    loadTile(0, 0);
    cpa_commit();

    for (int t = 0; t < nt; t++) {
        if (t + 1 < nt) loadTile(t + 1, (t + 1) & 1);
        cpa_commit();
        cpa_wait1();
        __syncthreads();

        const int st = t & 1;
#pragma unroll
        for (int kk = 0; kk < 2; kk++) {
            uint32_t a[2][4], b[8][2];
#pragma unroll
            for (int mi = 0; mi < 2; mi++) {
                int mr = wm * 32 + mi * 16;
                a[mi][0] = As[st][(mr + gid)     * 20 + kk * 8 + tig];
                a[mi][1] = As[st][(mr + gid + 8) * 20 + kk * 8 + tig];
                a[mi][2] = As[st][(mr + gid)     * 20 + kk * 8 + 4 + tig];
                a[mi][3] = As[st][(mr + gid + 8) * 20 + kk * 8 + 4 + tig];
            }
#pragma unroll
            for (int ni = 0; ni < 8; ni++) {
                int nr = wn * 64 + ni * 8;
                b[ni][0] = Bs[st][(nr + gid) * 20 + kk * 8 + tig];
                b[ni][1] = Bs[st][(nr + gid) * 20 + kk * 8 + 4 + tig];
            }
#pragma unroll
            for (int mi = 0; mi < 2; mi++)
#pragma unroll
                for (int ni = 0; ni < 8; ni++)
                    mma16h(acc[mi][ni], a[mi], b[ni]);
        }
        __syncthreads();
    }

#pragma unroll
    for (int mi = 0; mi < 2; mi++) {
#pragma unroll
        for (int half_ = 0; half_ < 2; half_++) {
            int r = row0 + wm * 32 + mi * 16 + gid + half_ * 8;
            if (r >= M) continue;
#pragma unroll
            for (int ni = 0; ni < 8; ni++) {
                int cI = col0 + wn * 64 + ni * 8 + tig * 2;
                float v0 = acc[mi][ni][half_ * 2 + 0];
                float v1 = acc[mi][ni][half_ * 2 + 1];
                if (bias) { v0 += bias[cI]; v1 += bias[cI + 1]; }
                if (RELU_) { v0 = fmaxf(v0, 0.f); v1 = fmaxf(v1, 0.f); }
                if (OUTH) {
                    __half2* cp = (__half2*)((__half*)ga.Cm + (size_t)r * Nm + cI);
                    *cp = __floats2half2_rn(v0, v1);
                } else {
                    float* cp = (float*)ga.Cm + (size_t)r * Nm + cI;
                    cp[0] = v0; cp[1] = v1;
                }
            }
        }
    }
}

// ---------------- fused LSTM step (FP16): GEMM + cell + attention dot ----
__global__ __launch_bounds__(256) void tlstm(
    const __half* __restrict__ xf, const __half* __restrict__ xb,
    const float* __restrict__ attw, int K2, int s)
{
    extern __shared__ uint32_t sraw[];   // 10240 words = 40960 B
    float* gbuf = (float*)sraw;          // epilogue: [64][133]

    const int dir  = blockIdx.z;
    const int c0   = blockIdx.x * 32;
    const int row0 = blockIdx.y * 128;
    const int pb   = s & 1;

    const __half* A  = dir ? xb : xf;
    const __half* B  = d_wihh + (size_t)dir * H4 * C;
    const __half* A2 = d_lhh[pb][dir];
    const __half* B2 = d_whhh + (size_t)dir * H4 * H;

    const int tid  = threadIdx.x;
    const int lane = tid & 31;
    const int wid  = tid >> 5;
    const int wm   = wid & 3;
    const int wn   = wid >> 2;
    const int gid  = lane >> 2;
    const int tig  = lane & 3;

    const int nt1 = C >> 5;              // 4
    const int nt  = nt1 + (K2 >> 5);     // 4 or 12

    float acc[2][8][4];
#pragma unroll
    for (int mi = 0; mi < 2; mi++)
#pragma unroll
        for (int ni = 0; ni < 8; ni++)
#pragma unroll
            for (int r = 0; r < 4; r++) acc[mi][ni][r] = 0.f;

    auto loadTile = [&](int t, int st) {
        const __half* Ap; const __half* Bp; int Kc, k0;
        if (t < nt1) { Ap = A;  Bp = B;  Kc = C; k0 = t << 5; }
        else         { Ap = A2; Bp = B2; Kc = H; k0 = (t - nt1) << 5; }
        uint32_t* Asb = sraw + st * 2560;
        uint32_t* Bsb = sraw + 5120 + st * 2560;
#pragma unroll
        for (int it = 0; it < 2; it++) {
            int idx = tid + it * 256;
            int rr = idx >> 2, part = idx & 3;
            int gr = row0 + rr;
            uint32_t dst = (uint32_t)__cvta_generic_to_shared(&Asb[rr * 20 + part * 4]);
            cpa16(dst, Ap + (size_t)gr * Kc + k0 + part * 8, gr < NN ? 16 : 0);
        }
#pragma unroll
        for (int it = 0; it < 2; it++) {
            int idx = tid + it * 256;
            int rr = idx >> 2, part = idx & 3;
            int brow = ((rr >> 5) << 8) + c0 + (rr & 31);   // gate*256 + c0 + j'
            uint32_t dst = (uint32_t)__cvta_generic_to_shared(&Bsb[rr * 20 + part * 4]);
            cpa16(dst, Bp + (size_t)brow * Kc + k0 + part * 8, 16);
        }
    };

    loadTile(0, 0);
    cpa_commit();

    for (int t = 0; t < nt; t++) {
        if (t + 1 < nt) loadTile(t + 1, (t + 1) & 1);
        cpa_commit();
        cpa_wait1();
        __syncthreads();

        const int st = t & 1;
        const uint32_t* Asb = sraw + st * 2560;
        const uint32_t* Bsb = sraw + 5120 + st * 2560;
#pragma unroll
        for (int kk = 0; kk < 2; kk++) {
            uint32_t a[2][4], b[8][2];
#pragma unroll
            for (int mi = 0; mi < 2; mi++) {
                int mr = wm * 32 + mi * 16;
                a[mi][0] = Asb[(mr + gid)     * 20 + kk * 8 + tig];
                a[mi][1] = Asb[(mr + gid + 8) * 20 + kk * 8 + tig];
                a[mi][2] = Asb[(mr + gid)     * 20 + kk * 8 + 4 + tig];
                a[mi][3] = Asb[(mr + gid + 8) * 20 + kk * 8 + 4 + tig];
            }
#pragma unroll
            for (int ni = 0; ni < 8; ni++) {
                int nr = wn * 64 + ni * 8;
                b[ni][0] = Bsb[(nr + gid) * 20 + kk * 8 + tig];
                b[ni][1] = Bsb[(nr + gid) * 20 + kk * 8 + 4 + tig];
            }
#pragma unroll
            for (int mi = 0; mi < 2; mi++)
#pragma unroll
                for (int ni = 0; ni < 8; ni++)
                    mma16h(acc[mi][ni], a[mi], b[ni]);
        }
        __syncthreads();
    }

    // ---- fused epilogue: two 64-row passes through smem ----
    const float* bs = d_bsum + (size_t)dir * H4;
    float* lc   = d_lc[dir];
    __half* lhw = d_lhh[1 - pb][dir];
    const int t_idx = dir ? (4 - s) : s;
    float* aout = (dir ? d_ab : d_af) + t_idx * NN;

#pragma unroll
    for (int p = 0; p < 2; p++) {
        __syncthreads();
        if ((wm >> 1) == p) {
#pragma unroll
            for (int mi = 0; mi < 2; mi++)
#pragma unroll
                for (int half_ = 0; half_ < 2; half_++) {
                    int rloc = (wm & 1) * 32 + mi * 16 + gid + half_ * 8;
#pragma unroll
                    for (int ni = 0; ni < 8; ni++) {
                        int col = wn * 64 + ni * 8 + tig * 2;
                        gbuf[rloc * 133 + col]     = acc[mi][ni][half_ * 2 + 0];
                        gbuf[rloc * 133 + col + 1] = acc[mi][ni][half_ * 2 + 1];
                    }
                }
        }
        __syncthreads();

        int rr = tid >> 2;                 // 0..63
        int n  = row0 + p * 64 + rr;
        bool valid = n < NN;
        float part = 0.f;
        if (valid) {
            int jb = (tid & 3) * 8;
#pragma unroll
            for (int q = 0; q < 8; q++) {
                int jl = jb + q;           // 0..31
                int j  = c0 + jl;          // 0..255
                float gi = gbuf[rr * 133 +  0 + jl] + bs[0 * H + j];
                float gf = gbuf[rr * 133 + 32 + jl] + bs[1 * H + j];
                float gg = gbuf[rr * 133 + 64 + jl] + bs[2 * H + j];
                float go = gbuf[rr * 133 + 96 + jl] + bs[3 * H + j];
                size_t ix = (size_t)n * H + j;
                float cprev = (K2 > 0) ? lc[ix] : 0.f;
                float cc = sigf(gf) * cprev + sigf(gi) * tanhf(gg);
                lc[ix] = cc;
                float hh = sigf(go) * tanhf(cc);
                lhw[ix] = __float2half_rn(hh);
                part = fmaf(hh, attw[dir * H + j], part);
            }
        }
        part += __shfl_down_sync(0xffffffffu, part, 2);
        part += __shfl_down_sync(0xffffffffu, part, 1);
        if (valid && (tid & 3) == 0) atomicAdd(&aout[n], part);
    }
}

// ---------------- small kernels ----------------
__global__ void k_zero(float* p, int n) {
    int i = blockIdx.x * blockDim.x + threadIdx.x;
    if (i < n) p[i] = 0.f;
}
__global__ void k_zeroi(int* p, int n) {
    int i = blockIdx.x * blockDim.x + threadIdx.x;
    if (i < n) p[i] = 0;
}
__global__ void k_zero2() {   // zero bns+bnq in one tiny launch
    int i = threadIdx.x;
    d_bns[i] = 0.f;
    d_bnq[i] = 0.f;
}

__global__ void k_degi(const int* __restrict__ dst) {
    int e = blockIdx.x * blockDim.x + threadIdx.x;
    if (e < NE) atomicAdd(&d_indeg[dst[e]], 1);
}

__global__ void k_scan() {
    const int T = 1024;
    __shared__ int buf[T];
    __shared__ int carry_s;
    int t = threadIdx.x;
    if (t == 0) carry_s = 0;
    __syncthreads();
    for (int base = 0; base < NN; base += T) {
        int v = (base + t < NN) ? d_indeg[base + t] : 0;
        buf[t] = v;
        __syncthreads();
        for (int off = 1; off < T; off <<= 1) {
            int add = (t >= off) ? buf[t - off] : 0;
            __syncthreads();
            buf[t] += add;
            __syncthreads();
        }
        int carry = carry_s;
        __syncthreads();
        if (base + t < NN) {
            d_rowptr[base + t] = carry + buf[t] - v;
            d_curp[base + t]   = carry + buf[t] - v;
        }
        if (t == T - 1) carry_s = carry + buf[t];
        __syncthreads();
    }
    if (t == 0) d_rowptr[NN] = carry_s;
}

__global__ void k_place(const int* __restrict__ src, const int* __restrict__ dst) {
    int e = blockIdx.x * blockDim.x + threadIdx.x;
    if (e >= NE) return;
    int slot = atomicAdd(&d_curp[dst[e]], 1);
    d_eid[slot]  = e;
    d_esrc[slot] = src[e];
}

// gT(half): [l][c][k*128+f] from g; rootT(half): [l][c][f]
__global__ void k_gt_h(const float* __restrict__ g, const float* __restrict__ root) {
    int i = blockIdx.x * blockDim.x + threadIdx.x;
    if (i < LL * C * KG * C) {
        int l   = i >> 17;
        int rem = i & 131071;
        int cR  = rem >> 10;
        int kf  = rem & 1023;
        int k = kf >> 7, f = kf & 127;
        d_gth[i] = __float2half_rn(g[((size_t)(l * 128 + f)) * 1024 + k * 128 + cR]);
    }
    if (i < LL * C * C) {
        int l = i >> 14;
        int c = (i >> 7) & 127;
        int f = i & 127;
        d_rooth[i] = __float2half_rn(root[((size_t)(l * 128 + f)) * 128 + c]);
    }
}

// half LSTM/MLP weights, fused biases, x->half
__global__ void k_prep(const float* __restrict__ wih, const float* __restrict__ whh,
                       const float* __restrict__ bih, const float* __restrict__ bhh,
                       const float* __restrict__ x,
                       const float* __restrict__ p1w, const float* __restrict__ p2w) {
    int i = blockIdx.x * blockDim.x + threadIdx.x;
    if (i < NN * C)       d_hlth[0][i] = __float2half_rn(x[i]);
    if (i < 2 * H4 * C)   d_wihh[i] = __float2half_rn(wih[i]);
    if (i < 2 * H4 * H)   d_whhh[i] = __float2half_rn(whh[i]);
    if (i < 2 * H4)       d_bsum[i] = bih[i] + bhh[i];
    if (i < NHID * C)  {
        int n = i / C, c = i % C;
        d_p1wh[i] = __float2half_rn(p1w[(size_t)c * NHID + n]);
    }
    if (i < NOUT * NHID) {
        int n = i / NHID, k = i % NHID;
        d_p2wh[i] = __float2half_rn(p2w[(size_t)k * NOUT + n]);
    }
}

// all-layer gaussian weights (half) in one launch
__global__ void k_ewall(const float* __restrict__ ea,
                        const float* __restrict__ mu,
                        const float* __restrict__ sg) {
    int e = blockIdx.x * blockDim.x + threadIdx.x;
    if (e >= NE) return;
    float a0 = ea[e * 2 + 0], a1 = ea[e * 2 + 1];
#pragma unroll
    for (int l = 0; l < LL; l++) {
        const float* mul = mu + l * KG * 2;
        const float* sgl = sg + l * KG * 2;
#pragma unroll
        for (int k = 0; k < KG; k++) {
            float dx = a0 - mul[k * 2 + 0];
            float dy = a1 - mul[k * 2 + 1];
            float s0 = sgl[k * 2 + 0], s1 = sgl[k * 2 + 1];
            float w = expf(-0.5f * (dx * dx / (1e-15f + s0 * s0) +
                                    dy * dy / (1e-15f + s1 * s1)));
            d_ewh[l][(size_t)e * KG + k] = __float2half_rn(w);
        }
    }
}

// S accumulation (warp per node), gathers from HALF h rows (256B/edge)
__global__ void k_sacc(const __half* __restrict__ hinh, int layer) {
    int n = (blockIdx.x * blockDim.x + threadIdx.x) >> 5;
    int l = threadIdx.x & 31;
    if (n >= NN) return;
    const __half* ewl = d_ewh[layer];
    const __half2* h2b = (const __half2*)hinh;
    int beg = d_rowptr[n], end = d_rowptr[n + 1];
    float acc[KG][4];
#pragma unroll
    for (int k = 0; k < KG; k++)
#pragma unroll
        for (int q = 0; q < 4; q++) acc[k][q] = 0.f;

    for (int p = beg; p < end; p++) {
        int e = d_eid[p], s = d_esrc[p];
        float wv = (l < KG) ? __half2float(ewl[(size_t)e * KG + l]) : 0.f;
        const __half2* hr2 = h2b + (size_t)s * 64;
        float2 f0 = __half22float2(hr2[l]);        // channels 2l, 2l+1
        float2 f1 = __half22float2(hr2[l + 32]);   // channels 64+2l, 64+2l+1
#pragma unroll
        for (int k = 0; k < KG; k++) {
            float wk = __shfl_sync(0xffffffffu, wv, k);
            acc[k][0] = fmaf(wk, f0.x, acc[k][0]);
            acc[k][1] = fmaf(wk, f0.y, acc[k][1]);
            acc[k][2] = fmaf(wk, f1.x, acc[k][2]);
            acc[k][3] = fmaf(wk, f1.y, acc[k][3]);
        }
    }
    float inv = 1.f / fmaxf((float)(end - beg), 1.f);
    __half2* Sp2 = (__half2*)&d_Sh[(size_t)n * (KG * C)];
#pragma unroll
    for (int k = 0; k < KG; k++) {
        Sp2[k * 64 + l]      = __floats2half2_rn(acc[k][0] * inv, acc[k][1] * inv);
        Sp2[k * 64 + 32 + l] = __floats2half2_rn(acc[k][2] * inv, acc[k][3] * inv);
    }
}

__global__ void k_bnred() {  // <<<512,128>>>
    int c = threadIdx.x;
    float s = 0.f, q = 0.f;
    for (int r = blockIdx.x; r < NN; r += gridDim.x) {
        float v = d_h[(size_t)r * C + c];
        s += v; q += v * v;
    }
    atomicAdd(&d_bns[c], s);
    atomicAdd(&d_bnq[c], q);
}

__global__ void k_bnapp(const float* __restrict__ gamma,
                        const float* __restrict__ beta,
                        float* __restrict__ out_hl,
                        __half* __restrict__ out_hlt, int relu) {
    int i = blockIdx.x * blockDim.x + threadIdx.x;
    if (i >= NN * C) return;
    int c = i % C;
    float mean = d_bns[c] / (float)NN;
    float var  = d_bnq[c] / (float)NN - mean * mean;
    float v = (d_h[i] - mean) * rsqrtf(var + 1e-5f) * gamma[c] + beta[c];
    if (relu) v = fmaxf(v, 0.f);
    d_h[i] = v;
    out_hl[i]  = v;
    out_hlt[i] = __float2half_rn(v);
}

// fused: attention softmax + weighted node rep + graph-pool atomicAdd
__global__ void k_nreppool(const float* __restrict__ x,
                           const int* __restrict__ batch) {
    int n = blockIdx.x;
    int c = threadIdx.x;
    __shared__ float p[5];
    __shared__ int gidx;
    if (c == 0) {
        float a[5], m = -1e30f;
#pragma unroll
        for (int t = 0; t < 5; t++) {
            a[t] = d_af[t * NN + n] + d_ab[t * NN + n];
            m = fmaxf(m, a[t]);
        }
        float s = 0.f;
#pragma unroll
        for (int t = 0; t < 5; t++) { a[t] = expf(a[t] - m); s += a[t]; }
#pragma unroll
        for (int t = 0; t < 5; t++) p[t] = a[t] / s;
        gidx = batch[n];
    }
    __syncthreads();
    float r = p[0] * x[(size_t)n * C + c];
#pragma unroll
    for (int t = 1; t < 5; t++) r = fmaf(p[t], d_hl[t - 1][(size_t)n * C + c], r);
    atomicAdd(&d_hg[(size_t)gidx * C + c], r);
}

__global__ void k_cnt(const int* __restrict__ batch) {
    int n = blockIdx.x * blockDim.x + threadIdx.x;
    if (n < NN) atomicAdd(&d_cnt[batch[n]], 1.f);
}

__global__ void k_pdiv() {
    int i = blockIdx.x * blockDim.x + threadIdx.x;
    if (i >= NB * C) return;
    float v = d_hg[i] / fmaxf(d_cnt[i / C], 1.f);
    d_hg[i]  = v;
    d_hgh[i] = __float2half_rn(v);
}

__global__ void k_ln(const float* __restrict__ g, const float* __restrict__ b,
                     float* __restrict__ out) {
    int row = blockIdx.x, t = threadIdx.x;
    __shared__ float sm[NOUT];
    float v = d_z2[(size_t)row * NOUT + t];
    sm[t] = v;
    __syncthreads();
    for (int o = NOUT / 2; o > 0; o >>= 1) {
        if (t < o) sm[t] += sm[t + o];
        __syncthreads();
    }
    float mean = sm[0] / (float)NOUT;
    __syncthreads();
    float dv = v - mean;
    sm[t] = dv * dv;
    __syncthreads();
    for (int o = NOUT / 2; o > 0; o >>= 1) {
        if (t < o) sm[t] += sm[t + o];
        __syncthreads();
    }
    float var = sm[0] / (float)NOUT;
    out[(size_t)row * NOUT + t] = dv * rsqrtf(var + 1e-5f) * g[t] + b[t];
}

// ---------------- host ----------------
static float* symf(const void* s) {
    void* p = nullptr;
    cudaGetSymbolAddress(&p, s);
    return (float*)p;
}
static __half* symh(const void* s) {
    void* p = nullptr;
    cudaGetSymbolAddress(&p, s);
    return (__half*)p;
}
static int* symi(const void* s) {
    void* p = nullptr;
    cudaGetSymbolAddress(&p, s);
    return (int*)p;
}

extern "C" void kernel_launch(void* const* d_in, const int* in_sizes, int n_in,
                              void* d_out, int out_size) {
    const float* x     = (const float*)d_in[0];
    const int*   ei    = (const int*)d_in[1];
    const int*   src   = ei;
    const int*   dst   = ei + NE;
    const float* ea    = (const float*)d_in[2];
    const int*   batch = (const int*)d_in[3];
    const float* g     = (const float*)d_in[4];
    const float* root  = (const float*)d_in[5];
    const float* bias  = (const float*)d_in[6];
    const float* mu    = (const float*)d_in[7];
    const float* sigma = (const float*)d_in[8];
    const float* bng   = (const float*)d_in[9];
    const float* bnb   = (const float*)d_in[10];
    const float* wih   = (const float*)d_in[11];
    const float* whh   = (const float*)d_in[12];
    const float* bih   = (const float*)d_in[13];
    const float* bhh   = (const float*)d_in[14];
    const float* attw  = (const float*)d_in[15];
    const float* p1w   = (const float*)d_in[17];
    const float* p1b   = (const float*)d_in[18];
    const float* p2w   = (const float*)d_in[19];
    const float* p2b   = (const float*)d_in[20];
    const float* lng   = (const float*)d_in[21];
    const float* lnb   = (const float*)d_in[22];
    float* out = (float*)d_out;

    float*  h     = symf(d_h);
    float*  hl    = symf(d_hl);
    __half* hlth  = symh(d_hlth);
    __half* Sh    = symh(d_Sh);
    __half* gth   = symh(d_gth);
    __half* rooth = symh(d_rooth);
    float*  af    = symf(d_af);
    float*  ab    = symf(d_ab);
    float*  cnt   = symf(d_cnt);
    float*  hg    = symf(d_hg);
    __half* hgh   = symh(d_hgh);
    __half* z1h   = symh(d_z1h);
    float*  z2    = symf(d_z2);
    __half* p1wh  = symh(d_p1wh);
    __half* p2wh  = symh(d_p2wh);
    int* indeg    = symi(d_indeg);

    const int TPB = 256;
    const dim3 blk(TPB);
    const int gridNC = (NN * C + TPB - 1) / TPB;
    const int rowsN  = (NN + 127) / 128;
    const int TLSTM_SMEM = 40960;

    static int smem_set = 0;
    if (!smem_set) {
        cudaFuncSetAttribute(tlstm, cudaFuncAttributeMaxDynamicSharedMemorySize,
                             TLSTM_SMEM);
        smem_set = 1;
    }

    // -------- CSR build + weight prep --------
    k_zeroi<<<(NN + TPB - 1) / TPB, blk>>>(indeg, NN);
    k_degi<<<(NE + TPB - 1) / TPB, blk>>>(dst);
    k_scan<<<1, 1024>>>();
    k_place<<<(NE + TPB - 1) / TPB, blk>>>(src, dst);
    k_gt_h<<<(LL * C * KG * C + TPB - 1) / TPB, blk>>>(g, root);
    k_prep<<<(NN * C + TPB - 1) / TPB, blk>>>(wih, whh, bih, bhh, x, p1w, p2w);
    k_ewall<<<(NE + TPB - 1) / TPB, blk>>>(ea, mu, sigma);

    // -------- GMMConv layers --------
    for (int i = 0; i < LL; i++) {
        k_sacc<<<(NN * 32 + TPB - 1) / TPB, blk>>>(hlth + (size_t)i * NN * C, i);
        GH gl = {Sh, gth + (size_t)i * C * KG * C,
                 hlth + (size_t)i * NN * C, rooth + (size_t)i * C * C,
                 h, bias + i * C, KG * C, C};
        tgemm_h<false, false><<<dim3(1, rowsN), blk>>>(gl, NN, C);
        k_zero2<<<1, C>>>();
        k_bnred<<<512, 128>>>();
        k_bnapp<<<gridNC, blk>>>(bng + i * C, bnb + i * C,
                                 hl + (size_t)i * NN * C,
                                 hlth + (size_t)(i + 1) * NN * C,
                                 (i < LL - 1) ? 1 : 0);
    }

    // -------- bidirectional LSTM JumpingKnowledge (fused fp16 GEMM+cell) --
    k_zero<<<(5 * NN + TPB - 1) / TPB, blk>>>(af, 5 * NN);
    k_zero<<<(5 * NN + TPB - 1) / TPB, blk>>>(ab, 5 * NN);
    for (int s = 0; s < 5; s++) {
        int tf = s, tb = 4 - s;
        const __half* xf = hlth + (size_t)tf * NN * C;
        const __half* xb = hlth + (size_t)tb * NN * C;
        tlstm<<<dim3(H / 32, rowsN, 2), blk, TLSTM_SMEM>>>(xf, xb, attw,
                                                           (s > 0) ? H : 0, s);
    }

    // global mean pool (fused attention mix + scatter)
    k_zero<<<(NB + TPB - 1) / TPB, blk>>>(cnt, NB);
    k_zero<<<(NB * C + TPB - 1) / TPB, blk>>>(hg, NB * C);
    k_cnt<<<(NN + TPB - 1) / TPB, blk>>>(batch);
    k_nreppool<<<NN, C>>>(x, batch);
    k_pdiv<<<(NB * C + TPB - 1) / TPB, blk>>>();

    // MLP + LayerNorm (fp16 GEMMs)
    GH gp1 = {hgh, p1wh, nullptr, nullptr, z1h, p1b, C, 0};
    tgemm_h<true, true><<<dim3(NHID / 128, NB / 128), blk>>>(gp1, NB, NHID);
    GH gp2 = {z1h, p2wh, nullptr, nullptr, z2, p2b, NHID, 0};
    tgemm_h<false, false><<<dim3(NOUT / 128, NB / 128), blk>>>(gp2, NB, NOUT);
    k_ln<<<NB, NOUT>>>(lng, lnb, out);
}

// round 11
// speedup vs baseline: 1.6959x; 1.0595x over previous
#include <cuda_runtime.h>
#include <cuda_fp16.h>
#include <math.h>
#include <stdint.h>

// ---------------- problem constants ----------------
namespace {
constexpr int NN   = 30000;   // nodes
constexpr int NE   = 480000;  // edges
constexpr int C    = 128;     // channels (= F)
constexpr int KG   = 8;       // gaussians
constexpr int LL   = 4;       // layers
constexpr int H    = 256;     // LSTM hidden
constexpr int H4   = 1024;    // 4*H
constexpr int NHID = 512;
constexpr int NOUT = 256;
constexpr int NB   = 1024;    // graphs
}

// ---------------- scratch (device globals; no allocations allowed) -------
__device__ __align__(256) float  d_h[NN * C];
__device__ __align__(256) float  d_hl[LL][NN * C];
__device__ __align__(256) __half d_hlth[5][NN * C];      // half x,h1..h4
__device__ __align__(256) __half d_Sh[NN * KG * C];
__device__ __align__(256) __half d_gth[LL * C * KG * C]; // [l][c][k*128+f]
__device__ __align__(256) __half d_rooth[LL * C * C];    // [l][c][f]
__device__ __align__(256) __half d_ewh[LL][NE * KG];
__device__ __align__(256) float  d_bns[C];
__device__ __align__(256) float  d_bnq[C];
__device__ __align__(256) __half d_lhh[2][2][NN * H];    // [pingpong][dir]
__device__ __align__(256) float  d_lc[2][NN * H];
__device__ __align__(256) float  d_af[5 * NN];
__device__ __align__(256) float  d_ab[5 * NN];
__device__ __align__(256) float  d_cnt[NB];
__device__ __align__(256) float  d_hg[NB * C];
__device__ __align__(256) __half d_hgh[NB * C];
__device__ __align__(256) __half d_z1h[NB * NHID];
__device__ __align__(256) float  d_z2[NB * NOUT];
// half LSTM weights ([n][k] layout) + fused biases, half MLP weights
__device__ __align__(256) __half d_wihh[2 * H4 * C];
__device__ __align__(256) __half d_whhh[2 * H4 * H];
__device__ __align__(256) float  d_bsum[2 * H4];
__device__ __align__(256) __half d_p1wh[NHID * C];       // [n][k]
__device__ __align__(256) __half d_p2wh[NOUT * NHID];    // [n][k]
// CSR scratch
__device__ __align__(256) int d_indeg[NN];
__device__ __align__(256) int d_rowptr[NN + 1];
__device__ __align__(256) int d_curp[NN];
__device__ __align__(256) int d_eid[NE];
__device__ __align__(256) int d_esrc[NE];

// ---------------- helpers ----------------
__device__ __forceinline__ void mma16h(float* c, const uint32_t* a, const uint32_t* b) {
    asm volatile(
        "mma.sync.aligned.m16n8k16.row.col.f32.f16.f16.f32 "
        "{%0,%1,%2,%3}, {%4,%5,%6,%7}, {%8,%9}, {%0,%1,%2,%3};"
        : "+f"(c[0]), "+f"(c[1]), "+f"(c[2]), "+f"(c[3])
        : "r"(a[0]), "r"(a[1]), "r"(a[2]), "r"(a[3]), "r"(b[0]), "r"(b[1]));
}
__device__ __forceinline__ void cpa16(uint32_t sdst, const void* gsrc, int srcsz) {
    asm volatile("cp.async.ca.shared.global [%0], [%1], 16, %2;\n"
                 :: "r"(sdst), "l"(gsrc), "r"(srcsz));
}
__device__ __forceinline__ void cpa_commit() { asm volatile("cp.async.commit_group;\n"); }
__device__ __forceinline__ void cpa_wait1()  { asm volatile("cp.async.wait_group 1;\n"); }
// fast sigmoid/tanh: 1 MUFU exp each, ~2ulp — noise far below current 4.3e-4
__device__ __forceinline__ float sigf(float x) {
    return __fdividef(1.f, 1.f + __expf(-x));
}
__device__ __forceinline__ float tanhfast(float x) {
    float t = __expf(-2.f * fabsf(x));
    float r = __fdividef(1.f - t, 1.f + t);
    return copysignf(r, x);
}

// ---------------- FP16 tensor GEMM (cp.async 2-stage, dual-K, TB form) ----
struct GH {
    const __half* A;
    const __half* B;
    const __half* A2;
    const __half* B2;
    void* Cm;            // float* or __half* (OUTH)
    const float* bias;   // nullptr -> none
    int Kd;
    int Kd2;
};

template <bool RELU_, bool OUTH>
__global__ __launch_bounds__(256) void tgemm_h(GH ga, int M, int Nm)
{
    __shared__ uint32_t As[2][2560];   // [row][20]
    __shared__ uint32_t Bs[2][2560];

    const __half* __restrict__ A  = ga.A;
    const __half* __restrict__ B  = ga.B;
    const __half* __restrict__ A2 = ga.A2;
    const __half* __restrict__ B2 = ga.B2;
    const float* __restrict__ bias = ga.bias;
    const int Kd = ga.Kd, Kd2 = ga.Kd2;

    const int tid  = threadIdx.x;
    const int lane = tid & 31;
    const int wid  = tid >> 5;
    const int wm   = wid & 3;
    const int wn   = wid >> 2;
    const int gid  = lane >> 2;
    const int tig  = lane & 3;
    const int row0 = blockIdx.y * 128, col0 = blockIdx.x * 128;

    const int nt1 = Kd >> 5;
    const int nt  = nt1 + (Kd2 >> 5);

    float acc[2][8][4];
#pragma unroll
    for (int mi = 0; mi < 2; mi++)
#pragma unroll
        for (int ni = 0; ni < 8; ni++)
#pragma unroll
            for (int r = 0; r < 4; r++) acc[mi][ni][r] = 0.f;

    auto loadTile = [&](int t, int st) {
        const __half* Ap; const __half* Bp; int Kc, k0;
        if (t < nt1) { Ap = A;  Bp = B;  Kc = Kd;  k0 = t << 5; }
        else         { Ap = A2; Bp = B2; Kc = Kd2; k0 = (t - nt1) << 5; }
#pragma unroll
        for (int it = 0; it < 2; it++) {
            int idx = tid + it * 256;
            int rr = idx >> 2, part = idx & 3;
            int gr = row0 + rr;
            uint32_t dst = (uint32_t)__cvta_generic_to_shared(&As[st][rr * 20 + part * 4]);
            cpa16(dst, Ap + (size_t)gr * Kc + k0 + part * 8, gr < M ? 16 : 0);
        }
#pragma unroll
        for (int it = 0; it < 2; it++) {
            int idx = tid + it * 256;
            int rr = idx >> 2, part = idx & 3;
            uint32_t dst = (uint32_t)__cvta_generic_to_shared(&Bs[st][rr * 20 + part * 4]);
            cpa16(dst, Bp + (size_t)(col0 + rr) * Kc + k0 + part * 8, 16);
        }
    };

    loadTile(0, 0);
    cpa_commit();

    for (int t = 0; t < nt; t++) {
        if (t + 1 < nt) loadTile(t + 1, (t + 1) & 1);
        cpa_commit();
        cpa_wait1();
        __syncthreads();

        const int st = t & 1;
#pragma unroll
        for (int kk = 0; kk < 2; kk++) {
            uint32_t a[2][4], b[8][2];
#pragma unroll
            for (int mi = 0; mi < 2; mi++) {
                int mr = wm * 32 + mi * 16;
                a[mi][0] = As[st][(mr + gid)     * 20 + kk * 8 + tig];
                a[mi][1] = As[st][(mr + gid + 8) * 20 + kk * 8 + tig];
                a[mi][2] = As[st][(mr + gid)     * 20 + kk * 8 + 4 + tig];
                a[mi][3] = As[st][(mr + gid + 8) * 20 + kk * 8 + 4 + tig];
            }
#pragma unroll
            for (int ni = 0; ni < 8; ni++) {
                int nr = wn * 64 + ni * 8;
                b[ni][0] = Bs[st][(nr + gid) * 20 + kk * 8 + tig];
                b[ni][1] = Bs[st][(nr + gid) * 20 + kk * 8 + 4 + tig];
            }
#pragma unroll
            for (int mi = 0; mi < 2; mi++)
#pragma unroll
                for (int ni = 0; ni < 8; ni++)
                    mma16h(acc[mi][ni], a[mi], b[ni]);
        }
        __syncthreads();
    }

#pragma unroll
    for (int mi = 0; mi < 2; mi++) {
#pragma unroll
        for (int half_ = 0; half_ < 2; half_++) {
            int r = row0 + wm * 32 + mi * 16 + gid + half_ * 8;
            if (r >= M) continue;
#pragma unroll
            for (int ni = 0; ni < 8; ni++) {
                int cI = col0 + wn * 64 + ni * 8 + tig * 2;
                float v0 = acc[mi][ni][half_ * 2 + 0];
                float v1 = acc[mi][ni][half_ * 2 + 1];
                if (bias) { v0 += bias[cI]; v1 += bias[cI + 1]; }
                if (RELU_) { v0 = fmaxf(v0, 0.f); v1 = fmaxf(v1, 0.f); }
                if (OUTH) {
                    __half2* cp = (__half2*)((__half*)ga.Cm + (size_t)r * Nm + cI);
                    *cp = __floats2half2_rn(v0, v1);
                } else {
                    float* cp = (float*)ga.Cm + (size_t)r * Nm + cI;
                    cp[0] = v0; cp[1] = v1;
                }
            }
        }
    }
}

// ---------------- fused LSTM step (FP16): GEMM + cell + attention dot ----
__global__ __launch_bounds__(256) void tlstm(
    const __half* __restrict__ xf, const __half* __restrict__ xb,
    const float* __restrict__ attw, int K2, int s)
{
    extern __shared__ uint32_t sraw[];   // 10240 words = 40960 B
    float* gbuf = (float*)sraw;          // epilogue: [64][133]

    const int dir  = blockIdx.z;
    const int c0   = blockIdx.x * 32;
    const int row0 = blockIdx.y * 128;
    const int pb   = s & 1;

    const __half* A  = dir ? xb : xf;
    const __half* B  = d_wihh + (size_t)dir * H4 * C;
    const __half* A2 = d_lhh[pb][dir];
    const __half* B2 = d_whhh + (size_t)dir * H4 * H;

    const int tid  = threadIdx.x;
    const int lane = tid & 31;
    const int wid  = tid >> 5;
    const int wm   = wid & 3;
    const int wn   = wid >> 2;
    const int gid  = lane >> 2;
    const int tig  = lane & 3;

    const int nt1 = C >> 5;              // 4
    const int nt  = nt1 + (K2 >> 5);     // 4 or 12

    float acc[2][8][4];
#pragma unroll
    for (int mi = 0; mi < 2; mi++)
#pragma unroll
        for (int ni = 0; ni < 8; ni++)
#pragma unroll
            for (int r = 0; r < 4; r++) acc[mi][ni][r] = 0.f;

    auto loadTile = [&](int t, int st) {
        const __half* Ap; const __half* Bp; int Kc, k0;
        if (t < nt1) { Ap = A;  Bp = B;  Kc = C; k0 = t << 5; }
        else         { Ap = A2; Bp = B2; Kc = H; k0 = (t - nt1) << 5; }
        uint32_t* Asb = sraw + st * 2560;
        uint32_t* Bsb = sraw + 5120 + st * 2560;
#pragma unroll
        for (int it = 0; it < 2; it++) {
            int idx = tid + it * 256;
            int rr = idx >> 2, part = idx & 3;
            int gr = row0 + rr;
            uint32_t dst = (uint32_t)__cvta_generic_to_shared(&Asb[rr * 20 + part * 4]);
            cpa16(dst, Ap + (size_t)gr * Kc + k0 + part * 8, gr < NN ? 16 : 0);
        }
#pragma unroll
        for (int it = 0; it < 2; it++) {
            int idx = tid + it * 256;
            int rr = idx >> 2, part = idx & 3;
            int brow = ((rr >> 5) << 8) + c0 + (rr & 31);   // gate*256 + c0 + j'
            uint32_t dst = (uint32_t)__cvta_generic_to_shared(&Bsb[rr * 20 + part * 4]);
            cpa16(dst, Bp + (size_t)brow * Kc + k0 + part * 8, 16);
        }
    };

    loadTile(0, 0);
    cpa_commit();

    for (int t = 0; t < nt; t++) {
        if (t + 1 < nt) loadTile(t + 1, (t + 1) & 1);
        cpa_commit();
        cpa_wait1();
        __syncthreads();

        const int st = t & 1;
        const uint32_t* Asb = sraw + st * 2560;
        const uint32_t* Bsb = sraw + 5120 + st * 2560;
#pragma unroll
        for (int kk = 0; kk < 2; kk++) {
            uint32_t a[2][4], b[8][2];
#pragma unroll
            for (int mi = 0; mi < 2; mi++) {
                int mr = wm * 32 + mi * 16;
                a[mi][0] = Asb[(mr + gid)     * 20 + kk * 8 + tig];
                a[mi][1] = Asb[(mr + gid + 8) * 20 + kk * 8 + tig];
                a[mi][2] = Asb[(mr + gid)     * 20 + kk * 8 + 4 + tig];
                a[mi][3] = Asb[(mr + gid + 8) * 20 + kk * 8 + 4 + tig];
            }
#pragma unroll
            for (int ni = 0; ni < 8; ni++) {
                int nr = wn * 64 + ni * 8;
                b[ni][0] = Bsb[(nr + gid) * 20 + kk * 8 + tig];
                b[ni][1] = Bsb[(nr + gid) * 20 + kk * 8 + 4 + tig];
            }
#pragma unroll
            for (int mi = 0; mi < 2; mi++)
#pragma unroll
                for (int ni = 0; ni < 8; ni++)
                    mma16h(acc[mi][ni], a[mi], b[ni]);
        }
        __syncthreads();
    }

    // ---- fused epilogue: two 64-row passes through smem ----
    const float* bs = d_bsum + (size_t)dir * H4;
    float* lc   = d_lc[dir];
    __half* lhw = d_lhh[1 - pb][dir];
    const int t_idx = dir ? (4 - s) : s;
    float* aout = (dir ? d_ab : d_af) + t_idx * NN;

#pragma unroll
    for (int p = 0; p < 2; p++) {
        __syncthreads();
        if ((wm >> 1) == p) {
#pragma unroll
            for (int mi = 0; mi < 2; mi++)
#pragma unroll
                for (int half_ = 0; half_ < 2; half_++) {
                    int rloc = (wm & 1) * 32 + mi * 16 + gid + half_ * 8;
#pragma unroll
                    for (int ni = 0; ni < 8; ni++) {
                        int col = wn * 64 + ni * 8 + tig * 2;
                        gbuf[rloc * 133 + col]     = acc[mi][ni][half_ * 2 + 0];
                        gbuf[rloc * 133 + col + 1] = acc[mi][ni][half_ * 2 + 1];
                    }
                }
        }
        __syncthreads();

        int rr = tid >> 2;                 // 0..63
        int n  = row0 + p * 64 + rr;
        bool valid = n < NN;
        float part = 0.f;
        if (valid) {
            int jb = (tid & 3) * 8;
#pragma unroll
            for (int q = 0; q < 8; q++) {
                int jl = jb + q;           // 0..31
                int j  = c0 + jl;          // 0..255
                float gi = gbuf[rr * 133 +  0 + jl] + bs[0 * H + j];
                float gf = gbuf[rr * 133 + 32 + jl] + bs[1 * H + j];
                float gg = gbuf[rr * 133 + 64 + jl] + bs[2 * H + j];
                float go = gbuf[rr * 133 + 96 + jl] + bs[3 * H + j];
                size_t ix = (size_t)n * H + j;
                float cprev = (K2 > 0) ? lc[ix] : 0.f;
                float cc = sigf(gf) * cprev + sigf(gi) * tanhfast(gg);
                lc[ix] = cc;
                float hh = sigf(go) * tanhfast(cc);
                lhw[ix] = __float2half_rn(hh);
                part = fmaf(hh, attw[dir * H + j], part);
            }
        }
        part += __shfl_down_sync(0xffffffffu, part, 2);
        part += __shfl_down_sync(0xffffffffu, part, 1);
        if (valid && (tid & 3) == 0) atomicAdd(&aout[n], part);
    }
}

// ---------------- small kernels ----------------
__global__ void k_zero(float* p, int n) {
    int i = blockIdx.x * blockDim.x + threadIdx.x;
    if (i < n) p[i] = 0.f;
}
__global__ void k_zeroi(int* p, int n) {
    int i = blockIdx.x * blockDim.x + threadIdx.x;
    if (i < n) p[i] = 0;
}
__global__ void k_zero2() {   // zero bns+bnq in one tiny launch
    int i = threadIdx.x;
    d_bns[i] = 0.f;
    d_bnq[i] = 0.f;
}

__global__ void k_degi(const int* __restrict__ dst) {
    int e = blockIdx.x * blockDim.x + threadIdx.x;
    if (e < NE) atomicAdd(&d_indeg[dst[e]], 1);
}

__global__ void k_scan() {
    const int T = 1024;
    __shared__ int buf[T];
    __shared__ int carry_s;
    int t = threadIdx.x;
    if (t == 0) carry_s = 0;
    __syncthreads();
    for (int base = 0; base < NN; base += T) {
        int v = (base + t < NN) ? d_indeg[base + t] : 0;
        buf[t] = v;
        __syncthreads();
        for (int off = 1; off < T; off <<= 1) {
            int add = (t >= off) ? buf[t - off] : 0;
            __syncthreads();
            buf[t] += add;
            __syncthreads();
        }
        int carry = carry_s;
        __syncthreads();
        if (base + t < NN) {
            d_rowptr[base + t] = carry + buf[t] - v;
            d_curp[base + t]   = carry + buf[t] - v;
        }
        if (t == T - 1) carry_s = carry + buf[t];
        __syncthreads();
    }
    if (t == 0) d_rowptr[NN] = carry_s;
}

__global__ void k_place(const int* __restrict__ src, const int* __restrict__ dst) {
    int e = blockIdx.x * blockDim.x + threadIdx.x;
    if (e >= NE) return;
    int slot = atomicAdd(&d_curp[dst[e]], 1);
    d_eid[slot]  = e;
    d_esrc[slot] = src[e];
}

// gT(half): [l][c][k*128+f] from g; rootT(half): [l][c][f]
__global__ void k_gt_h(const float* __restrict__ g, const float* __restrict__ root) {
    int i = blockIdx.x * blockDim.x + threadIdx.x;
    if (i < LL * C * KG * C) {
        int l   = i >> 17;
        int rem = i & 131071;
        int cR  = rem >> 10;
        int kf  = rem & 1023;
        int k = kf >> 7, f = kf & 127;
        d_gth[i] = __float2half_rn(g[((size_t)(l * 128 + f)) * 1024 + k * 128 + cR]);
    }
    if (i < LL * C * C) {
        int l = i >> 14;
        int c = (i >> 7) & 127;
        int f = i & 127;
        d_rooth[i] = __float2half_rn(root[((size_t)(l * 128 + f)) * 128 + c]);
    }
}

// half LSTM/MLP weights, fused biases, x->half
__global__ void k_prep(const float* __restrict__ wih, const float* __restrict__ whh,
                       const float* __restrict__ bih, const float* __restrict__ bhh,
                       const float* __restrict__ x,
                       const float* __restrict__ p1w, const float* __restrict__ p2w) {
    int i = blockIdx.x * blockDim.x + threadIdx.x;
    if (i < NN * C)       d_hlth[0][i] = __float2half_rn(x[i]);
    if (i < 2 * H4 * C)   d_wihh[i] = __float2half_rn(wih[i]);
    if (i < 2 * H4 * H)   d_whhh[i] = __float2half_rn(whh[i]);
    if (i < 2 * H4)       d_bsum[i] = bih[i] + bhh[i];
    if (i < NHID * C)  {
        int n = i / C, c = i % C;
        d_p1wh[i] = __float2half_rn(p1w[(size_t)c * NHID + n]);
    }
    if (i < NOUT * NHID) {
        int n = i / NHID, k = i % NHID;
        d_p2wh[i] = __float2half_rn(p2w[(size_t)k * NOUT + n]);
    }
}

// all-layer gaussian weights (half) in one launch
__global__ void k_ewall(const float* __restrict__ ea,
                        const float* __restrict__ mu,
                        const float* __restrict__ sg) {
    int e = blockIdx.x * blockDim.x + threadIdx.x;
    if (e >= NE) return;
    float a0 = ea[e * 2 + 0], a1 = ea[e * 2 + 1];
#pragma unroll
    for (int l = 0; l < LL; l++) {
        const float* mul = mu + l * KG * 2;
        const float* sgl = sg + l * KG * 2;
#pragma unroll
        for (int k = 0; k < KG; k++) {
            float dx = a0 - mul[k * 2 + 0];
            float dy = a1 - mul[k * 2 + 1];
            float s0 = sgl[k * 2 + 0], s1 = sgl[k * 2 + 1];
            float w = __expf(-0.5f * (__fdividef(dx * dx, 1e-15f + s0 * s0) +
                                      __fdividef(dy * dy, 1e-15f + s1 * s1)));
            d_ewh[l][(size_t)e * KG + k] = __float2half_rn(w);
        }
    }
}

// S accumulation (warp per node), gathers from HALF h rows (256B/edge)
__global__ void k_sacc(const __half* __restrict__ hinh, int layer) {
    int n = (blockIdx.x * blockDim.x + threadIdx.x) >> 5;
    int l = threadIdx.x & 31;
    if (n >= NN) return;
    const __half* ewl = d_ewh[layer];
    const __half2* h2b = (const __half2*)hinh;
    int beg = d_rowptr[n], end = d_rowptr[n + 1];
    float acc[KG][4];
#pragma unroll
    for (int k = 0; k < KG; k++)
#pragma unroll
        for (int q = 0; q < 4; q++) acc[k][q] = 0.f;

    for (int p = beg; p < end; p++) {
        int e = d_eid[p], s = d_esrc[p];
        float wv = (l < KG) ? __half2float(ewl[(size_t)e * KG + l]) : 0.f;
        const __half2* hr2 = h2b + (size_t)s * 64;
        float2 f0 = __half22float2(hr2[l]);
        float2 f1 = __half22float2(hr2[l + 32]);
#pragma unroll
        for (int k = 0; k < KG; k++) {
            float wk = __shfl_sync(0xffffffffu, wv, k);
            acc[k][0] = fmaf(wk, f0.x, acc[k][0]);
            acc[k][1] = fmaf(wk, f0.y, acc[k][1]);
            acc[k][2] = fmaf(wk, f1.x, acc[k][2]);
            acc[k][3] = fmaf(wk, f1.y, acc[k][3]);
        }
    }
    float inv = __fdividef(1.f, fmaxf((float)(end - beg), 1.f));
    __half2* Sp2 = (__half2*)&d_Sh[(size_t)n * (KG * C)];
#pragma unroll
    for (int k = 0; k < KG; k++) {
        Sp2[k * 64 + l]      = __floats2half2_rn(acc[k][0] * inv, acc[k][1] * inv);
        Sp2[k * 64 + 32 + l] = __floats2half2_rn(acc[k][2] * inv, acc[k][3] * inv);
    }
}

__global__ void k_bnred() {  // <<<512,128>>>
    int c = threadIdx.x;
    float s = 0.f, q = 0.f;
    for (int r = blockIdx.x; r < NN; r += gridDim.x) {
        float v = d_h[(size_t)r * C + c];
        s += v; q += v * v;
    }
    atomicAdd(&d_bns[c], s);
    atomicAdd(&d_bnq[c], q);
}

__global__ void k_bnapp(const float* __restrict__ gamma,
                        const float* __restrict__ beta,
                        float* __restrict__ out_hl,
                        __half* __restrict__ out_hlt, int relu) {
    int i = blockIdx.x * blockDim.x + threadIdx.x;
    if (i >= NN * C) return;
    int c = i % C;
    float mean = d_bns[c] / (float)NN;
    float var  = d_bnq[c] / (float)NN - mean * mean;
    float v = (d_h[i] - mean) * rsqrtf(var + 1e-5f) * gamma[c] + beta[c];
    if (relu) v = fmaxf(v, 0.f);
    out_hl[i]  = v;                       // d_h store dropped (dead)
    out_hlt[i] = __float2half_rn(v);
}

// fused: attention softmax + weighted node rep + graph-pool atomicAdd
__global__ void k_nreppool(const float* __restrict__ x,
                           const int* __restrict__ batch) {
    int n = blockIdx.x;
    int c = threadIdx.x;
    __shared__ float p[5];
    __shared__ int gidx;
    if (c == 0) {
        float a[5], m = -1e30f;
#pragma unroll
        for (int t = 0; t < 5; t++) {
            a[t] = d_af[t * NN + n] + d_ab[t * NN + n];
            m = fmaxf(m, a[t]);
        }
        float s = 0.f;
#pragma unroll
        for (int t = 0; t < 5; t++) { a[t] = __expf(a[t] - m); s += a[t]; }
        float invs = __fdividef(1.f, s);
#pragma unroll
        for (int t = 0; t < 5; t++) p[t] = a[t] * invs;
        gidx = batch[n];
    }
    __syncthreads();
    float r = p[0] * x[(size_t)n * C + c];
#pragma unroll
    for (int t = 1; t < 5; t++) r = fmaf(p[t], d_hl[t - 1][(size_t)n * C + c], r);
    atomicAdd(&d_hg[(size_t)gidx * C + c], r);
}

__global__ void k_cnt(const int* __restrict__ batch) {
    int n = blockIdx.x * blockDim.x + threadIdx.x;
    if (n < NN) atomicAdd(&d_cnt[batch[n]], 1.f);
}

__global__ void k_pdiv() {
    int i = blockIdx.x * blockDim.x + threadIdx.x;
    if (i >= NB * C) return;
    float v = d_hg[i] / fmaxf(d_cnt[i / C], 1.f);
    d_hg[i]  = v;
    d_hgh[i] = __float2half_rn(v);
}

__global__ void k_ln(const float* __restrict__ g, const float* __restrict__ b,
                     float* __restrict__ out) {
    int row = blockIdx.x, t = threadIdx.x;
    __shared__ float sm[NOUT];
    float v = d_z2[(size_t)row * NOUT + t];
    sm[t] = v;
    __syncthreads();
    for (int o = NOUT / 2; o > 0; o >>= 1) {
        if (t < o) sm[t] += sm[t + o];
        __syncthreads();
    }
    float mean = sm[0] / (float)NOUT;
    __syncthreads();
    float dv = v - mean;
    sm[t] = dv * dv;
    __syncthreads();
    for (int o = NOUT / 2; o > 0; o >>= 1) {
        if (t < o) sm[t] += sm[t + o];
        __syncthreads();
    }
    float var = sm[0] / (float)NOUT;
    out[(size_t)row * NOUT + t] = dv * rsqrtf(var + 1e-5f) * g[t] + b[t];
}

// ---------------- host ----------------
static float* symf(const void* s) {
    void* p = nullptr;
    cudaGetSymbolAddress(&p, s);
    return (float*)p;
}
static __half* symh(const void* s) {
    void* p = nullptr;
    cudaGetSymbolAddress(&p, s);
    return (__half*)p;
}
static int* symi(const void* s) {
    void* p = nullptr;
    cudaGetSymbolAddress(&p, s);
    return (int*)p;
}

extern "C" void kernel_launch(void* const* d_in, const int* in_sizes, int n_in,
                              void* d_out, int out_size) {
    const float* x     = (const float*)d_in[0];
    const int*   ei    = (const int*)d_in[1];
    const int*   src   = ei;
    const int*   dst   = ei + NE;
    const float* ea    = (const float*)d_in[2];
    const int*   batch = (const int*)d_in[3];
    const float* g     = (const float*)d_in[4];
    const float* root  = (const float*)d_in[5];
    const float* bias  = (const float*)d_in[6];
    const float* mu    = (const float*)d_in[7];
    const float* sigma = (const float*)d_in[8];
    const float* bng   = (const float*)d_in[9];
    const float* bnb   = (const float*)d_in[10];
    const float* wih   = (const float*)d_in[11];
    const float* whh   = (const float*)d_in[12];
    const float* bih   = (const float*)d_in[13];
    const float* bhh   = (const float*)d_in[14];
    const float* attw  = (const float*)d_in[15];
    const float* p1w   = (const float*)d_in[17];
    const float* p1b   = (const float*)d_in[18];
    const float* p2w   = (const float*)d_in[19];
    const float* p2b   = (const float*)d_in[20];
    const float* lng   = (const float*)d_in[21];
    const float* lnb   = (const float*)d_in[22];
    float* out = (float*)d_out;

    float*  h     = symf(d_h);
    float*  hl    = symf(d_hl);
    __half* hlth  = symh(d_hlth);
    __half* Sh    = symh(d_Sh);
    __half* gth   = symh(d_gth);
    __half* rooth = symh(d_rooth);
    float*  af    = symf(d_af);
    float*  ab    = symf(d_ab);
    float*  cnt   = symf(d_cnt);
    float*  hg    = symf(d_hg);
    __half* hgh   = symh(d_hgh);
    __half* z1h   = symh(d_z1h);
    float*  z2    = symf(d_z2);
    __half* p1wh  = symh(d_p1wh);
    __half* p2wh  = symh(d_p2wh);
    int* indeg    = symi(d_indeg);

    const int TPB = 256;
    const dim3 blk(TPB);
    const int gridNC = (NN * C + TPB - 1) / TPB;
    const int rowsN  = (NN + 127) / 128;
    const int TLSTM_SMEM = 40960;

    static int smem_set = 0;
    if (!smem_set) {
        cudaFuncSetAttribute(tlstm, cudaFuncAttributeMaxDynamicSharedMemorySize,
                             TLSTM_SMEM);
        smem_set = 1;
    }

    // -------- CSR build + weight prep --------
    k_zeroi<<<(NN + TPB - 1) / TPB, blk>>>(indeg, NN);
    k_degi<<<(NE + TPB - 1) / TPB, blk>>>(dst);
    k_scan<<<1, 1024>>>();
    k_place<<<(NE + TPB - 1) / TPB, blk>>>(src, dst);
    k_gt_h<<<(LL * C * KG * C + TPB - 1) / TPB, blk>>>(g, root);
    k_prep<<<(NN * C + TPB - 1) / TPB, blk>>>(wih, whh, bih, bhh, x, p1w, p2w);
    k_ewall<<<(NE + TPB - 1) / TPB, blk>>>(ea, mu, sigma);

    // -------- GMMConv layers --------
    for (int i = 0; i < LL; i++) {
        k_sacc<<<(NN * 32 + TPB - 1) / TPB, blk>>>(hlth + (size_t)i * NN * C, i);
        GH gl = {Sh, gth + (size_t)i * C * KG * C,
                 hlth + (size_t)i * NN * C, rooth + (size_t)i * C * C,
                 h, bias + i * C, KG * C, C};
        tgemm_h<false, false><<<dim3(1, rowsN), blk>>>(gl, NN, C);
        k_zero2<<<1, C>>>();
        k_bnred<<<512, 128>>>();
        k_bnapp<<<gridNC, blk>>>(bng + i * C, bnb + i * C,
                                 hl + (size_t)i * NN * C,
                                 hlth + (size_t)(i + 1) * NN * C,
                                 (i < LL - 1) ? 1 : 0);
    }

    // -------- bidirectional LSTM JumpingKnowledge (fused fp16 GEMM+cell) --
    k_zero<<<(5 * NN + TPB - 1) / TPB, blk>>>(af, 5 * NN);
    k_zero<<<(5 * NN + TPB - 1) / TPB, blk>>>(ab, 5 * NN);
    for (int s = 0; s < 5; s++) {
        int tf = s, tb = 4 - s;
        const __half* xf = hlth + (size_t)tf * NN * C;
        const __half* xb = hlth + (size_t)tb * NN * C;
        tlstm<<<dim3(H / 32, rowsN, 2), blk, TLSTM_SMEM>>>(xf, xb, attw,
                                                           (s > 0) ? H : 0, s);
    }

    // global mean pool (fused attention mix + scatter)
    k_zero<<<(NB + TPB - 1) / TPB, blk>>>(cnt, NB);
    k_zero<<<(NB * C + TPB - 1) / TPB, blk>>>(hg, NB * C);
    k_cnt<<<(NN + TPB - 1) / TPB, blk>>>(batch);
    k_nreppool<<<NN, C>>>(x, batch);
    k_pdiv<<<(NB * C + TPB - 1) / TPB, blk>>>();

    // MLP + LayerNorm (fp16 GEMMs)
    GH gp1 = {hgh, p1wh, nullptr, nullptr, z1h, p1b, C, 0};
    tgemm_h<true, true><<<dim3(NHID / 128, NB / 128), blk>>>(gp1, NB, NHID);
    GH gp2 = {z1h, p2wh, nullptr, nullptr, z2, p2b, NHID, 0};
    tgemm_h<false, false><<<dim3(NOUT / 128, NB / 128), blk>>>(gp2, NB, NOUT);
    k_ln<<<NB, NOUT>>>(lng, lnb, out);
}

// round 12
// speedup vs baseline: 1.7460x; 1.0295x over previous
#include <cuda_runtime.h>
#include <cuda_fp16.h>
#include <math.h>
#include <stdint.h>

// ---------------- problem constants ----------------
namespace {
constexpr int NN   = 30000;   // nodes
constexpr int NE   = 480000;  // edges
constexpr int C    = 128;     // channels (= F)
constexpr int KG   = 8;       // gaussians
constexpr int LL   = 4;       // layers
constexpr int H    = 256;     // LSTM hidden
constexpr int H4   = 1024;    // 4*H
constexpr int NHID = 512;
constexpr int NOUT = 256;
constexpr int NB   = 1024;    // graphs
}

// ---------------- scratch (device globals; no allocations allowed) -------
__device__ __align__(256) float  d_h[NN * C];
__device__ __align__(256) __half d_hlth[5][NN * C];      // half x,h1..h4
__device__ __align__(256) __half d_Sh[NN * KG * C];
__device__ __align__(256) __half d_gth[LL * C * KG * C]; // [l][c][k*128+f]
__device__ __align__(256) __half d_rooth[LL * C * C];    // [l][c][f]
__device__ __align__(256) __half d_ewh[LL][NE * KG];
__device__ __align__(256) float  d_bns[C];
__device__ __align__(256) float  d_bnq[C];
__device__ __align__(256) __half d_lhh[2][2][NN * H];    // [pingpong][dir]
__device__ __align__(256) float  d_lc[2][NN * H];
__device__ __align__(256) float  d_af[5 * NN];
__device__ __align__(256) float  d_ab[5 * NN];
__device__ __align__(256) float  d_cnt[NB];
__device__ __align__(256) float  d_hg[NB * C];
__device__ __align__(256) __half d_hgh[NB * C];
__device__ __align__(256) __half d_z1h[NB * NHID];
__device__ __align__(256) float  d_z2[NB * NOUT];
// half LSTM weights ([n][k] layout) + fused biases, half MLP weights
__device__ __align__(256) __half d_wihh[2 * H4 * C];
__device__ __align__(256) __half d_whhh[2 * H4 * H];
__device__ __align__(256) float  d_bsum[2 * H4];
__device__ __align__(256) __half d_p1wh[NHID * C];       // [n][k]
__device__ __align__(256) __half d_p2wh[NOUT * NHID];    // [n][k]
// CSR scratch
__device__ __align__(256) int d_indeg[NN];
__device__ __align__(256) int d_rowptr[NN + 1];
__device__ __align__(256) int d_curp[NN];
__device__ __align__(256) int d_eid[NE];
__device__ __align__(256) int d_esrc[NE];

// ---------------- helpers ----------------
__device__ __forceinline__ void mma16h(float* c, const uint32_t* a, const uint32_t* b) {
    asm volatile(
        "mma.sync.aligned.m16n8k16.row.col.f32.f16.f16.f32 "
        "{%0,%1,%2,%3}, {%4,%5,%6,%7}, {%8,%9}, {%0,%1,%2,%3};"
        : "+f"(c[0]), "+f"(c[1]), "+f"(c[2]), "+f"(c[3])
        : "r"(a[0]), "r"(a[1]), "r"(a[2]), "r"(a[3]), "r"(b[0]), "r"(b[1]));
}
__device__ __forceinline__ void cpa16(uint32_t sdst, const void* gsrc, int srcsz) {
    asm volatile("cp.async.ca.shared.global [%0], [%1], 16, %2;\n"
                 :: "r"(sdst), "l"(gsrc), "r"(srcsz));
}
__device__ __forceinline__ void cpa_commit() { asm volatile("cp.async.commit_group;\n"); }
__device__ __forceinline__ void cpa_wait1()  { asm volatile("cp.async.wait_group 1;\n"); }
__device__ __forceinline__ float sigf(float x) {
    return __fdividef(1.f, 1.f + __expf(-x));
}
__device__ __forceinline__ float tanhfast(float x) {
    float t = __expf(-2.f * fabsf(x));
    float r = __fdividef(1.f - t, 1.f + t);
    return copysignf(r, x);
}

// ---------------- FP16 tensor GEMM (cp.async 2-stage, dual-K, TB form) ----
// If BN: also accumulates per-column sum/sumsq of outputs into d_bns/d_bnq
// (requires Nm == 128, col0 == 0 usage pattern of the GMM layer call).
struct GH {
    const __half* A;
    const __half* B;
    const __half* A2;
    const __half* B2;
    void* Cm;            // float* or __half* (OUTH)
    const float* bias;   // nullptr -> none
    int Kd;
    int Kd2;
};

template <bool RELU_, bool OUTH, bool BN>
__global__ __launch_bounds__(256) void tgemm_h(GH ga, int M, int Nm)
{
    __shared__ uint32_t As[2][2560];   // [row][20]
    __shared__ uint32_t Bs[2][2560];

    const __half* __restrict__ A  = ga.A;
    const __half* __restrict__ B  = ga.B;
    const __half* __restrict__ A2 = ga.A2;
    const __half* __restrict__ B2 = ga.B2;
    const float* __restrict__ bias = ga.bias;
    const int Kd = ga.Kd, Kd2 = ga.Kd2;

    const int tid  = threadIdx.x;
    const int lane = tid & 31;
    const int wid  = tid >> 5;
    const int wm   = wid & 3;
    const int wn   = wid >> 2;
    const int gid  = lane >> 2;
    const int tig  = lane & 3;
    const int row0 = blockIdx.y * 128, col0 = blockIdx.x * 128;

    const int nt1 = Kd >> 5;
    const int nt  = nt1 + (Kd2 >> 5);

    float acc[2][8][4];
#pragma unroll
    for (int mi = 0; mi < 2; mi++)
#pragma unroll
        for (int ni = 0; ni < 8; ni++)
#pragma unroll
            for (int r = 0; r < 4; r++) acc[mi][ni][r] = 0.f;

    auto loadTile = [&](int t, int st) {
        const __half* Ap; const __half* Bp; int Kc, k0;
        if (t < nt1) { Ap = A;  Bp = B;  Kc = Kd;  k0 = t << 5; }
        else         { Ap = A2; Bp = B2; Kc = Kd2; k0 = (t - nt1) << 5; }
#pragma unroll
        for (int it = 0; it < 2; it++) {
            int idx = tid + it * 256;
            int rr = idx >> 2, part = idx & 3;
            int gr = row0 + rr;
            uint32_t dst = (uint32_t)__cvta_generic_to_shared(&As[st][rr * 20 + part * 4]);
            cpa16(dst, Ap + (size_t)gr * Kc + k0 + part * 8, gr < M ? 16 : 0);
        }
#pragma unroll
        for (int it = 0; it < 2; it++) {
            int idx = tid + it * 256;
            int rr = idx >> 2, part = idx & 3;
            uint32_t dst = (uint32_t)__cvta_generic_to_shared(&Bs[st][rr * 20 + part * 4]);
            cpa16(dst, Bp + (size_t)(col0 + rr) * Kc + k0 + part * 8, 16);
        }
    };

    loadTile(0, 0);
    cpa_commit();

    for (int t = 0; t < nt; t++) {
        if (t + 1 < nt) loadTile(t + 1, (t + 1) & 1);
        cpa_commit();
        cpa_wait1();
        __syncthreads();

        const int st = t & 1;
#pragma unroll
        for (int kk = 0; kk < 2; kk++) {
            uint32_t a[2][4], b[8][2];
#pragma unroll
            for (int mi = 0; mi < 2; mi++) {
                int mr = wm * 32 + mi * 16;
                a[mi][0] = As[st][(mr + gid)     * 20 + kk * 8 + tig];
                a[mi][1] = As[st][(mr + gid + 8) * 20 + kk * 8 + tig];
                a[mi][2] = As[st][(mr + gid)     * 20 + kk * 8 + 4 + tig];
                a[mi][3] = As[st][(mr + gid + 8) * 20 + kk * 8 + 4 + tig];
            }
#pragma unroll
            for (int ni = 0; ni < 8; ni++) {
                int nr = wn * 64 + ni * 8;
                b[ni][0] = Bs[st][(nr + gid) * 20 + kk * 8 + tig];
                b[ni][1] = Bs[st][(nr + gid) * 20 + kk * 8 + 4 + tig];
            }
#pragma unroll
            for (int mi = 0; mi < 2; mi++)
#pragma unroll
                for (int ni = 0; ni < 8; ni++)
                    mma16h(acc[mi][ni], a[mi], b[ni]);
        }
        __syncthreads();
    }

    // per-thread BN partials: [ni][sub] sum and sumsq
    float cs[8][2], cq[8][2];
    if (BN) {
#pragma unroll
        for (int ni = 0; ni < 8; ni++) {
            cs[ni][0] = cs[ni][1] = 0.f;
            cq[ni][0] = cq[ni][1] = 0.f;
        }
    }

#pragma unroll
    for (int mi = 0; mi < 2; mi++) {
#pragma unroll
        for (int half_ = 0; half_ < 2; half_++) {
            int r = row0 + wm * 32 + mi * 16 + gid + half_ * 8;
            if (r >= M) continue;
#pragma unroll
            for (int ni = 0; ni < 8; ni++) {
                int cI = col0 + wn * 64 + ni * 8 + tig * 2;
                float v0 = acc[mi][ni][half_ * 2 + 0];
                float v1 = acc[mi][ni][half_ * 2 + 1];
                if (bias) { v0 += bias[cI]; v1 += bias[cI + 1]; }
                if (RELU_) { v0 = fmaxf(v0, 0.f); v1 = fmaxf(v1, 0.f); }
                if (OUTH) {
                    __half2* cp = (__half2*)((__half*)ga.Cm + (size_t)r * Nm + cI);
                    *cp = __floats2half2_rn(v0, v1);
                } else {
                    float* cp = (float*)ga.Cm + (size_t)r * Nm + cI;
                    cp[0] = v0; cp[1] = v1;
                }
                if (BN) {
                    cs[ni][0] += v0; cq[ni][0] += v0 * v0;
                    cs[ni][1] += v1; cq[ni][1] += v1 * v1;
                }
            }
        }
    }

    if (BN) {
        // reduce over gid (8 row-groups) within warp; lane = gid*4 + tig
#pragma unroll
        for (int off = 16; off >= 4; off >>= 1) {
#pragma unroll
            for (int ni = 0; ni < 8; ni++) {
#pragma unroll
                for (int sub = 0; sub < 2; sub++) {
                    cs[ni][sub] += __shfl_down_sync(0xffffffffu, cs[ni][sub], off);
                    cq[ni][sub] += __shfl_down_sync(0xffffffffu, cq[ni][sub], off);
                }
            }
        }
        // smem cross-warp combine (reuse As); 8 warps x 4 tig x 8 ni x 2 sub x 2 stat
        float* bnb = (float*)As;
        if (gid == 0) {
#pragma unroll
            for (int ni = 0; ni < 8; ni++)
#pragma unroll
                for (int sub = 0; sub < 2; sub++) {
                    int slot = (((wid << 2) | tig) * 8 + ni) * 4 + sub * 2;
                    bnb[slot]     = cs[ni][sub];
                    bnb[slot + 1] = cq[ni][sub];
                }
        }
        __syncthreads();
        // 256 threads: one (column, stat) each
        int colL = tid >> 1, stat = tid & 1;
        int wn_ = colL >> 6, r_ = colL & 63;
        int ni_ = r_ >> 3, q_ = r_ & 7, tig_ = q_ >> 1, sub_ = q_ & 1;
        float v = 0.f;
#pragma unroll
        for (int wm_ = 0; wm_ < 4; wm_++) {
            int wid_ = wn_ * 4 + wm_;
            v += bnb[(((wid_ << 2) | tig_) * 8 + ni_) * 4 + sub_ * 2 + stat];
        }
        atomicAdd(stat ? &d_bnq[col0 + colL] : &d_bns[col0 + colL], v);
    }
}

// ---------------- fused LSTM step (FP16): GEMM + cell + attention dot ----
__global__ __launch_bounds__(256) void tlstm(
    const __half* __restrict__ xf, const __half* __restrict__ xb,
    const float* __restrict__ attw, int K2, int s)
{
    extern __shared__ uint32_t sraw[];   // 10240 words = 40960 B
    float* gbuf = (float*)sraw;          // epilogue: [64][133]

    const int dir  = blockIdx.z;
    const int c0   = blockIdx.x * 32;
    const int row0 = blockIdx.y * 128;
    const int pb   = s & 1;

    const __half* A  = dir ? xb : xf;
    const __half* B  = d_wihh + (size_t)dir * H4 * C;
    const __half* A2 = d_lhh[pb][dir];
    const __half* B2 = d_whhh + (size_t)dir * H4 * H;

    const int tid  = threadIdx.x;
    const int lane = tid & 31;
    const int wid  = tid >> 5;
    const int wm   = wid & 3;
    const int wn   = wid >> 2;
    const int gid  = lane >> 2;
    const int tig  = lane & 3;

    const int nt1 = C >> 5;              // 4
    const int nt  = nt1 + (K2 >> 5);     // 4 or 12

    float acc[2][8][4];
#pragma unroll
    for (int mi = 0; mi < 2; mi++)
#pragma unroll
        for (int ni = 0; ni < 8; ni++)
#pragma unroll
            for (int r = 0; r < 4; r++) acc[mi][ni][r] = 0.f;

    auto loadTile = [&](int t, int st) {
        const __half* Ap; const __half* Bp; int Kc, k0;
        if (t < nt1) { Ap = A;  Bp = B;  Kc = C; k0 = t << 5; }
        else         { Ap = A2; Bp = B2; Kc = H; k0 = (t - nt1) << 5; }
        uint32_t* Asb = sraw + st * 2560;
        uint32_t* Bsb = sraw + 5120 + st * 2560;
#pragma unroll
        for (int it = 0; it < 2; it++) {
            int idx = tid + it * 256;
            int rr = idx >> 2, part = idx & 3;
            int gr = row0 + rr;
            uint32_t dst = (uint32_t)__cvta_generic_to_shared(&Asb[rr * 20 + part * 4]);
            cpa16(dst, Ap + (size_t)gr * Kc + k0 + part * 8, gr < NN ? 16 : 0);
        }
#pragma unroll
        for (int it = 0; it < 2; it++) {
            int idx = tid + it * 256;
            int rr = idx >> 2, part = idx & 3;
            int brow = ((rr >> 5) << 8) + c0 + (rr & 31);   // gate*256 + c0 + j'
            uint32_t dst = (uint32_t)__cvta_generic_to_shared(&Bsb[rr * 20 + part * 4]);
            cpa16(dst, Bp + (size_t)brow * Kc + k0 + part * 8, 16);
        }
    };

    loadTile(0, 0);
    cpa_commit();

    for (int t = 0; t < nt; t++) {
        if (t + 1 < nt) loadTile(t + 1, (t + 1) & 1);
        cpa_commit();
        cpa_wait1();
        __syncthreads();

        const int st = t & 1;
        const uint32_t* Asb = sraw + st * 2560;
        const uint32_t* Bsb = sraw + 5120 + st * 2560;
#pragma unroll
        for (int kk = 0; kk < 2; kk++) {
            uint32_t a[2][4], b[8][2];
#pragma unroll
            for (int mi = 0; mi < 2; mi++) {
                int mr = wm * 32 + mi * 16;
                a[mi][0] = Asb[(mr + gid)     * 20 + kk * 8 + tig];
                a[mi][1] = Asb[(mr + gid + 8) * 20 + kk * 8 + tig];
                a[mi][2] = Asb[(mr + gid)     * 20 + kk * 8 + 4 + tig];
                a[mi][3] = Asb[(mr + gid + 8) * 20 + kk * 8 + 4 + tig];
            }
#pragma unroll
            for (int ni = 0; ni < 8; ni++) {
                int nr = wn * 64 + ni * 8;
                b[ni][0] = Bsb[(nr + gid) * 20 + kk * 8 + tig];
                b[ni][1] = Bsb[(nr + gid) * 20 + kk * 8 + 4 + tig];
            }
#pragma unroll
            for (int mi = 0; mi < 2; mi++)
#pragma unroll
                for (int ni = 0; ni < 8; ni++)
                    mma16h(acc[mi][ni], a[mi], b[ni]);
        }
        __syncthreads();
    }

    // ---- fused epilogue: two 64-row passes through smem ----
    const float* bs = d_bsum + (size_t)dir * H4;
    float* lc   = d_lc[dir];
    __half* lhw = d_lhh[1 - pb][dir];
    const int t_idx = dir ? (4 - s) : s;
    float* aout = (dir ? d_ab : d_af) + t_idx * NN;

#pragma unroll
    for (int p = 0; p < 2; p++) {
        __syncthreads();
        if ((wm >> 1) == p) {
#pragma unroll
            for (int mi = 0; mi < 2; mi++)
#pragma unroll
                for (int half_ = 0; half_ < 2; half_++) {
                    int rloc = (wm & 1) * 32 + mi * 16 + gid + half_ * 8;
#pragma unroll
                    for (int ni = 0; ni < 8; ni++) {
                        int col = wn * 64 + ni * 8 + tig * 2;
                        gbuf[rloc * 133 + col]     = acc[mi][ni][half_ * 2 + 0];
                        gbuf[rloc * 133 + col + 1] = acc[mi][ni][half_ * 2 + 1];
                    }
                }
        }
        __syncthreads();

        int rr = tid >> 2;                 // 0..63
        int n  = row0 + p * 64 + rr;
        bool valid = n < NN;
        float part = 0.f;
        if (valid) {
            int jb = (tid & 3) * 8;
#pragma unroll
            for (int q = 0; q < 8; q++) {
                int jl = jb + q;           // 0..31
                int j  = c0 + jl;          // 0..255
                float gi = gbuf[rr * 133 +  0 + jl] + bs[0 * H + j];
                float gf = gbuf[rr * 133 + 32 + jl] + bs[1 * H + j];
                float gg = gbuf[rr * 133 + 64 + jl] + bs[2 * H + j];
                float go = gbuf[rr * 133 + 96 + jl] + bs[3 * H + j];
                size_t ix = (size_t)n * H + j;
                float cprev = (K2 > 0) ? lc[ix] : 0.f;
                float cc = sigf(gf) * cprev + sigf(gi) * tanhfast(gg);
                lc[ix] = cc;
                float hh = sigf(go) * tanhfast(cc);
                lhw[ix] = __float2half_rn(hh);
                part = fmaf(hh, attw[dir * H + j], part);
            }
        }
        part += __shfl_down_sync(0xffffffffu, part, 2);
        part += __shfl_down_sync(0xffffffffu, part, 1);
        if (valid && (tid & 3) == 0) atomicAdd(&aout[n], part);
    }
}

// ---------------- small kernels ----------------
__global__ void k_zero(float* p, int n) {
    int i = blockIdx.x * blockDim.x + threadIdx.x;
    if (i < n) p[i] = 0.f;
}
__global__ void k_zero02(float* p0, float* p1, int n) {
    int i = blockIdx.x * blockDim.x + threadIdx.x;
    if (i < n) { p0[i] = 0.f; p1[i] = 0.f; }
}
__global__ void k_zeroi(int* p, int n) {
    int i = blockIdx.x * blockDim.x + threadIdx.x;
    if (i < n) p[i] = 0;
}
__global__ void k_zero2() {   // zero bns+bnq
    int i = threadIdx.x;
    d_bns[i] = 0.f;
    d_bnq[i] = 0.f;
}

__global__ void k_degi(const int* __restrict__ dst) {
    int e = blockIdx.x * blockDim.x + threadIdx.x;
    if (e < NE) atomicAdd(&d_indeg[dst[e]], 1);
}

__global__ void k_scan() {
    const int T = 1024;
    __shared__ int buf[T];
    __shared__ int carry_s;
    int t = threadIdx.x;
    if (t == 0) carry_s = 0;
    __syncthreads();
    for (int base = 0; base < NN; base += T) {
        int v = (base + t < NN) ? d_indeg[base + t] : 0;
        buf[t] = v;
        __syncthreads();
        for (int off = 1; off < T; off <<= 1) {
            int add = (t >= off) ? buf[t - off] : 0;
            __syncthreads();
            buf[t] += add;
            __syncthreads();
        }
        int carry = carry_s;
        __syncthreads();
        if (base + t < NN) {
            d_rowptr[base + t] = carry + buf[t] - v;
            d_curp[base + t]   = carry + buf[t] - v;
        }
        if (t == T - 1) carry_s = carry + buf[t];
        __syncthreads();
    }
    if (t == 0) d_rowptr[NN] = carry_s;
}

__global__ void k_place(const int* __restrict__ src, const int* __restrict__ dst) {
    int e = blockIdx.x * blockDim.x + threadIdx.x;
    if (e >= NE) return;
    int slot = atomicAdd(&d_curp[dst[e]], 1);
    d_eid[slot]  = e;
    d_esrc[slot] = src[e];
}

// gT(half): [l][c][k*128+f] from g; rootT(half): [l][c][f]
__global__ void k_gt_h(const float* __restrict__ g, const float* __restrict__ root) {
    int i = blockIdx.x * blockDim.x + threadIdx.x;
    if (i < LL * C * KG * C) {
        int l   = i >> 17;
        int rem = i & 131071;
        int cR  = rem >> 10;
        int kf  = rem & 1023;
        int k = kf >> 7, f = kf & 127;
        d_gth[i] = __float2half_rn(g[((size_t)(l * 128 + f)) * 1024 + k * 128 + cR]);
    }
    if (i < LL * C * C) {
        int l = i >> 14;
        int c = (i >> 7) & 127;
        int f = i & 127;
        d_rooth[i] = __float2half_rn(root[((size_t)(l * 128 + f)) * 128 + c]);
    }
}

// half LSTM/MLP weights, fused biases, x->half
__global__ void k_prep(const float* __restrict__ wih, const float* __restrict__ whh,
                       const float* __restrict__ bih, const float* __restrict__ bhh,
                       const float* __restrict__ x,
                       const float* __restrict__ p1w, const float* __restrict__ p2w) {
    int i = blockIdx.x * blockDim.x + threadIdx.x;
    if (i < NN * C)       d_hlth[0][i] = __float2half_rn(x[i]);
    if (i < 2 * H4 * C)   d_wihh[i] = __float2half_rn(wih[i]);
    if (i < 2 * H4 * H)   d_whhh[i] = __float2half_rn(whh[i]);
    if (i < 2 * H4)       d_bsum[i] = bih[i] + bhh[i];
    if (i < NHID * C)  {
        int n = i / C, c = i % C;
        d_p1wh[i] = __float2half_rn(p1w[(size_t)c * NHID + n]);
    }
    if (i < NOUT * NHID) {
        int n = i / NHID, k = i % NHID;
        d_p2wh[i] = __float2half_rn(p2w[(size_t)k * NOUT + n]);
    }
}

// all-layer gaussian weights (half) in one launch
__global__ void k_ewall(const float* __restrict__ ea,
                        const float* __restrict__ mu,
                        const float* __restrict__ sg) {
    int e = blockIdx.x * blockDim.x + threadIdx.x;
    if (e >= NE) return;
    float a0 = ea[e * 2 + 0], a1 = ea[e * 2 + 1];
#pragma unroll
    for (int l = 0; l < LL; l++) {
        const float* mul = mu + l * KG * 2;
        const float* sgl = sg + l * KG * 2;
#pragma unroll
        for (int k = 0; k < KG; k++) {
            float dx = a0 - mul[k * 2 + 0];
            float dy = a1 - mul[k * 2 + 1];
            float s0 = sgl[k * 2 + 0], s1 = sgl[k * 2 + 1];
            float w = __expf(-0.5f * (__fdividef(dx * dx, 1e-15f + s0 * s0) +
                                      __fdividef(dy * dy, 1e-15f + s1 * s1)));
            d_ewh[l][(size_t)e * KG + k] = __float2half_rn(w);
        }
    }
}

// S accumulation (warp per node), gathers from HALF h rows (256B/edge)
__global__ void k_sacc(const __half* __restrict__ hinh, int layer) {
    int n = (blockIdx.x * blockDim.x + threadIdx.x) >> 5;
    int l = threadIdx.x & 31;
    if (n >= NN) return;
    const __half* ewl = d_ewh[layer];
    const __half2* h2b = (const __half2*)hinh;
    int beg = d_rowptr[n], end = d_rowptr[n + 1];
    float acc[KG][4];
#pragma unroll
    for (int k = 0; k < KG; k++)
#pragma unroll
        for (int q = 0; q < 4; q++) acc[k][q] = 0.f;

    for (int p = beg; p < end; p++) {
        int e = d_eid[p], s = d_esrc[p];
        float wv = (l < KG) ? __half2float(ewl[(size_t)e * KG + l]) : 0.f;
        const __half2* hr2 = h2b + (size_t)s * 64;
        float2 f0 = __half22float2(hr2[l]);
        float2 f1 = __half22float2(hr2[l + 32]);
#pragma unroll
        for (int k = 0; k < KG; k++) {
            float wk = __shfl_sync(0xffffffffu, wv, k);
            acc[k][0] = fmaf(wk, f0.x, acc[k][0]);
            acc[k][1] = fmaf(wk, f0.y, acc[k][1]);
            acc[k][2] = fmaf(wk, f1.x, acc[k][2]);
            acc[k][3] = fmaf(wk, f1.y, acc[k][3]);
        }
    }
    float inv = __fdividef(1.f, fmaxf((float)(end - beg), 1.f));
    __half2* Sp2 = (__half2*)&d_Sh[(size_t)n * (KG * C)];
#pragma unroll
    for (int k = 0; k < KG; k++) {
        Sp2[k * 64 + l]      = __floats2half2_rn(acc[k][0] * inv, acc[k][1] * inv);
        Sp2[k * 64 + 32 + l] = __floats2half2_rn(acc[k][2] * inv, acc[k][3] * inv);
    }
}

// BN apply: reads fp32 GEMM output d_h, writes only half activation copy
__global__ void k_bnapp(const float* __restrict__ gamma,
                        const float* __restrict__ beta,
                        __half* __restrict__ out_hlt, int relu) {
    int i = blockIdx.x * blockDim.x + threadIdx.x;
    if (i >= NN * C) return;
    int c = i % C;
    float mean = d_bns[c] / (float)NN;
    float var  = d_bnq[c] / (float)NN - mean * mean;
    float v = (d_h[i] - mean) * rsqrtf(var + 1e-5f) * gamma[c] + beta[c];
    if (relu) v = fmaxf(v, 0.f);
    out_hlt[i] = __float2half_rn(v);
}

// fused: attention softmax + weighted node rep (from half h_list) + pool
__global__ void k_nreppool(const float* __restrict__ x,
                           const int* __restrict__ batch) {
    int n = blockIdx.x;
    int c = threadIdx.x;
    __shared__ float p[5];
    __shared__ int gidx;
    if (c == 0) {
        float a[5], m = -1e30f;
#pragma unroll
        for (int t = 0; t < 5; t++) {
            a[t] = d_af[t * NN + n] + d_ab[t * NN + n];
            m = fmaxf(m, a[t]);
        }
        float s = 0.f;
#pragma unroll
        for (int t = 0; t < 5; t++) { a[t] = __expf(a[t] - m); s += a[t]; }
        float invs = __fdividef(1.f, s);
#pragma unroll
        for (int t = 0; t < 5; t++) p[t] = a[t] * invs;
        gidx = batch[n];
    }
    __syncthreads();
    float r = p[0] * x[(size_t)n * C + c];
#pragma unroll
    for (int t = 1; t < 5; t++)
        r = fmaf(p[t], __half2float(d_hlth[t][(size_t)n * C + c]), r);
    atomicAdd(&d_hg[(size_t)gidx * C + c], r);
}

__global__ void k_cnt(const int* __restrict__ batch) {
    int n = blockIdx.x * blockDim.x + threadIdx.x;
    if (n < NN) atomicAdd(&d_cnt[batch[n]], 1.f);
}

__global__ void k_pdiv() {
    int i = blockIdx.x * blockDim.x + threadIdx.x;
    if (i >= NB * C) return;
    float v = d_hg[i] / fmaxf(d_cnt[i / C], 1.f);
    d_hg[i]  = v;
    d_hgh[i] = __float2half_rn(v);
}

__global__ void k_ln(const float* __restrict__ g, const float* __restrict__ b,
                     float* __restrict__ out) {
    int row = blockIdx.x, t = threadIdx.x;
    __shared__ float sm[NOUT];
    float v = d_z2[(size_t)row * NOUT + t];
    sm[t] = v;
    __syncthreads();
    for (int o = NOUT / 2; o > 0; o >>= 1) {
        if (t < o) sm[t] += sm[t + o];
        __syncthreads();
    }
    float mean = sm[0] / (float)NOUT;
    __syncthreads();
    float dv = v - mean;
    sm[t] = dv * dv;
    __syncthreads();
    for (int o = NOUT / 2; o > 0; o >>= 1) {
        if (t < o) sm[t] += sm[t + o];
        __syncthreads();
    }
    float var = sm[0] / (float)NOUT;
    out[(size_t)row * NOUT + t] = dv * rsqrtf(var + 1e-5f) * g[t] + b[t];
}

// ---------------- host ----------------
static float* symf(const void* s) {
    void* p = nullptr;
    cudaGetSymbolAddress(&p, s);
    return (float*)p;
}
static __half* symh(const void* s) {
    void* p = nullptr;
    cudaGetSymbolAddress(&p, s);
    return (__half*)p;
}
static int* symi(const void* s) {
    void* p = nullptr;
    cudaGetSymbolAddress(&p, s);
    return (int*)p;
}

extern "C" void kernel_launch(void* const* d_in, const int* in_sizes, int n_in,
                              void* d_out, int out_size) {
    const float* x     = (const float*)d_in[0];
    const int*   ei    = (const int*)d_in[1];
    const int*   src   = ei;
    const int*   dst   = ei + NE;
    const float* ea    = (const float*)d_in[2];
    const int*   batch = (const int*)d_in[3];
    const float* g     = (const float*)d_in[4];
    const float* root  = (const float*)d_in[5];
    const float* bias  = (const float*)d_in[6];
    const float* mu    = (const float*)d_in[7];
    const float* sigma = (const float*)d_in[8];
    const float* bng   = (const float*)d_in[9];
    const float* bnb   = (const float*)d_in[10];
    const float* wih   = (const float*)d_in[11];
    const float* whh   = (const float*)d_in[12];
    const float* bih   = (const float*)d_in[13];
    const float* bhh   = (const float*)d_in[14];
    const float* attw  = (const float*)d_in[15];
    const float* p1w   = (const float*)d_in[17];
    const float* p1b   = (const float*)d_in[18];
    const float* p2w   = (const float*)d_in[19];
    const float* p2b   = (const float*)d_in[20];
    const float* lng   = (const float*)d_in[21];
    const float* lnb   = (const float*)d_in[22];
    float* out = (float*)d_out;

    float*  h     = symf(d_h);
    __half* hlth  = symh(d_hlth);
    __half* Sh    = symh(d_Sh);
    __half* gth   = symh(d_gth);
    __half* rooth = symh(d_rooth);
    float*  af    = symf(d_af);
    float*  ab    = symf(d_ab);
    float*  cnt   = symf(d_cnt);
    float*  hg    = symf(d_hg);
    __half* hgh   = symh(d_hgh);
    __half* z1h   = symh(d_z1h);
    float*  z2    = symf(d_z2);
    __half* p1wh  = symh(d_p1wh);
    __half* p2wh  = symh(d_p2wh);
    int* indeg    = symi(d_indeg);

    const int TPB = 256;
    const dim3 blk(TPB);
    const int gridNC = (NN * C + TPB - 1) / TPB;
    const int rowsN  = (NN + 127) / 128;
    const int TLSTM_SMEM = 40960;

    static int smem_set = 0;
    if (!smem_set) {
        cudaFuncSetAttribute(tlstm, cudaFuncAttributeMaxDynamicSharedMemorySize,
                             TLSTM_SMEM);
        smem_set = 1;
    }

    // -------- CSR build + weight prep --------
    k_zeroi<<<(NN + TPB - 1) / TPB, blk>>>(indeg, NN);
    k_degi<<<(NE + TPB - 1) / TPB, blk>>>(dst);
    k_scan<<<1, 1024>>>();
    k_place<<<(NE + TPB - 1) / TPB, blk>>>(src, dst);
    k_gt_h<<<(LL * C * KG * C + TPB - 1) / TPB, blk>>>(g, root);
    k_prep<<<(NN * C + TPB - 1) / TPB, blk>>>(wih, whh, bih, bhh, x, p1w, p2w);
    k_ewall<<<(NE + TPB - 1) / TPB, blk>>>(ea, mu, sigma);

    // -------- GMMConv layers (BN stats fused in GEMM epilogue) --------
    for (int i = 0; i < LL; i++) {
        k_sacc<<<(NN * 32 + TPB - 1) / TPB, blk>>>(hlth + (size_t)i * NN * C, i);
        k_zero2<<<1, C>>>();
        GH gl = {Sh, gth + (size_t)i * C * KG * C,
                 hlth + (size_t)i * NN * C, rooth + (size_t)i * C * C,
                 h, bias + i * C, KG * C, C};
        tgemm_h<false, false, true><<<dim3(1, rowsN), blk>>>(gl, NN, C);
        k_bnapp<<<gridNC, blk>>>(bng + i * C, bnb + i * C,
                                 hlth + (size_t)(i + 1) * NN * C,
                                 (i < LL - 1) ? 1 : 0);
    }

    // -------- bidirectional LSTM JumpingKnowledge (fused fp16 GEMM+cell) --
    k_zero02<<<(5 * NN + TPB - 1) / TPB, blk>>>(af, ab, 5 * NN);
    for (int s = 0; s < 5; s++) {
        int tf = s, tb = 4 - s;
        const __half* xf = hlth + (size_t)tf * NN * C;
        const __half* xb = hlth + (size_t)tb * NN * C;
        tlstm<<<dim3(H / 32, rowsN, 2), blk, TLSTM_SMEM>>>(xf, xb, attw,
                                                           (s > 0) ? H : 0, s);
    }

    // global mean pool (fused attention mix + scatter)
    k_zero<<<(NB + TPB - 1) / TPB, blk>>>(cnt, NB);
    k_zero<<<(NB * C + TPB - 1) / TPB, blk>>>(hg, NB * C);
    k_cnt<<<(NN + TPB - 1) / TPB, blk>>>(batch);
    k_nreppool<<<NN, C>>>(x, batch);
    k_pdiv<<<(NB * C + TPB - 1) / TPB, blk>>>();

    // MLP + LayerNorm (fp16 GEMMs)
    GH gp1 = {hgh, p1wh, nullptr, nullptr, z1h, p1b, C, 0};
    tgemm_h<true, true, false><<<dim3(NHID / 128, NB / 128), blk>>>(gp1, NB, NHID);
    GH gp2 = {z1h, p2wh, nullptr, nullptr, z2, p2b, NHID, 0};
    tgemm_h<false, false, false><<<dim3(NOUT / 128, NB / 128), blk>>>(gp2, NB, NOUT);
    k_ln<<<NB, NOUT>>>(lng, lnb, out);
}

// round 13
// speedup vs baseline: 1.8362x; 1.0517x over previous
#include <cuda_runtime.h>
#include <cuda_fp16.h>
#include <math.h>
#include <stdint.h>

// ---------------- problem constants ----------------
namespace {
constexpr int NN   = 30000;   // nodes
constexpr int NE   = 480000;  // edges
constexpr int C    = 128;     // channels (= F)
constexpr int KG   = 8;       // gaussians
constexpr int LL   = 4;       // layers
constexpr int H    = 256;     // LSTM hidden
constexpr int H4   = 1024;    // 4*H
constexpr int NHID = 512;
constexpr int NOUT = 256;
constexpr int NB   = 1024;    // graphs
}

// ---------------- scratch (device globals; no allocations allowed) -------
__device__ __align__(256) float  d_h[NN * C];
__device__ __align__(256) __half d_hlth[5][NN * C];      // half x,h1..h4
__device__ __align__(256) __half d_Sh[NN * KG * C];
__device__ __align__(256) __half d_gth[LL * C * KG * C]; // [l][c][k*128+f]
__device__ __align__(256) __half d_rooth[LL * C * C];    // [l][c][f]
__device__ __align__(256) __half d_ewh[LL][NE * KG];
__device__ __align__(256) float  d_bns[C];
__device__ __align__(256) float  d_bnq[C];
__device__ __align__(256) __half d_lhh[2][2][NN * H];    // [pingpong][dir]
__device__ __align__(256) float  d_lc[2][NN * H];
__device__ __align__(256) float  d_af[5 * NN];
__device__ __align__(256) float  d_ab[5 * NN];
__device__ __align__(256) float  d_cnt[NB];
__device__ __align__(256) float  d_hg[NB * C];
__device__ __align__(256) __half d_hgh[NB * C];
__device__ __align__(256) __half d_z1h[NB * NHID];
__device__ __align__(256) float  d_z2[NB * NOUT];
// half LSTM weights ([n][k] layout) + fused biases, half MLP weights
__device__ __align__(256) __half d_wihh[2 * H4 * C];
__device__ __align__(256) __half d_whhh[2 * H4 * H];
__device__ __align__(256) float  d_bsum[2 * H4];
__device__ __align__(256) __half d_p1wh[NHID * C];       // [n][k]
__device__ __align__(256) __half d_p2wh[NOUT * NHID];    // [n][k]
// CSR scratch
__device__ __align__(256) int d_indeg[NN];
__device__ __align__(256) int d_rowptr[NN + 1];
__device__ __align__(256) int d_curp[NN];
__device__ __align__(256) int d_eid[NE];
__device__ __align__(256) int d_esrc[NE];

// ---------------- helpers ----------------
__device__ __forceinline__ void mma16h(float* c, const uint32_t* a, const uint32_t* b) {
    asm volatile(
        "mma.sync.aligned.m16n8k16.row.col.f32.f16.f16.f32 "
        "{%0,%1,%2,%3}, {%4,%5,%6,%7}, {%8,%9}, {%0,%1,%2,%3};"
        : "+f"(c[0]), "+f"(c[1]), "+f"(c[2]), "+f"(c[3])
        : "r"(a[0]), "r"(a[1]), "r"(a[2]), "r"(a[3]), "r"(b[0]), "r"(b[1]));
}
__device__ __forceinline__ void ldsm4(uint32_t* r, uint32_t saddr) {
    asm volatile("ldmatrix.sync.aligned.m8n8.x4.shared.b16 {%0,%1,%2,%3}, [%4];"
                 : "=r"(r[0]), "=r"(r[1]), "=r"(r[2]), "=r"(r[3])
                 : "r"(saddr));
}
__device__ __forceinline__ void cpa16(uint32_t sdst, const void* gsrc, int srcsz) {
    asm volatile("cp.async.ca.shared.global [%0], [%1], 16, %2;\n"
                 :: "r"(sdst), "l"(gsrc), "r"(srcsz));
}
__device__ __forceinline__ void cpa_commit() { asm volatile("cp.async.commit_group;\n"); }
__device__ __forceinline__ void cpa_wait1()  { asm volatile("cp.async.wait_group 1;\n"); }
__device__ __forceinline__ float sigf(float x) {
    return __fdividef(1.f, 1.f + __expf(-x));
}
__device__ __forceinline__ float tanhfast(float x) {
    float t = __expf(-2.f * fabsf(x));
    float r = __fdividef(1.f - t, 1.f + t);
    return copysignf(r, x);
}

// ---------------- FP16 tensor GEMM (cp.async 2-stage, dual-K, TB form) ----
// If BN: also accumulates per-column sum/sumsq of outputs into d_bns/d_bnq.
struct GH {
    const __half* A;
    const __half* B;
    const __half* A2;
    const __half* B2;
    void* Cm;            // float* or __half* (OUTH)
    const float* bias;   // nullptr -> none
    int Kd;
    int Kd2;
};

template <bool RELU_, bool OUTH, bool BN>
__global__ __launch_bounds__(256) void tgemm_h(GH ga, int M, int Nm)
{
    __shared__ uint32_t As[2][2560];   // [row][20]
    __shared__ uint32_t Bs[2][2560];

    const __half* __restrict__ A  = ga.A;
    const __half* __restrict__ B  = ga.B;
    const __half* __restrict__ A2 = ga.A2;
    const __half* __restrict__ B2 = ga.B2;
    const float* __restrict__ bias = ga.bias;
    const int Kd = ga.Kd, Kd2 = ga.Kd2;

    const int tid  = threadIdx.x;
    const int lane = tid & 31;
    const int wid  = tid >> 5;
    const int wm   = wid & 3;
    const int wn   = wid >> 2;
    const int gid  = lane >> 2;
    const int tig  = lane & 3;
    const int row0 = blockIdx.y * 128, col0 = blockIdx.x * 128;

    const int nt1 = Kd >> 5;
    const int nt  = nt1 + (Kd2 >> 5);

    // ldmatrix lane-derived offsets
    const int aRow = (lane & 7) + ((lane >> 3) & 1) * 8;   // row within 16
    const int aCol = (lane >> 4) * 4;                       // uint32 col
    const int bRow = (lane & 7) + (lane >> 4) * 8;
    const int bCol = ((lane >> 3) & 1) * 4;
    const uint32_t asb = (uint32_t)__cvta_generic_to_shared(&As[0][0]);
    const uint32_t bsb = (uint32_t)__cvta_generic_to_shared(&Bs[0][0]);

    float acc[2][8][4];
#pragma unroll
    for (int mi = 0; mi < 2; mi++)
#pragma unroll
        for (int ni = 0; ni < 8; ni++)
#pragma unroll
            for (int r = 0; r < 4; r++) acc[mi][ni][r] = 0.f;

    auto loadTile = [&](int t, int st) {
        const __half* Ap; const __half* Bp; int Kc, k0;
        if (t < nt1) { Ap = A;  Bp = B;  Kc = Kd;  k0 = t << 5; }
        else         { Ap = A2; Bp = B2; Kc = Kd2; k0 = (t - nt1) << 5; }
#pragma unroll
        for (int it = 0; it < 2; it++) {
            int idx = tid + it * 256;
            int rr = idx >> 2, part = idx & 3;
            int gr = row0 + rr;
            uint32_t dst = (uint32_t)__cvta_generic_to_shared(&As[st][rr * 20 + part * 4]);
            cpa16(dst, Ap + (size_t)gr * Kc + k0 + part * 8, gr < M ? 16 : 0);
        }
#pragma unroll
        for (int it = 0; it < 2; it++) {
            int idx = tid + it * 256;
            int rr = idx >> 2, part = idx & 3;
            uint32_t dst = (uint32_t)__cvta_generic_to_shared(&Bs[st][rr * 20 + part * 4]);
            cpa16(dst, Bp + (size_t)(col0 + rr) * Kc + k0 + part * 8, 16);
        }
    };

    loadTile(0, 0);
    cpa_commit();

    for (int t = 0; t < nt; t++) {
        if (t + 1 < nt) loadTile(t + 1, (t + 1) & 1);
        cpa_commit();
        cpa_wait1();
        __syncthreads();

        const int st = t & 1;
        const uint32_t aST = asb + st * 2560 * 4;
        const uint32_t bST = bsb + st * 2560 * 4;
#pragma unroll
        for (int kk = 0; kk < 2; kk++) {
            uint32_t a[2][4], b[8][2];
#pragma unroll
            for (int mi = 0; mi < 2; mi++) {
                int mr = wm * 32 + mi * 16;
                ldsm4(a[mi], aST + ((mr + aRow) * 20 + kk * 8 + aCol) * 4);
            }
#pragma unroll
            for (int np = 0; np < 4; np++) {
                uint32_t bb[4];
                int nr = wn * 64 + np * 16;
                ldsm4(bb, bST + ((nr + bRow) * 20 + kk * 8 + bCol) * 4);
                b[np * 2][0]     = bb[0]; b[np * 2][1]     = bb[1];
                b[np * 2 + 1][0] = bb[2]; b[np * 2 + 1][1] = bb[3];
            }
#pragma unroll
            for (int mi = 0; mi < 2; mi++)
#pragma unroll
                for (int ni = 0; ni < 8; ni++)
                    mma16h(acc[mi][ni], a[mi], b[ni]);
        }
        __syncthreads();
    }

    // per-thread BN partials
    float cs[8][2], cq[8][2];
    if (BN) {
#pragma unroll
        for (int ni = 0; ni < 8; ni++) {
            cs[ni][0] = cs[ni][1] = 0.f;
            cq[ni][0] = cq[ni][1] = 0.f;
        }
    }

#pragma unroll
    for (int mi = 0; mi < 2; mi++) {
#pragma unroll
        for (int half_ = 0; half_ < 2; half_++) {
            int r = row0 + wm * 32 + mi * 16 + gid + half_ * 8;
            if (r >= M) continue;
#pragma unroll
            for (int ni = 0; ni < 8; ni++) {
                int cI = col0 + wn * 64 + ni * 8 + tig * 2;
                float v0 = acc[mi][ni][half_ * 2 + 0];
                float v1 = acc[mi][ni][half_ * 2 + 1];
                if (bias) { v0 += bias[cI]; v1 += bias[cI + 1]; }
                if (RELU_) { v0 = fmaxf(v0, 0.f); v1 = fmaxf(v1, 0.f); }
                if (OUTH) {
                    __half2* cp = (__half2*)((__half*)ga.Cm + (size_t)r * Nm + cI);
                    *cp = __floats2half2_rn(v0, v1);
                } else {
                    float* cp = (float*)ga.Cm + (size_t)r * Nm + cI;
                    cp[0] = v0; cp[1] = v1;
                }
                if (BN) {
                    cs[ni][0] += v0; cq[ni][0] += v0 * v0;
                    cs[ni][1] += v1; cq[ni][1] += v1 * v1;
                }
            }
        }
    }

    if (BN) {
#pragma unroll
        for (int off = 16; off >= 4; off >>= 1) {
#pragma unroll
            for (int ni = 0; ni < 8; ni++) {
#pragma unroll
                for (int sub = 0; sub < 2; sub++) {
                    cs[ni][sub] += __shfl_down_sync(0xffffffffu, cs[ni][sub], off);
                    cq[ni][sub] += __shfl_down_sync(0xffffffffu, cq[ni][sub], off);
                }
            }
        }
        float* bnb = (float*)As;
        if (gid == 0) {
#pragma unroll
            for (int ni = 0; ni < 8; ni++)
#pragma unroll
                for (int sub = 0; sub < 2; sub++) {
                    int slot = (((wid << 2) | tig) * 8 + ni) * 4 + sub * 2;
                    bnb[slot]     = cs[ni][sub];
                    bnb[slot + 1] = cq[ni][sub];
                }
        }
        __syncthreads();
        int colL = tid >> 1, stat = tid & 1;
        int wn_ = colL >> 6, r_ = colL & 63;
        int ni_ = r_ >> 3, q_ = r_ & 7, tig_ = q_ >> 1, sub_ = q_ & 1;
        float v = 0.f;
#pragma unroll
        for (int wm_ = 0; wm_ < 4; wm_++) {
            int wid_ = wn_ * 4 + wm_;
            v += bnb[(((wid_ << 2) | tig_) * 8 + ni_) * 4 + sub_ * 2 + stat];
        }
        atomicAdd(stat ? &d_bnq[col0 + colL] : &d_bns[col0 + colL], v);
    }
}

// ---------------- fused LSTM step (FP16): GEMM + cell + attention dot ----
__global__ __launch_bounds__(256) void tlstm(
    const __half* __restrict__ xf, const __half* __restrict__ xb,
    const float* __restrict__ attw, int K2, int s)
{
    extern __shared__ uint32_t sraw[];   // 10240 words = 40960 B
    float* gbuf = (float*)sraw;          // epilogue: [64][133]

    const int dir  = blockIdx.z;
    const int c0   = blockIdx.x * 32;
    const int row0 = blockIdx.y * 128;
    const int pb   = s & 1;

    const __half* A  = dir ? xb : xf;
    const __half* B  = d_wihh + (size_t)dir * H4 * C;
    const __half* A2 = d_lhh[pb][dir];
    const __half* B2 = d_whhh + (size_t)dir * H4 * H;

    const int tid  = threadIdx.x;
    const int lane = tid & 31;
    const int wid  = tid >> 5;
    const int wm   = wid & 3;
    const int wn   = wid >> 2;
    const int gid  = lane >> 2;
    const int tig  = lane & 3;

    const int nt1 = C >> 5;              // 4
    const int nt  = nt1 + (K2 >> 5);     // 4 or 12

    const int aRow = (lane & 7) + ((lane >> 3) & 1) * 8;
    const int aCol = (lane >> 4) * 4;
    const int bRow = (lane & 7) + (lane >> 4) * 8;
    const int bCol = ((lane >> 3) & 1) * 4;
    const uint32_t sbase = (uint32_t)__cvta_generic_to_shared(sraw);

    float acc[2][8][4];
#pragma unroll
    for (int mi = 0; mi < 2; mi++)
#pragma unroll
        for (int ni = 0; ni < 8; ni++)
#pragma unroll
            for (int r = 0; r < 4; r++) acc[mi][ni][r] = 0.f;

    auto loadTile = [&](int t, int st) {
        const __half* Ap; const __half* Bp; int Kc, k0;
        if (t < nt1) { Ap = A;  Bp = B;  Kc = C; k0 = t << 5; }
        else         { Ap = A2; Bp = B2; Kc = H; k0 = (t - nt1) << 5; }
        uint32_t* Asb = sraw + st * 2560;
        uint32_t* Bsb = sraw + 5120 + st * 2560;
#pragma unroll
        for (int it = 0; it < 2; it++) {
            int idx = tid + it * 256;
            int rr = idx >> 2, part = idx & 3;
            int gr = row0 + rr;
            uint32_t dst = (uint32_t)__cvta_generic_to_shared(&Asb[rr * 20 + part * 4]);
            cpa16(dst, Ap + (size_t)gr * Kc + k0 + part * 8, gr < NN ? 16 : 0);
        }
#pragma unroll
        for (int it = 0; it < 2; it++) {
            int idx = tid + it * 256;
            int rr = idx >> 2, part = idx & 3;
            int brow = ((rr >> 5) << 8) + c0 + (rr & 31);   // gate*256 + c0 + j'
            uint32_t dst = (uint32_t)__cvta_generic_to_shared(&Bsb[rr * 20 + part * 4]);
            cpa16(dst, Bp + (size_t)brow * Kc + k0 + part * 8, 16);
        }
    };

    loadTile(0, 0);
    cpa_commit();

    for (int t = 0; t < nt; t++) {
        if (t + 1 < nt) loadTile(t + 1, (t + 1) & 1);
        cpa_commit();
        cpa_wait1();
        __syncthreads();

        const int st = t & 1;
        const uint32_t aST = sbase + st * 2560 * 4;
        const uint32_t bST = sbase + (5120 + st * 2560) * 4;
#pragma unroll
        for (int kk = 0; kk < 2; kk++) {
            uint32_t a[2][4], b[8][2];
#pragma unroll
            for (int mi = 0; mi < 2; mi++) {
                int mr = wm * 32 + mi * 16;
                ldsm4(a[mi], aST + ((mr + aRow) * 20 + kk * 8 + aCol) * 4);
            }
#pragma unroll
            for (int np = 0; np < 4; np++) {
                uint32_t bb[4];
                int nr = wn * 64 + np * 16;
                ldsm4(bb, bST + ((nr + bRow) * 20 + kk * 8 + bCol) * 4);
                b[np * 2][0]     = bb[0]; b[np * 2][1]     = bb[1];
                b[np * 2 + 1][0] = bb[2]; b[np * 2 + 1][1] = bb[3];
            }
#pragma unroll
            for (int mi = 0; mi < 2; mi++)
#pragma unroll
                for (int ni = 0; ni < 8; ni++)
                    mma16h(acc[mi][ni], a[mi], b[ni]);
        }
        __syncthreads();
    }

    // ---- fused epilogue: two 64-row passes through smem ----
    const float* bs = d_bsum + (size_t)dir * H4;
    float* lc   = d_lc[dir];
    __half* lhw = d_lhh[1 - pb][dir];
    const int t_idx = dir ? (4 - s) : s;
    float* aout = (dir ? d_ab : d_af) + t_idx * NN;

#pragma unroll
    for (int p = 0; p < 2; p++) {
        __syncthreads();
        if ((wm >> 1) == p) {
#pragma unroll
            for (int mi = 0; mi < 2; mi++)
#pragma unroll
                for (int half_ = 0; half_ < 2; half_++) {
                    int rloc = (wm & 1) * 32 + mi * 16 + gid + half_ * 8;
#pragma unroll
                    for (int ni = 0; ni < 8; ni++) {
                        int col = wn * 64 + ni * 8 + tig * 2;
                        gbuf[rloc * 133 + col]     = acc[mi][ni][half_ * 2 + 0];
                        gbuf[rloc * 133 + col + 1] = acc[mi][ni][half_ * 2 + 1];
                    }
                }
        }
        __syncthreads();

        int rr = tid >> 2;                 // 0..63
        int n  = row0 + p * 64 + rr;
        bool valid = n < NN;
        float part = 0.f;
        if (valid) {
            int jb = (tid & 3) * 8;
#pragma unroll
            for (int q = 0; q < 8; q++) {
                int jl = jb + q;           // 0..31
                int j  = c0 + jl;          // 0..255
                float gi = gbuf[rr * 133 +  0 + jl] + bs[0 * H + j];
                float gf = gbuf[rr * 133 + 32 + jl] + bs[1 * H + j];
                float gg = gbuf[rr * 133 + 64 + jl] + bs[2 * H + j];
                float go = gbuf[rr * 133 + 96 + jl] + bs[3 * H + j];
                size_t ix = (size_t)n * H + j;
                float cprev = (K2 > 0) ? lc[ix] : 0.f;
                float cc = sigf(gf) * cprev + sigf(gi) * tanhfast(gg);
                lc[ix] = cc;
                float hh = sigf(go) * tanhfast(cc);
                lhw[ix] = __float2half_rn(hh);
                part = fmaf(hh, attw[dir * H + j], part);
            }
        }
        part += __shfl_down_sync(0xffffffffu, part, 2);
        part += __shfl_down_sync(0xffffffffu, part, 1);
        if (valid && (tid & 3) == 0) atomicAdd(&aout[n], part);
    }
}

// ---------------- small kernels ----------------
__global__ void k_zero(float* p, int n) {
    int i = blockIdx.x * blockDim.x + threadIdx.x;
    if (i < n) p[i] = 0.f;
}
__global__ void k_zero02(float* p0, float* p1, int n) {
    int i = blockIdx.x * blockDim.x + threadIdx.x;
    if (i < n) { p0[i] = 0.f; p1[i] = 0.f; }
}
__global__ void k_zeroi(int* p, int n) {
    int i = blockIdx.x * blockDim.x + threadIdx.x;
    if (i < n) p[i] = 0;
}
__global__ void k_zero2() {
    int i = threadIdx.x;
    d_bns[i] = 0.f;
    d_bnq[i] = 0.f;
}

__global__ void k_degi(const int* __restrict__ dst) {
    int e = blockIdx.x * blockDim.x + threadIdx.x;
    if (e < NE) atomicAdd(&d_indeg[dst[e]], 1);
}

__global__ void k_scan() {
    const int T = 1024;
    __shared__ int buf[T];
    __shared__ int carry_s;
    int t = threadIdx.x;
    if (t == 0) carry_s = 0;
    __syncthreads();
    for (int base = 0; base < NN; base += T) {
        int v = (base + t < NN) ? d_indeg[base + t] : 0;
        buf[t] = v;
        __syncthreads();
        for (int off = 1; off < T; off <<= 1) {
            int add = (t >= off) ? buf[t - off] : 0;
            __syncthreads();
            buf[t] += add;
            __syncthreads();
        }
        int carry = carry_s;
        __syncthreads();
        if (base + t < NN) {
            d_rowptr[base + t] = carry + buf[t] - v;
            d_curp[base + t]   = carry + buf[t] - v;
        }
        if (t == T - 1) carry_s = carry + buf[t];
        __syncthreads();
    }
    if (t == 0) d_rowptr[NN] = carry_s;
}

__global__ void k_place(const int* __restrict__ src, const int* __restrict__ dst) {
    int e = blockIdx.x * blockDim.x + threadIdx.x;
    if (e >= NE) return;
    int slot = atomicAdd(&d_curp[dst[e]], 1);
    d_eid[slot]  = e;
    d_esrc[slot] = src[e];
}

// gT(half): [l][c][k*128+f] from g; rootT(half): [l][c][f]
__global__ void k_gt_h(const float* __restrict__ g, const float* __restrict__ root) {
    int i = blockIdx.x * blockDim.x + threadIdx.x;
    if (i < LL * C * KG * C) {
        int l   = i >> 17;
        int rem = i & 131071;
        int cR  = rem >> 10;
        int kf  = rem & 1023;
        int k = kf >> 7, f = kf & 127;
        d_gth[i] = __float2half_rn(g[((size_t)(l * 128 + f)) * 1024 + k * 128 + cR]);
    }
    if (i < LL * C * C) {
        int l = i >> 14;
        int c = (i >> 7) & 127;
        int f = i & 127;
        d_rooth[i] = __float2half_rn(root[((size_t)(l * 128 + f)) * 128 + c]);
    }
}

// half LSTM/MLP weights, fused biases, x->half
__global__ void k_prep(const float* __restrict__ wih, const float* __restrict__ whh,
                       const float* __restrict__ bih, const float* __restrict__ bhh,
                       const float* __restrict__ x,
                       const float* __restrict__ p1w, const float* __restrict__ p2w) {
    int i = blockIdx.x * blockDim.x + threadIdx.x;
    if (i < NN * C)       d_hlth[0][i] = __float2half_rn(x[i]);
    if (i < 2 * H4 * C)   d_wihh[i] = __float2half_rn(wih[i]);
    if (i < 2 * H4 * H)   d_whhh[i] = __float2half_rn(whh[i]);
    if (i < 2 * H4)       d_bsum[i] = bih[i] + bhh[i];
    if (i < NHID * C)  {
        int n = i / C, c = i % C;
        d_p1wh[i] = __float2half_rn(p1w[(size_t)c * NHID + n]);
    }
    if (i < NOUT * NHID) {
        int n = i / NHID, k = i % NHID;
        d_p2wh[i] = __float2half_rn(p2w[(size_t)k * NOUT + n]);
    }
}

// all-layer gaussian weights (half) in one launch
__global__ void k_ewall(const float* __restrict__ ea,
                        const float* __restrict__ mu,
                        const float* __restrict__ sg) {
    int e = blockIdx.x * blockDim.x + threadIdx.x;
    if (e >= NE) return;
    float a0 = ea[e * 2 + 0], a1 = ea[e * 2 + 1];
#pragma unroll
    for (int l = 0; l < LL; l++) {
        const float* mul = mu + l * KG * 2;
        const float* sgl = sg + l * KG * 2;
#pragma unroll
        for (int k = 0; k < KG; k++) {
            float dx = a0 - mul[k * 2 + 0];
            float dy = a1 - mul[k * 2 + 1];
            float s0 = sgl[k * 2 + 0], s1 = sgl[k * 2 + 1];
            float w = __expf(-0.5f * (__fdividef(dx * dx, 1e-15f + s0 * s0) +
                                      __fdividef(dy * dy, 1e-15f + s1 * s1)));
            d_ewh[l][(size_t)e * KG + k] = __float2half_rn(w);
        }
    }
}

// S accumulation (warp per node), gathers from HALF h rows (256B/edge)
__global__ void k_sacc(const __half* __restrict__ hinh, int layer) {
    int n = (blockIdx.x * blockDim.x + threadIdx.x) >> 5;
    int l = threadIdx.x & 31;
    if (n >= NN) return;
    const __half* ewl = d_ewh[layer];
    const __half2* h2b = (const __half2*)hinh;
    int beg = d_rowptr[n], end = d_rowptr[n + 1];
    float acc[KG][4];
#pragma unroll
    for (int k = 0; k < KG; k++)
#pragma unroll
        for (int q = 0; q < 4; q++) acc[k][q] = 0.f;

    for (int p = beg; p < end; p++) {
        int e = d_eid[p], s = d_esrc[p];
        float wv = (l < KG) ? __half2float(ewl[(size_t)e * KG + l]) : 0.f;
        const __half2* hr2 = h2b + (size_t)s * 64;
        float2 f0 = __half22float2(hr2[l]);
        float2 f1 = __half22float2(hr2[l + 32]);
#pragma unroll
        for (int k = 0; k < KG; k++) {
            float wk = __shfl_sync(0xffffffffu, wv, k);
            acc[k][0] = fmaf(wk, f0.x, acc[k][0]);
            acc[k][1] = fmaf(wk, f0.y, acc[k][1]);
            acc[k][2] = fmaf(wk, f1.x, acc[k][2]);
            acc[k][3] = fmaf(wk, f1.y, acc[k][3]);
        }
    }
    float inv = __fdividef(1.f, fmaxf((float)(end - beg), 1.f));
    __half2* Sp2 = (__half2*)&d_Sh[(size_t)n * (KG * C)];
#pragma unroll
    for (int k = 0; k < KG; k++) {
        Sp2[k * 64 + l]      = __floats2half2_rn(acc[k][0] * inv, acc[k][1] * inv);
        Sp2[k * 64 + 32 + l] = __floats2half2_rn(acc[k][2] * inv, acc[k][3] * inv);
    }
}

// BN apply: reads fp32 GEMM output d_h, writes only half activation copy
__global__ void k_bnapp(const float* __restrict__ gamma,
                        const float* __restrict__ beta,
                        __half* __restrict__ out_hlt, int relu) {
    int i = blockIdx.x * blockDim.x + threadIdx.x;
    if (i >= NN * C) return;
    int c = i % C;
    float mean = d_bns[c] / (float)NN;
    float var  = d_bnq[c] / (float)NN - mean * mean;
    float v = (d_h[i] - mean) * rsqrtf(var + 1e-5f) * gamma[c] + beta[c];
    if (relu) v = fmaxf(v, 0.f);
    out_hlt[i] = __float2half_rn(v);
}

// fused: attention softmax + weighted node rep (from half h_list) + pool
__global__ void k_nreppool(const float* __restrict__ x,
                           const int* __restrict__ batch) {
    int n = blockIdx.x;
    int c = threadIdx.x;
    __shared__ float p[5];
    __shared__ int gidx;
    if (c == 0) {
        float a[5], m = -1e30f;
#pragma unroll
        for (int t = 0; t < 5; t++) {
            a[t] = d_af[t * NN + n] + d_ab[t * NN + n];
            m = fmaxf(m, a[t]);
        }
        float s = 0.f;
#pragma unroll
        for (int t = 0; t < 5; t++) { a[t] = __expf(a[t] - m); s += a[t]; }
        float invs = __fdividef(1.f, s);
#pragma unroll
        for (int t = 0; t < 5; t++) p[t] = a[t] * invs;
        gidx = batch[n];
    }
    __syncthreads();
    float r = p[0] * x[(size_t)n * C + c];
#pragma unroll
    for (int t = 1; t < 5; t++)
        r = fmaf(p[t], __half2float(d_hlth[t][(size_t)n * C + c]), r);
    atomicAdd(&d_hg[(size_t)gidx * C + c], r);
}

__global__ void k_cnt(const int* __restrict__ batch) {
    int n = blockIdx.x * blockDim.x + threadIdx.x;
    if (n < NN) atomicAdd(&d_cnt[batch[n]], 1.f);
}

__global__ void k_pdiv() {
    int i = blockIdx.x * blockDim.x + threadIdx.x;
    if (i >= NB * C) return;
    float v = d_hg[i] / fmaxf(d_cnt[i / C], 1.f);
    d_hg[i]  = v;
    d_hgh[i] = __float2half_rn(v);
}

__global__ void k_ln(const float* __restrict__ g, const float* __restrict__ b,
                     float* __restrict__ out) {
    int row = blockIdx.x, t = threadIdx.x;
    __shared__ float sm[NOUT];
    float v = d_z2[(size_t)row * NOUT + t];
    sm[t] = v;
    __syncthreads();
    for (int o = NOUT / 2; o > 0; o >>= 1) {
        if (t < o) sm[t] += sm[t + o];
        __syncthreads();
    }
    float mean = sm[0] / (float)NOUT;
    __syncthreads();
    float dv = v - mean;
    sm[t] = dv * dv;
    __syncthreads();
    for (int o = NOUT / 2; o > 0; o >>= 1) {
        if (t < o) sm[t] += sm[t + o];
        __syncthreads();
    }
    float var = sm[0] / (float)NOUT;
    out[(size_t)row * NOUT + t] = dv * rsqrtf(var + 1e-5f) * g[t] + b[t];
}

// ---------------- host ----------------
static float* symf(const void* s) {
    void* p = nullptr;
    cudaGetSymbolAddress(&p, s);
    return (float*)p;
}
static __half* symh(const void* s) {
    void* p = nullptr;
    cudaGetSymbolAddress(&p, s);
    return (__half*)p;
}
static int* symi(const void* s) {
    void* p = nullptr;
    cudaGetSymbolAddress(&p, s);
    return (int*)p;
}

extern "C" void kernel_launch(void* const* d_in, const int* in_sizes, int n_in,
                              void* d_out, int out_size) {
    const float* x     = (const float*)d_in[0];
    const int*   ei    = (const int*)d_in[1];
    const int*   src   = ei;
    const int*   dst   = ei + NE;
    const float* ea    = (const float*)d_in[2];
    const int*   batch = (const int*)d_in[3];
    const float* g     = (const float*)d_in[4];
    const float* root  = (const float*)d_in[5];
    const float* bias  = (const float*)d_in[6];
    const float* mu    = (const float*)d_in[7];
    const float* sigma = (const float*)d_in[8];
    const float* bng   = (const float*)d_in[9];
    const float* bnb   = (const float*)d_in[10];
    const float* wih   = (const float*)d_in[11];
    const float* whh   = (const float*)d_in[12];
    const float* bih   = (const float*)d_in[13];
    const float* bhh   = (const float*)d_in[14];
    const float* attw  = (const float*)d_in[15];
    const float* p1w   = (const float*)d_in[17];
    const float* p1b   = (const float*)d_in[18];
    const float* p2w   = (const float*)d_in[19];
    const float* p2b   = (const float*)d_in[20];
    const float* lng   = (const float*)d_in[21];
    const float* lnb   = (const float*)d_in[22];
    float* out = (float*)d_out;

    float*  h     = symf(d_h);
    __half* hlth  = symh(d_hlth);
    __half* Sh    = symh(d_Sh);
    __half* gth   = symh(d_gth);
    __half* rooth = symh(d_rooth);
    float*  af    = symf(d_af);
    float*  ab    = symf(d_ab);
    float*  cnt   = symf(d_cnt);
    float*  hg    = symf(d_hg);
    __half* hgh   = symh(d_hgh);
    __half* z1h   = symh(d_z1h);
    float*  z2    = symf(d_z2);
    __half* p1wh  = symh(d_p1wh);
    __half* p2wh  = symh(d_p2wh);
    int* indeg    = symi(d_indeg);

    const int TPB = 256;
    const dim3 blk(TPB);
    const int gridNC = (NN * C + TPB - 1) / TPB;
    const int rowsN  = (NN + 127) / 128;
    const int TLSTM_SMEM = 40960;

    static int smem_set = 0;
    if (!smem_set) {
        cudaFuncSetAttribute(tlstm, cudaFuncAttributeMaxDynamicSharedMemorySize,
                             TLSTM_SMEM);
        smem_set = 1;
    }

    // -------- CSR build + weight prep --------
    k_zeroi<<<(NN + TPB - 1) / TPB, blk>>>(indeg, NN);
    k_degi<<<(NE + TPB - 1) / TPB, blk>>>(dst);
    k_scan<<<1, 1024>>>();
    k_place<<<(NE + TPB - 1) / TPB, blk>>>(src, dst);
    k_gt_h<<<(LL * C * KG * C + TPB - 1) / TPB, blk>>>(g, root);
    k_prep<<<(NN * C + TPB - 1) / TPB, blk>>>(wih, whh, bih, bhh, x, p1w, p2w);
    k_ewall<<<(NE + TPB - 1) / TPB, blk>>>(ea, mu, sigma);

    // -------- GMMConv layers (BN stats fused in GEMM epilogue) --------
    for (int i = 0; i < LL; i++) {
        k_sacc<<<(NN * 32 + TPB - 1) / TPB, blk>>>(hlth + (size_t)i * NN * C, i);
        k_zero2<<<1, C>>>();
        GH gl = {Sh, gth + (size_t)i * C * KG * C,
                 hlth + (size_t)i * NN * C, rooth + (size_t)i * C * C,
                 h, bias + i * C, KG * C, C};
        tgemm_h<false, false, true><<<dim3(1, rowsN), blk>>>(gl, NN, C);
        k_bnapp<<<gridNC, blk>>>(bng + i * C, bnb + i * C,
                                 hlth + (size_t)(i + 1) * NN * C,
                                 (i < LL - 1) ? 1 : 0);
    }

    // -------- bidirectional LSTM JumpingKnowledge (fused fp16 GEMM+cell) --
    k_zero02<<<(5 * NN + TPB - 1) / TPB, blk>>>(af, ab, 5 * NN);
    for (int s = 0; s < 5; s++) {
        int tf = s, tb = 4 - s;
        const __half* xf = hlth + (size_t)tf * NN * C;
        const __half* xb = hlth + (size_t)tb * NN * C;
        tlstm<<<dim3(H / 32, rowsN, 2), blk, TLSTM_SMEM>>>(xf, xb, attw,
                                                           (s > 0) ? H : 0, s);
    }

    // global mean pool (fused attention mix + scatter)
    k_zero<<<(NB + TPB - 1) / TPB, blk>>>(cnt, NB);
    k_zero<<<(NB * C + TPB - 1) / TPB, blk>>>(hg, NB * C);
    k_cnt<<<(NN + TPB - 1) / TPB, blk>>>(batch);
    k_nreppool<<<NN, C>>>(x, batch);
    k_pdiv<<<(NB * C + TPB - 1) / TPB, blk>>>();

    // MLP + LayerNorm (fp16 GEMMs)
    GH gp1 = {hgh, p1wh, nullptr, nullptr, z1h, p1b, C, 0};
    tgemm_h<true, true, false><<<dim3(NHID / 128, NB / 128), blk>>>(gp1, NB, NHID);
    GH gp2 = {z1h, p2wh, nullptr, nullptr, z2, p2b, NHID, 0};
    tgemm_h<false, false, false><<<dim3(NOUT / 128, NB / 128), blk>>>(gp2, NB, NOUT);
    k_ln<<<NB, NOUT>>>(lng, lnb, out);
}

// round 14
// speedup vs baseline: 1.8533x; 1.0093x over previous
#include <cuda_runtime.h>
#include <cuda_fp16.h>
#include <math.h>
#include <stdint.h>

// ---------------- problem constants ----------------
namespace {
constexpr int NN   = 30000;   // nodes
constexpr int NE   = 480000;  // edges
constexpr int C    = 128;     // channels (= F)
constexpr int KG   = 8;       // gaussians
constexpr int LL   = 4;       // layers
constexpr int H    = 256;     // LSTM hidden
constexpr int H4   = 1024;    // 4*H
constexpr int NHID = 512;
constexpr int NOUT = 256;
constexpr int NB   = 1024;    // graphs
}

// ---------------- scratch (device globals; no allocations allowed) -------
__device__ __align__(256) __half d_hh[NN * C];           // GMM GEMM out (half)
__device__ __align__(256) __half d_hlth[5][NN * C];      // half x,h1..h4
__device__ __align__(256) __half d_Sh[NN * KG * C];
__device__ __align__(256) __half d_gth[LL * C * KG * C]; // [l][c][k*128+f]
__device__ __align__(256) __half d_rooth[LL * C * C];    // [l][c][f]
__device__ __align__(256) __half d_ewh[LL][NE * KG];
__device__ __align__(256) float  d_bns[C];
__device__ __align__(256) float  d_bnq[C];
__device__ __align__(256) __half d_lhh[2][2][NN * H];    // [pingpong][dir]
__device__ __align__(256) float  d_lc[2][NN * H];
__device__ __align__(256) float  d_af[5 * NN];
__device__ __align__(256) float  d_ab[5 * NN];
__device__ __align__(256) float  d_cnt[NB];
__device__ __align__(256) float  d_hg[NB * C];
__device__ __align__(256) __half d_hgh[NB * C];
__device__ __align__(256) __half d_z1h[NB * NHID];
__device__ __align__(256) float  d_z2[NB * NOUT];
// half LSTM weights ([n][k] layout) + fused biases, half MLP weights
__device__ __align__(256) __half d_wihh[2 * H4 * C];
__device__ __align__(256) __half d_whhh[2 * H4 * H];
__device__ __align__(256) float  d_bsum[2 * H4];
__device__ __align__(256) __half d_p1wh[NHID * C];       // [n][k]
__device__ __align__(256) __half d_p2wh[NOUT * NHID];    // [n][k]
// CSR scratch
__device__ __align__(256) int d_indeg[NN];
__device__ __align__(256) int d_rowptr[NN + 1];
__device__ __align__(256) int d_curp[NN];
__device__ __align__(256) int d_eid[NE];
__device__ __align__(256) int d_esrc[NE];

// ---------------- helpers ----------------
__device__ __forceinline__ void mma16h(float* c, const uint32_t* a, const uint32_t* b) {
    asm volatile(
        "mma.sync.aligned.m16n8k16.row.col.f32.f16.f16.f32 "
        "{%0,%1,%2,%3}, {%4,%5,%6,%7}, {%8,%9}, {%0,%1,%2,%3};"
        : "+f"(c[0]), "+f"(c[1]), "+f"(c[2]), "+f"(c[3])
        : "r"(a[0]), "r"(a[1]), "r"(a[2]), "r"(a[3]), "r"(b[0]), "r"(b[1]));
}
__device__ __forceinline__ void ldsm4(uint32_t* r, uint32_t saddr) {
    asm volatile("ldmatrix.sync.aligned.m8n8.x4.shared.b16 {%0,%1,%2,%3}, [%4];"
                 : "=r"(r[0]), "=r"(r[1]), "=r"(r[2]), "=r"(r[3])
                 : "r"(saddr));
}
__device__ __forceinline__ void cpa16(uint32_t sdst, const void* gsrc, int srcsz) {
    asm volatile("cp.async.ca.shared.global [%0], [%1], 16, %2;\n"
                 :: "r"(sdst), "l"(gsrc), "r"(srcsz));
}
__device__ __forceinline__ void cpa_commit() { asm volatile("cp.async.commit_group;\n"); }
__device__ __forceinline__ void cpa_wait1()  { asm volatile("cp.async.wait_group 1;\n"); }
__device__ __forceinline__ float sigf(float x) {
    return __fdividef(1.f, 1.f + __expf(-x));
}
__device__ __forceinline__ float tanhfast(float x) {
    float t = __expf(-2.f * fabsf(x));
    float r = __fdividef(1.f - t, 1.f + t);
    return copysignf(r, x);
}

// ---------------- FP16 tensor GEMM (cp.async 2-stage, dual-K, TB form) ----
// If BN: also accumulates per-column sum/sumsq of outputs into d_bns/d_bnq.
struct GH {
    const __half* A;
    const __half* B;
    const __half* A2;
    const __half* B2;
    void* Cm;            // float* or __half* (OUTH)
    const float* bias;   // nullptr -> none
    int Kd;
    int Kd2;
};

template <bool RELU_, bool OUTH, bool BN>
__global__ __launch_bounds__(256) void tgemm_h(GH ga, int M, int Nm)
{
    __shared__ uint32_t As[2][2560];   // [row][20]
    __shared__ uint32_t Bs[2][2560];

    const __half* __restrict__ A  = ga.A;
    const __half* __restrict__ B  = ga.B;
    const __half* __restrict__ A2 = ga.A2;
    const __half* __restrict__ B2 = ga.B2;
    const float* __restrict__ bias = ga.bias;
    const int Kd = ga.Kd, Kd2 = ga.Kd2;

    const int tid  = threadIdx.x;
    const int lane = tid & 31;
    const int wid  = tid >> 5;
    const int wm   = wid & 3;
    const int wn   = wid >> 2;
    const int gid  = lane >> 2;
    const int tig  = lane & 3;
    const int row0 = blockIdx.y * 128, col0 = blockIdx.x * 128;

    const int nt1 = Kd >> 5;
    const int nt  = nt1 + (Kd2 >> 5);

    const int aRow = (lane & 7) + ((lane >> 3) & 1) * 8;
    const int aCol = (lane >> 4) * 4;
    const int bRow = (lane & 7) + (lane >> 4) * 8;
    const int bCol = ((lane >> 3) & 1) * 4;
    const uint32_t asb = (uint32_t)__cvta_generic_to_shared(&As[0][0]);
    const uint32_t bsb = (uint32_t)__cvta_generic_to_shared(&Bs[0][0]);

    float acc[2][8][4];
#pragma unroll
    for (int mi = 0; mi < 2; mi++)
#pragma unroll
        for (int ni = 0; ni < 8; ni++)
#pragma unroll
            for (int r = 0; r < 4; r++) acc[mi][ni][r] = 0.f;

    auto loadTile = [&](int t, int st) {
        const __half* Ap; const __half* Bp; int Kc, k0;
        if (t < nt1) { Ap = A;  Bp = B;  Kc = Kd;  k0 = t << 5; }
        else         { Ap = A2; Bp = B2; Kc = Kd2; k0 = (t - nt1) << 5; }
#pragma unroll
        for (int it = 0; it < 2; it++) {
            int idx = tid + it * 256;
            int rr = idx >> 2, part = idx & 3;
            int gr = row0 + rr;
            uint32_t dst = (uint32_t)__cvta_generic_to_shared(&As[st][rr * 20 + part * 4]);
            cpa16(dst, Ap + (size_t)gr * Kc + k0 + part * 8, gr < M ? 16 : 0);
        }
#pragma unroll
        for (int it = 0; it < 2; it++) {
            int idx = tid + it * 256;
            int rr = idx >> 2, part = idx & 3;
            uint32_t dst = (uint32_t)__cvta_generic_to_shared(&Bs[st][rr * 20 + part * 4]);
            cpa16(dst, Bp + (size_t)(col0 + rr) * Kc + k0 + part * 8, 16);
        }
    };

    loadTile(0, 0);
    cpa_commit();

    for (int t = 0; t < nt; t++) {
        if (t + 1 < nt) loadTile(t + 1, (t + 1) & 1);
        cpa_commit();
        cpa_wait1();
        __syncthreads();

        const int st = t & 1;
        const uint32_t aST = asb + st * 2560 * 4;
        const uint32_t bST = bsb + st * 2560 * 4;
#pragma unroll
        for (int kk = 0; kk < 2; kk++) {
            uint32_t a[2][4], b[8][2];
#pragma unroll
            for (int mi = 0; mi < 2; mi++) {
                int mr = wm * 32 + mi * 16;
                ldsm4(a[mi], aST + ((mr + aRow) * 20 + kk * 8 + aCol) * 4);
            }
#pragma unroll
            for (int np = 0; np < 4; np++) {
                uint32_t bb[4];
                int nr = wn * 64 + np * 16;
                ldsm4(bb, bST + ((nr + bRow) * 20 + kk * 8 + bCol) * 4);
                b[np * 2][0]     = bb[0]; b[np * 2][1]     = bb[1];
                b[np * 2 + 1][0] = bb[2]; b[np * 2 + 1][1] = bb[3];
            }
#pragma unroll
            for (int mi = 0; mi < 2; mi++)
#pragma unroll
                for (int ni = 0; ni < 8; ni++)
                    mma16h(acc[mi][ni], a[mi], b[ni]);
        }
        __syncthreads();
    }

    float cs[8][2], cq[8][2];
    if (BN) {
#pragma unroll
        for (int ni = 0; ni < 8; ni++) {
            cs[ni][0] = cs[ni][1] = 0.f;
            cq[ni][0] = cq[ni][1] = 0.f;
        }
    }

#pragma unroll
    for (int mi = 0; mi < 2; mi++) {
#pragma unroll
        for (int half_ = 0; half_ < 2; half_++) {
            int r = row0 + wm * 32 + mi * 16 + gid + half_ * 8;
            if (r >= M) continue;
#pragma unroll
            for (int ni = 0; ni < 8; ni++) {
                int cI = col0 + wn * 64 + ni * 8 + tig * 2;
                float v0 = acc[mi][ni][half_ * 2 + 0];
                float v1 = acc[mi][ni][half_ * 2 + 1];
                if (bias) { v0 += bias[cI]; v1 += bias[cI + 1]; }
                if (RELU_) { v0 = fmaxf(v0, 0.f); v1 = fmaxf(v1, 0.f); }
                if (OUTH) {
                    __half2* cp = (__half2*)((__half*)ga.Cm + (size_t)r * Nm + cI);
                    *cp = __floats2half2_rn(v0, v1);
                } else {
                    float* cp = (float*)ga.Cm + (size_t)r * Nm + cI;
                    cp[0] = v0; cp[1] = v1;
                }
                if (BN) {
                    cs[ni][0] += v0; cq[ni][0] += v0 * v0;
                    cs[ni][1] += v1; cq[ni][1] += v1 * v1;
                }
            }
        }
    }

    if (BN) {
#pragma unroll
        for (int off = 16; off >= 4; off >>= 1) {
#pragma unroll
            for (int ni = 0; ni < 8; ni++) {
#pragma unroll
                for (int sub = 0; sub < 2; sub++) {
                    cs[ni][sub] += __shfl_down_sync(0xffffffffu, cs[ni][sub], off);
                    cq[ni][sub] += __shfl_down_sync(0xffffffffu, cq[ni][sub], off);
                }
            }
        }
        float* bnb = (float*)As;
        if (gid == 0) {
#pragma unroll
            for (int ni = 0; ni < 8; ni++)
#pragma unroll
                for (int sub = 0; sub < 2; sub++) {
                    int slot = (((wid << 2) | tig) * 8 + ni) * 4 + sub * 2;
                    bnb[slot]     = cs[ni][sub];
                    bnb[slot + 1] = cq[ni][sub];
                }
        }
        __syncthreads();
        int colL = tid >> 1, stat = tid & 1;
        int wn_ = colL >> 6, r_ = colL & 63;
        int ni_ = r_ >> 3, q_ = r_ & 7, tig_ = q_ >> 1, sub_ = q_ & 1;
        float v = 0.f;
#pragma unroll
        for (int wm_ = 0; wm_ < 4; wm_++) {
            int wid_ = wn_ * 4 + wm_;
            v += bnb[(((wid_ << 2) | tig_) * 8 + ni_) * 4 + sub_ * 2 + stat];
        }
        atomicAdd(stat ? &d_bnq[col0 + colL] : &d_bns[col0 + colL], v);
    }
}

// ---------------- fused LSTM step (FP16): GEMM + cell + attention dot ----
__global__ __launch_bounds__(256) void tlstm(
    const __half* __restrict__ xf, const __half* __restrict__ xb,
    const float* __restrict__ attw, int K2, int s)
{
    extern __shared__ uint32_t sraw[];   // 10240 words = 40960 B
    float* gbuf = (float*)sraw;          // epilogue: [64][133]

    const int dir  = blockIdx.z;
    const int c0   = blockIdx.x * 32;
    const int row0 = blockIdx.y * 128;
    const int pb   = s & 1;

    const __half* A  = dir ? xb : xf;
    const __half* B  = d_wihh + (size_t)dir * H4 * C;
    const __half* A2 = d_lhh[pb][dir];
    const __half* B2 = d_whhh + (size_t)dir * H4 * H;

    const int tid  = threadIdx.x;
    const int lane = tid & 31;
    const int wid  = tid >> 5;
    const int wm   = wid & 3;
    const int wn   = wid >> 2;
    const int gid  = lane >> 2;
    const int tig  = lane & 3;

    const int nt1 = C >> 5;              // 4
    const int nt  = nt1 + (K2 >> 5);     // 4 or 12

    const int aRow = (lane & 7) + ((lane >> 3) & 1) * 8;
    const int aCol = (lane >> 4) * 4;
    const int bRow = (lane & 7) + (lane >> 4) * 8;
    const int bCol = ((lane >> 3) & 1) * 4;
    const uint32_t sbase = (uint32_t)__cvta_generic_to_shared(sraw);

    float acc[2][8][4];
#pragma unroll
    for (int mi = 0; mi < 2; mi++)
#pragma unroll
        for (int ni = 0; ni < 8; ni++)
#pragma unroll
            for (int r = 0; r < 4; r++) acc[mi][ni][r] = 0.f;

    auto loadTile = [&](int t, int st) {
        const __half* Ap; const __half* Bp; int Kc, k0;
        if (t < nt1) { Ap = A;  Bp = B;  Kc = C; k0 = t << 5; }
        else         { Ap = A2; Bp = B2; Kc = H; k0 = (t - nt1) << 5; }
        uint32_t* Asb = sraw + st * 2560;
        uint32_t* Bsb = sraw + 5120 + st * 2560;
#pragma unroll
        for (int it = 0; it < 2; it++) {
            int idx = tid + it * 256;
            int rr = idx >> 2, part = idx & 3;
            int gr = row0 + rr;
            uint32_t dst = (uint32_t)__cvta_generic_to_shared(&Asb[rr * 20 + part * 4]);
            cpa16(dst, Ap + (size_t)gr * Kc + k0 + part * 8, gr < NN ? 16 : 0);
        }
#pragma unroll
        for (int it = 0; it < 2; it++) {
            int idx = tid + it * 256;
            int rr = idx >> 2, part = idx & 3;
            int brow = ((rr >> 5) << 8) + c0 + (rr & 31);   // gate*256 + c0 + j'
            uint32_t dst = (uint32_t)__cvta_generic_to_shared(&Bsb[rr * 20 + part * 4]);
            cpa16(dst, Bp + (size_t)brow * Kc + k0 + part * 8, 16);
        }
    };

    loadTile(0, 0);
    cpa_commit();

    for (int t = 0; t < nt; t++) {
        if (t + 1 < nt) loadTile(t + 1, (t + 1) & 1);
        cpa_commit();
        cpa_wait1();
        __syncthreads();

        const int st = t & 1;
        const uint32_t aST = sbase + st * 2560 * 4;
        const uint32_t bST = sbase + (5120 + st * 2560) * 4;
#pragma unroll
        for (int kk = 0; kk < 2; kk++) {
            uint32_t a[2][4], b[8][2];
#pragma unroll
            for (int mi = 0; mi < 2; mi++) {
                int mr = wm * 32 + mi * 16;
                ldsm4(a[mi], aST + ((mr + aRow) * 20 + kk * 8 + aCol) * 4);
            }
#pragma unroll
            for (int np = 0; np < 4; np++) {
                uint32_t bb[4];
                int nr = wn * 64 + np * 16;
                ldsm4(bb, bST + ((nr + bRow) * 20 + kk * 8 + bCol) * 4);
                b[np * 2][0]     = bb[0]; b[np * 2][1]     = bb[1];
                b[np * 2 + 1][0] = bb[2]; b[np * 2 + 1][1] = bb[3];
            }
#pragma unroll
            for (int mi = 0; mi < 2; mi++)
#pragma unroll
                for (int ni = 0; ni < 8; ni++)
                    mma16h(acc[mi][ni], a[mi], b[ni]);
        }
        __syncthreads();
    }

    // ---- fused epilogue: two 64-row passes through smem ----
    const float* bs = d_bsum + (size_t)dir * H4;
    float* lc   = d_lc[dir];
    __half* lhw = d_lhh[1 - pb][dir];
    const int t_idx = dir ? (4 - s) : s;
    float* aout = (dir ? d_ab : d_af) + t_idx * NN;

#pragma unroll
    for (int p = 0; p < 2; p++) {
        __syncthreads();
        if ((wm >> 1) == p) {
#pragma unroll
            for (int mi = 0; mi < 2; mi++)
#pragma unroll
                for (int half_ = 0; half_ < 2; half_++) {
                    int rloc = (wm & 1) * 32 + mi * 16 + gid + half_ * 8;
#pragma unroll
                    for (int ni = 0; ni < 8; ni++) {
                        int col = wn * 64 + ni * 8 + tig * 2;
                        gbuf[rloc * 133 + col]     = acc[mi][ni][half_ * 2 + 0];
                        gbuf[rloc * 133 + col + 1] = acc[mi][ni][half_ * 2 + 1];
                    }
                }
        }
        __syncthreads();

        int rr = tid >> 2;                 // 0..63
        int n  = row0 + p * 64 + rr;
        bool valid = n < NN;
        float part = 0.f;
        if (valid) {
            int jb = (tid & 3) * 8;
#pragma unroll
            for (int q = 0; q < 8; q++) {
                int jl = jb + q;           // 0..31
                int j  = c0 + jl;          // 0..255
                float gi = gbuf[rr * 133 +  0 + jl] + bs[0 * H + j];
                float gf = gbuf[rr * 133 + 32 + jl] + bs[1 * H + j];
                float gg = gbuf[rr * 133 + 64 + jl] + bs[2 * H + j];
                float go = gbuf[rr * 133 + 96 + jl] + bs[3 * H + j];
                size_t ix = (size_t)n * H + j;
                float cprev = (K2 > 0) ? lc[ix] : 0.f;
                float cc = sigf(gf) * cprev + sigf(gi) * tanhfast(gg);
                lc[ix] = cc;
                float hh = sigf(go) * tanhfast(cc);
                lhw[ix] = __float2half_rn(hh);
                part = fmaf(hh, attw[dir * H + j], part);
            }
        }
        part += __shfl_down_sync(0xffffffffu, part, 2);
        part += __shfl_down_sync(0xffffffffu, part, 1);
        if (valid && (tid & 3) == 0) atomicAdd(&aout[n], part);
    }
}

// ---------------- small kernels ----------------
__global__ void k_zero(float* p, int n) {
    int i = blockIdx.x * blockDim.x + threadIdx.x;
    if (i < n) p[i] = 0.f;
}
__global__ void k_zero02(float* p0, float* p1, int n) {
    int i = blockIdx.x * blockDim.x + threadIdx.x;
    if (i < n) { p0[i] = 0.f; p1[i] = 0.f; }
}
__global__ void k_zeroi(int* p, int n) {
    int i = blockIdx.x * blockDim.x + threadIdx.x;
    if (i < n) p[i] = 0;
}
__global__ void k_zerog() {   // zero hg + cnt in one launch
    int i = blockIdx.x * blockDim.x + threadIdx.x;
    if (i < NB * C) d_hg[i] = 0.f;
    if (i < NB)     d_cnt[i] = 0.f;
}

__global__ void k_degi(const int* __restrict__ dst) {
    int e = blockIdx.x * blockDim.x + threadIdx.x;
    if (e < NE) atomicAdd(&d_indeg[dst[e]], 1);
}

__global__ void k_scan() {
    const int T = 1024;
    __shared__ int buf[T];
    __shared__ int carry_s;
    int t = threadIdx.x;
    if (t == 0) carry_s = 0;
    __syncthreads();
    for (int base = 0; base < NN; base += T) {
        int v = (base + t < NN) ? d_indeg[base + t] : 0;
        buf[t] = v;
        __syncthreads();
        for (int off = 1; off < T; off <<= 1) {
            int add = (t >= off) ? buf[t - off] : 0;
            __syncthreads();
            buf[t] += add;
            __syncthreads();
        }
        int carry = carry_s;
        __syncthreads();
        if (base + t < NN) {
            d_rowptr[base + t] = carry + buf[t] - v;
            d_curp[base + t]   = carry + buf[t] - v;
        }
        if (t == T - 1) carry_s = carry + buf[t];
        __syncthreads();
    }
    if (t == 0) d_rowptr[NN] = carry_s;
}

__global__ void k_place(const int* __restrict__ src, const int* __restrict__ dst) {
    int e = blockIdx.x * blockDim.x + threadIdx.x;
    if (e >= NE) return;
    int slot = atomicAdd(&d_curp[dst[e]], 1);
    d_eid[slot]  = e;
    d_esrc[slot] = src[e];
}

// gT(half): [l][c][k*128+f] from g; rootT(half): [l][c][f]
__global__ void k_gt_h(const float* __restrict__ g, const float* __restrict__ root) {
    int i = blockIdx.x * blockDim.x + threadIdx.x;
    if (i < LL * C * KG * C) {
        int l   = i >> 17;
        int rem = i & 131071;
        int cR  = rem >> 10;
        int kf  = rem & 1023;
        int k = kf >> 7, f = kf & 127;
        d_gth[i] = __float2half_rn(g[((size_t)(l * 128 + f)) * 1024 + k * 128 + cR]);
    }
    if (i < LL * C * C) {
        int l = i >> 14;
        int c = (i >> 7) & 127;
        int f = i & 127;
        d_rooth[i] = __float2half_rn(root[((size_t)(l * 128 + f)) * 128 + c]);
    }
}

// half LSTM/MLP weights, fused biases, x->half
__global__ void k_prep(const float* __restrict__ wih, const float* __restrict__ whh,
                       const float* __restrict__ bih, const float* __restrict__ bhh,
                       const float* __restrict__ x,
                       const float* __restrict__ p1w, const float* __restrict__ p2w) {
    int i = blockIdx.x * blockDim.x + threadIdx.x;
    if (i < NN * C)       d_hlth[0][i] = __float2half_rn(x[i]);
    if (i < 2 * H4 * C)   d_wihh[i] = __float2half_rn(wih[i]);
    if (i < 2 * H4 * H)   d_whhh[i] = __float2half_rn(whh[i]);
    if (i < 2 * H4)       d_bsum[i] = bih[i] + bhh[i];
    if (i < NHID * C)  {
        int n = i / C, c = i % C;
        d_p1wh[i] = __float2half_rn(p1w[(size_t)c * NHID + n]);
    }
    if (i < NOUT * NHID) {
        int n = i / NHID, k = i % NHID;
        d_p2wh[i] = __float2half_rn(p2w[(size_t)k * NOUT + n]);
    }
}

// all-layer gaussian weights (half) in one launch
__global__ void k_ewall(const float* __restrict__ ea,
                        const float* __restrict__ mu,
                        const float* __restrict__ sg) {
    int e = blockIdx.x * blockDim.x + threadIdx.x;
    if (e >= NE) return;
    float a0 = ea[e * 2 + 0], a1 = ea[e * 2 + 1];
#pragma unroll
    for (int l = 0; l < LL; l++) {
        const float* mul = mu + l * KG * 2;
        const float* sgl = sg + l * KG * 2;
#pragma unroll
        for (int k = 0; k < KG; k++) {
            float dx = a0 - mul[k * 2 + 0];
            float dy = a1 - mul[k * 2 + 1];
            float s0 = sgl[k * 2 + 0], s1 = sgl[k * 2 + 1];
            float w = __expf(-0.5f * (__fdividef(dx * dx, 1e-15f + s0 * s0) +
                                      __fdividef(dy * dy, 1e-15f + s1 * s1)));
            d_ewh[l][(size_t)e * KG + k] = __float2half_rn(w);
        }
    }
}

// S accumulation (warp per node); block 0 also zeroes BN accumulators
__global__ void k_sacc(const __half* __restrict__ hinh, int layer) {
    if (blockIdx.x == 0 && threadIdx.x < C) {
        d_bns[threadIdx.x] = 0.f;
        d_bnq[threadIdx.x] = 0.f;
    }
    int n = (blockIdx.x * blockDim.x + threadIdx.x) >> 5;
    int l = threadIdx.x & 31;
    if (n >= NN) return;
    const __half* ewl = d_ewh[layer];
    const __half2* h2b = (const __half2*)hinh;
    int beg = d_rowptr[n], end = d_rowptr[n + 1];
    float acc[KG][4];
#pragma unroll
    for (int k = 0; k < KG; k++)
#pragma unroll
        for (int q = 0; q < 4; q++) acc[k][q] = 0.f;

    for (int p = beg; p < end; p++) {
        int e = d_eid[p], s = d_esrc[p];
        float wv = (l < KG) ? __half2float(ewl[(size_t)e * KG + l]) : 0.f;
        const __half2* hr2 = h2b + (size_t)s * 64;
        float2 f0 = __half22float2(hr2[l]);
        float2 f1 = __half22float2(hr2[l + 32]);
#pragma unroll
        for (int k = 0; k < KG; k++) {
            float wk = __shfl_sync(0xffffffffu, wv, k);
            acc[k][0] = fmaf(wk, f0.x, acc[k][0]);
            acc[k][1] = fmaf(wk, f0.y, acc[k][1]);
            acc[k][2] = fmaf(wk, f1.x, acc[k][2]);
            acc[k][3] = fmaf(wk, f1.y, acc[k][3]);
        }
    }
    float inv = __fdividef(1.f, fmaxf((float)(end - beg), 1.f));
    __half2* Sp2 = (__half2*)&d_Sh[(size_t)n * (KG * C)];
#pragma unroll
    for (int k = 0; k < KG; k++) {
        Sp2[k * 64 + l]      = __floats2half2_rn(acc[k][0] * inv, acc[k][1] * inv);
        Sp2[k * 64 + 32 + l] = __floats2half2_rn(acc[k][2] * inv, acc[k][3] * inv);
    }
}

// BN apply: reads half GEMM output, writes half activation copy
__global__ void k_bnapp(const float* __restrict__ gamma,
                        const float* __restrict__ beta,
                        __half* __restrict__ out_hlt, int relu) {
    int i = blockIdx.x * blockDim.x + threadIdx.x;
    if (i >= NN * C) return;
    int c = i % C;
    float mean = d_bns[c] / (float)NN;
    float var  = d_bnq[c] / (float)NN - mean * mean;
    float v = (__half2float(d_hh[i]) - mean) * rsqrtf(var + 1e-5f) * gamma[c] + beta[c];
    if (relu) v = fmaxf(v, 0.f);
    out_hlt[i] = __float2half_rn(v);
}

// fused: attention softmax + weighted node rep + pool + graph count
__global__ void k_nreppool(const float* __restrict__ x,
                           const int* __restrict__ batch) {
    int n = blockIdx.x;
    int c = threadIdx.x;
    __shared__ float p[5];
    __shared__ int gidx;
    if (c == 0) {
        float a[5], m = -1e30f;
#pragma unroll
        for (int t = 0; t < 5; t++) {
            a[t] = d_af[t * NN + n] + d_ab[t * NN + n];
            m = fmaxf(m, a[t]);
        }
        float s = 0.f;
#pragma unroll
        for (int t = 0; t < 5; t++) { a[t] = __expf(a[t] - m); s += a[t]; }
        float invs = __fdividef(1.f, s);
#pragma unroll
        for (int t = 0; t < 5; t++) p[t] = a[t] * invs;
        gidx = batch[n];
        atomicAdd(&d_cnt[gidx], 1.f);
    }
    __syncthreads();
    float r = p[0] * x[(size_t)n * C + c];
#pragma unroll
    for (int t = 1; t < 5; t++)
        r = fmaf(p[t], __half2float(d_hlth[t][(size_t)n * C + c]), r);
    atomicAdd(&d_hg[(size_t)gidx * C + c], r);
}

__global__ void k_pdiv() {
    int i = blockIdx.x * blockDim.x + threadIdx.x;
    if (i >= NB * C) return;
    float v = d_hg[i] / fmaxf(d_cnt[i / C], 1.f);
    d_hgh[i] = __float2half_rn(v);
}

__global__ void k_ln(const float* __restrict__ g, const float* __restrict__ b,
                     float* __restrict__ out) {
    int row = blockIdx.x, t = threadIdx.x;
    __shared__ float sm[NOUT];
    float v = d_z2[(size_t)row * NOUT + t];
    sm[t] = v;
    __syncthreads();
    for (int o = NOUT / 2; o > 0; o >>= 1) {
        if (t < o) sm[t] += sm[t + o];
        __syncthreads();
    }
    float mean = sm[0] / (float)NOUT;
    __syncthreads();
    float dv = v - mean;
    sm[t] = dv * dv;
    __syncthreads();
    for (int o = NOUT / 2; o > 0; o >>= 1) {
        if (t < o) sm[t] += sm[t + o];
        __syncthreads();
    }
    float var = sm[0] / (float)NOUT;
    out[(size_t)row * NOUT + t] = dv * rsqrtf(var + 1e-5f) * g[t] + b[t];
}

// ---------------- host ----------------
static float* symf(const void* s) {
    void* p = nullptr;
    cudaGetSymbolAddress(&p, s);
    return (float*)p;
}
static __half* symh(const void* s) {
    void* p = nullptr;
    cudaGetSymbolAddress(&p, s);
    return (__half*)p;
}
static int* symi(const void* s) {
    void* p = nullptr;
    cudaGetSymbolAddress(&p, s);
    return (int*)p;
}

extern "C" void kernel_launch(void* const* d_in, const int* in_sizes, int n_in,
                              void* d_out, int out_size) {
    const float* x     = (const float*)d_in[0];
    const int*   ei    = (const int*)d_in[1];
    const int*   src   = ei;
    const int*   dst   = ei + NE;
    const float* ea    = (const float*)d_in[2];
    const int*   batch = (const int*)d_in[3];
    const float* g     = (const float*)d_in[4];
    const float* root  = (const float*)d_in[5];
    const float* bias  = (const float*)d_in[6];
    const float* mu    = (const float*)d_in[7];
    const float* sigma = (const float*)d_in[8];
    const float* bng   = (const float*)d_in[9];
    const float* bnb   = (const float*)d_in[10];
    const float* wih   = (const float*)d_in[11];
    const float* whh   = (const float*)d_in[12];
    const float* bih   = (const float*)d_in[13];
    const float* bhh   = (const float*)d_in[14];
    const float* attw  = (const float*)d_in[15];
    const float* p1w   = (const float*)d_in[17];
    const float* p1b   = (const float*)d_in[18];
    const float* p2w   = (const float*)d_in[19];
    const float* p2b   = (const float*)d_in[20];
    const float* lng   = (const float*)d_in[21];
    const float* lnb   = (const float*)d_in[22];
    float* out = (float*)d_out;

    __half* hh    = symh(d_hh);
    __half* hlth  = symh(d_hlth);
    __half* Sh    = symh(d_Sh);
    __half* gth   = symh(d_gth);
    __half* rooth = symh(d_rooth);
    float*  af    = symf(d_af);
    float*  ab    = symf(d_ab);
    __half* hgh   = symh(d_hgh);
    __half* z1h   = symh(d_z1h);
    float*  z2    = symf(d_z2);
    __half* p1wh  = symh(d_p1wh);
    __half* p2wh  = symh(d_p2wh);
    int* indeg    = symi(d_indeg);

    const int TPB = 256;
    const dim3 blk(TPB);
    const int gridNC = (NN * C + TPB - 1) / TPB;
    const int rowsN  = (NN + 127) / 128;
    const int TLSTM_SMEM = 40960;

    static int smem_set = 0;
    if (!smem_set) {
        cudaFuncSetAttribute(tlstm, cudaFuncAttributeMaxDynamicSharedMemorySize,
                             TLSTM_SMEM);
        smem_set = 1;
    }

    // -------- CSR build + weight prep --------
    k_zeroi<<<(NN + TPB - 1) / TPB, blk>>>(indeg, NN);
    k_degi<<<(NE + TPB - 1) / TPB, blk>>>(dst);
    k_scan<<<1, 1024>>>();
    k_place<<<(NE + TPB - 1) / TPB, blk>>>(src, dst);
    k_gt_h<<<(LL * C * KG * C + TPB - 1) / TPB, blk>>>(g, root);
    k_prep<<<(NN * C + TPB - 1) / TPB, blk>>>(wih, whh, bih, bhh, x, p1w, p2w);
    k_ewall<<<(NE + TPB - 1) / TPB, blk>>>(ea, mu, sigma);

    // -------- GMMConv layers (BN stats fused in GEMM epilogue) --------
    for (int i = 0; i < LL; i++) {
        k_sacc<<<(NN * 32 + TPB - 1) / TPB, blk>>>(hlth + (size_t)i * NN * C, i);
        GH gl = {Sh, gth + (size_t)i * C * KG * C,
                 hlth + (size_t)i * NN * C, rooth + (size_t)i * C * C,
                 hh, bias + i * C, KG * C, C};
        tgemm_h<false, true, true><<<dim3(1, rowsN), blk>>>(gl, NN, C);
        k_bnapp<<<gridNC, blk>>>(bng + i * C, bnb + i * C,
                                 hlth + (size_t)(i + 1) * NN * C,
                                 (i < LL - 1) ? 1 : 0);
    }

    // -------- bidirectional LSTM JumpingKnowledge (fused fp16 GEMM+cell) --
    k_zero02<<<(5 * NN + TPB - 1) / TPB, blk>>>(af, ab, 5 * NN);
    for (int s = 0; s < 5; s++) {
        int tf = s, tb = 4 - s;
        const __half* xf = hlth + (size_t)tf * NN * C;
        const __half* xb = hlth + (size_t)tb * NN * C;
        tlstm<<<dim3(H / 32, rowsN, 2), blk, TLSTM_SMEM>>>(xf, xb, attw,
                                                           (s > 0) ? H : 0, s);
    }

    // global mean pool (fused attention mix + scatter + count)
    k_zerog<<<(NB * C + TPB - 1) / TPB, blk>>>();
    k_nreppool<<<NN, C>>>(x, batch);
    k_pdiv<<<(NB * C + TPB - 1) / TPB, blk>>>();

    // MLP + LayerNorm (fp16 GEMMs)
    GH gp1 = {hgh, p1wh, nullptr, nullptr, z1h, p1b, C, 0};
    tgemm_h<true, true, false><<<dim3(NHID / 128, NB / 128), blk>>>(gp1, NB, NHID);
    GH gp2 = {z1h, p2wh, nullptr, nullptr, z2, p2b, NHID, 0};
    tgemm_h<false, false, false><<<dim3(NOUT / 128, NB / 128), blk>>>(gp2, NB, NOUT);
    k_ln<<<NB, NOUT>>>(lng, lnb, out);
}

// round 15
// speedup vs baseline: 1.9280x; 1.0403x over previous
#include <cuda_runtime.h>
#include <cuda_fp16.h>
#include <math.h>
#include <stdint.h>

// ---------------- problem constants ----------------
namespace {
constexpr int NN   = 30000;   // nodes
constexpr int NE   = 480000;  // edges
constexpr int C    = 128;     // channels (= F)
constexpr int KG   = 8;       // gaussians
constexpr int LL   = 4;       // layers
constexpr int H    = 256;     // LSTM hidden
constexpr int H4   = 1024;    // 4*H
constexpr int NHID = 512;
constexpr int NOUT = 256;
constexpr int NB   = 1024;    // graphs
}

// ---------------- scratch (device globals; no allocations allowed) -------
__device__ __align__(256) __half d_hh[NN * C];           // GMM GEMM out (half)
__device__ __align__(256) __half d_hlth[5][NN * C];      // half x,h1..h4
__device__ __align__(256) __half d_Sh[NN * KG * C];
__device__ __align__(256) __half d_gth[LL * C * KG * C]; // [l][c][k*128+f]
__device__ __align__(256) __half d_rooth[LL * C * C];    // [l][c][f]
__device__ __align__(256) __half d_ewh[LL][NE * KG];     // CSR-slot ordered!
__device__ __align__(256) float  d_bns[C];
__device__ __align__(256) float  d_bnq[C];
__device__ __align__(256) __half d_lhh[2][2][NN * H];    // [pingpong][dir]
__device__ __align__(256) float  d_lc[2][NN * H];
__device__ __align__(256) float  d_af[5 * NN];
__device__ __align__(256) float  d_ab[5 * NN];
__device__ __align__(256) float  d_cnt[NB];
__device__ __align__(256) float  d_hg[NB * C];
__device__ __align__(256) __half d_hgh[NB * C];
__device__ __align__(256) __half d_z1h[NB * NHID];
__device__ __align__(256) float  d_z2[NB * NOUT];
// half LSTM weights ([n][k] layout) + fused biases, half MLP weights
__device__ __align__(256) __half d_wihh[2 * H4 * C];
__device__ __align__(256) __half d_whhh[2 * H4 * H];
__device__ __align__(256) float  d_bsum[2 * H4];
__device__ __align__(256) __half d_p1wh[NHID * C];       // [n][k]
__device__ __align__(256) __half d_p2wh[NOUT * NHID];    // [n][k]
// CSR scratch
__device__ __align__(256) int d_indeg[NN];
__device__ __align__(256) int d_rowptr[NN + 1];
__device__ __align__(256) int d_curp[NN];
__device__ __align__(256) int d_eid[NE];
__device__ __align__(256) int d_esrc[NE];

// ---------------- helpers ----------------
__device__ __forceinline__ void mma16h(float* c, const uint32_t* a, const uint32_t* b) {
    asm volatile(
        "mma.sync.aligned.m16n8k16.row.col.f32.f16.f16.f32 "
        "{%0,%1,%2,%3}, {%4,%5,%6,%7}, {%8,%9}, {%0,%1,%2,%3};"
        : "+f"(c[0]), "+f"(c[1]), "+f"(c[2]), "+f"(c[3])
        : "r"(a[0]), "r"(a[1]), "r"(a[2]), "r"(a[3]), "r"(b[0]), "r"(b[1]));
}
__device__ __forceinline__ void ldsm4(uint32_t* r, uint32_t saddr) {
    asm volatile("ldmatrix.sync.aligned.m8n8.x4.shared.b16 {%0,%1,%2,%3}, [%4];"
                 : "=r"(r[0]), "=r"(r[1]), "=r"(r[2]), "=r"(r[3])
                 : "r"(saddr));
}
__device__ __forceinline__ void cpa16(uint32_t sdst, const void* gsrc, int srcsz) {
    asm volatile("cp.async.ca.shared.global [%0], [%1], 16, %2;\n"
                 :: "r"(sdst), "l"(gsrc), "r"(srcsz));
}
__device__ __forceinline__ void cpa_commit() { asm volatile("cp.async.commit_group;\n"); }
__device__ __forceinline__ void cpa_wait1()  { asm volatile("cp.async.wait_group 1;\n"); }
__device__ __forceinline__ float sigf(float x) {
    return __fdividef(1.f, 1.f + __expf(-x));
}
__device__ __forceinline__ float tanhfast(float x) {
    float t = __expf(-2.f * fabsf(x));
    float r = __fdividef(1.f - t, 1.f + t);
    return copysignf(r, x);
}

// ---------------- FP16 tensor GEMM (cp.async 2-stage, dual-K, TB form) ----
struct GH {
    const __half* A;
    const __half* B;
    const __half* A2;
    const __half* B2;
    void* Cm;            // float* or __half* (OUTH)
    const float* bias;   // nullptr -> none
    int Kd;
    int Kd2;
};

template <bool RELU_, bool OUTH, bool BN>
__global__ __launch_bounds__(256) void tgemm_h(GH ga, int M, int Nm)
{
    __shared__ uint32_t As[2][2560];   // [row][20]
    __shared__ uint32_t Bs[2][2560];

    const __half* __restrict__ A  = ga.A;
    const __half* __restrict__ B  = ga.B;
    const __half* __restrict__ A2 = ga.A2;
    const __half* __restrict__ B2 = ga.B2;
    const float* __restrict__ bias = ga.bias;
    const int Kd = ga.Kd, Kd2 = ga.Kd2;

    const int tid  = threadIdx.x;
    const int lane = tid & 31;
    const int wid  = tid >> 5;
    const int wm   = wid & 3;
    const int wn   = wid >> 2;
    const int gid  = lane >> 2;
    const int tig  = lane & 3;
    const int row0 = blockIdx.y * 128, col0 = blockIdx.x * 128;

    const int nt1 = Kd >> 5;
    const int nt  = nt1 + (Kd2 >> 5);

    const int aRow = (lane & 7) + ((lane >> 3) & 1) * 8;
    const int aCol = (lane >> 4) * 4;
    const int bRow = (lane & 7) + (lane >> 4) * 8;
    const int bCol = ((lane >> 3) & 1) * 4;
    const uint32_t asb = (uint32_t)__cvta_generic_to_shared(&As[0][0]);
    const uint32_t bsb = (uint32_t)__cvta_generic_to_shared(&Bs[0][0]);

    float acc[2][8][4];
#pragma unroll
    for (int mi = 0; mi < 2; mi++)
#pragma unroll
        for (int ni = 0; ni < 8; ni++)
#pragma unroll
            for (int r = 0; r < 4; r++) acc[mi][ni][r] = 0.f;

    auto loadTile = [&](int t, int st) {
        const __half* Ap; const __half* Bp; int Kc, k0;
        if (t < nt1) { Ap = A;  Bp = B;  Kc = Kd;  k0 = t << 5; }
        else         { Ap = A2; Bp = B2; Kc = Kd2; k0 = (t - nt1) << 5; }
#pragma unroll
        for (int it = 0; it < 2; it++) {
            int idx = tid + it * 256;
            int rr = idx >> 2, part = idx & 3;
            int gr = row0 + rr;
            uint32_t dst = (uint32_t)__cvta_generic_to_shared(&As[st][rr * 20 + part * 4]);
            cpa16(dst, Ap + (size_t)gr * Kc + k0 + part * 8, gr < M ? 16 : 0);
        }
#pragma unroll
        for (int it = 0; it < 2; it++) {
            int idx = tid + it * 256;
            int rr = idx >> 2, part = idx & 3;
            uint32_t dst = (uint32_t)__cvta_generic_to_shared(&Bs[st][rr * 20 + part * 4]);
            cpa16(dst, Bp + (size_t)(col0 + rr) * Kc + k0 + part * 8, 16);
        }
    };

    loadTile(0, 0);
    cpa_commit();

    for (int t = 0; t < nt; t++) {
        if (t + 1 < nt) loadTile(t + 1, (t + 1) & 1);
        cpa_commit();
        cpa_wait1();
        __syncthreads();

        const int st = t & 1;
        const uint32_t aST = asb + st * 2560 * 4;
        const uint32_t bST = bsb + st * 2560 * 4;
#pragma unroll
        for (int kk = 0; kk < 2; kk++) {
            uint32_t a[2][4], b[8][2];
#pragma unroll
            for (int mi = 0; mi < 2; mi++) {
                int mr = wm * 32 + mi * 16;
                ldsm4(a[mi], aST + ((mr + aRow) * 20 + kk * 8 + aCol) * 4);
            }
#pragma unroll
            for (int np = 0; np < 4; np++) {
                uint32_t bb[4];
                int nr = wn * 64 + np * 16;
                ldsm4(bb, bST + ((nr + bRow) * 20 + kk * 8 + bCol) * 4);
                b[np * 2][0]     = bb[0]; b[np * 2][1]     = bb[1];
                b[np * 2 + 1][0] = bb[2]; b[np * 2 + 1][1] = bb[3];
            }
#pragma unroll
            for (int mi = 0; mi < 2; mi++)
#pragma unroll
                for (int ni = 0; ni < 8; ni++)
                    mma16h(acc[mi][ni], a[mi], b[ni]);
        }
        __syncthreads();
    }

    float cs[8][2], cq[8][2];
    if (BN) {
#pragma unroll
        for (int ni = 0; ni < 8; ni++) {
            cs[ni][0] = cs[ni][1] = 0.f;
            cq[ni][0] = cq[ni][1] = 0.f;
        }
    }

#pragma unroll
    for (int mi = 0; mi < 2; mi++) {
#pragma unroll
        for (int half_ = 0; half_ < 2; half_++) {
            int r = row0 + wm * 32 + mi * 16 + gid + half_ * 8;
            if (r >= M) continue;
#pragma unroll
            for (int ni = 0; ni < 8; ni++) {
                int cI = col0 + wn * 64 + ni * 8 + tig * 2;
                float v0 = acc[mi][ni][half_ * 2 + 0];
                float v1 = acc[mi][ni][half_ * 2 + 1];
                if (bias) { v0 += bias[cI]; v1 += bias[cI + 1]; }
                if (RELU_) { v0 = fmaxf(v0, 0.f); v1 = fmaxf(v1, 0.f); }
                if (OUTH) {
                    __half2* cp = (__half2*)((__half*)ga.Cm + (size_t)r * Nm + cI);
                    *cp = __floats2half2_rn(v0, v1);
                } else {
                    float* cp = (float*)ga.Cm + (size_t)r * Nm + cI;
                    cp[0] = v0; cp[1] = v1;
                }
                if (BN) {
                    cs[ni][0] += v0; cq[ni][0] += v0 * v0;
                    cs[ni][1] += v1; cq[ni][1] += v1 * v1;
                }
            }
        }
    }

    if (BN) {
#pragma unroll
        for (int off = 16; off >= 4; off >>= 1) {
#pragma unroll
            for (int ni = 0; ni < 8; ni++) {
#pragma unroll
                for (int sub = 0; sub < 2; sub++) {
                    cs[ni][sub] += __shfl_down_sync(0xffffffffu, cs[ni][sub], off);
                    cq[ni][sub] += __shfl_down_sync(0xffffffffu, cq[ni][sub], off);
                }
            }
        }
        float* bnb = (float*)As;
        if (gid == 0) {
#pragma unroll
            for (int ni = 0; ni < 8; ni++)
#pragma unroll
                for (int sub = 0; sub < 2; sub++) {
                    int slot = (((wid << 2) | tig) * 8 + ni) * 4 + sub * 2;
                    bnb[slot]     = cs[ni][sub];
                    bnb[slot + 1] = cq[ni][sub];
                }
        }
        __syncthreads();
        int colL = tid >> 1, stat = tid & 1;
        int wn_ = colL >> 6, r_ = colL & 63;
        int ni_ = r_ >> 3, q_ = r_ & 7, tig_ = q_ >> 1, sub_ = q_ & 1;
        float v = 0.f;
#pragma unroll
        for (int wm_ = 0; wm_ < 4; wm_++) {
            int wid_ = wn_ * 4 + wm_;
            v += bnb[(((wid_ << 2) | tig_) * 8 + ni_) * 4 + sub_ * 2 + stat];
        }
        atomicAdd(stat ? &d_bnq[col0 + colL] : &d_bns[col0 + colL], v);
    }
}

// ---------------- fused LSTM step (FP16): GEMM + cell + attention dot ----
__global__ __launch_bounds__(256) void tlstm(
    const __half* __restrict__ xf, const __half* __restrict__ xb,
    const float* __restrict__ attw, int K2, int s)
{
    extern __shared__ uint32_t sraw[];   // 10240 words = 40960 B
    float* gbuf = (float*)sraw;          // epilogue: [64][133]

    const int dir  = blockIdx.z;
    const int c0   = blockIdx.x * 32;
    const int row0 = blockIdx.y * 128;
    const int pb   = s & 1;

    const __half* A  = dir ? xb : xf;
    const __half* B  = d_wihh + (size_t)dir * H4 * C;
    const __half* A2 = d_lhh[pb][dir];
    const __half* B2 = d_whhh + (size_t)dir * H4 * H;

    const int tid  = threadIdx.x;
    const int lane = tid & 31;
    const int wid  = tid >> 5;
    const int wm   = wid & 3;
    const int wn   = wid >> 2;
    const int gid  = lane >> 2;
    const int tig  = lane & 3;

    const int nt1 = C >> 5;              // 4
    const int nt  = nt1 + (K2 >> 5);     // 4 or 12

    const int aRow = (lane & 7) + ((lane >> 3) & 1) * 8;
    const int aCol = (lane >> 4) * 4;
    const int bRow = (lane & 7) + (lane >> 4) * 8;
    const int bCol = ((lane >> 3) & 1) * 4;
    const uint32_t sbase = (uint32_t)__cvta_generic_to_shared(sraw);

    float acc[2][8][4];
#pragma unroll
    for (int mi = 0; mi < 2; mi++)
#pragma unroll
        for (int ni = 0; ni < 8; ni++)
#pragma unroll
            for (int r = 0; r < 4; r++) acc[mi][ni][r] = 0.f;

    auto loadTile = [&](int t, int st) {
        const __half* Ap; const __half* Bp; int Kc, k0;
        if (t < nt1) { Ap = A;  Bp = B;  Kc = C; k0 = t << 5; }
        else         { Ap = A2; Bp = B2; Kc = H; k0 = (t - nt1) << 5; }
        uint32_t* Asb = sraw + st * 2560;
        uint32_t* Bsb = sraw + 5120 + st * 2560;
#pragma unroll
        for (int it = 0; it < 2; it++) {
            int idx = tid + it * 256;
            int rr = idx >> 2, part = idx & 3;
            int gr = row0 + rr;
            uint32_t dst = (uint32_t)__cvta_generic_to_shared(&Asb[rr * 20 + part * 4]);
            cpa16(dst, Ap + (size_t)gr * Kc + k0 + part * 8, gr < NN ? 16 : 0);
        }
#pragma unroll
        for (int it = 0; it < 2; it++) {
            int idx = tid + it * 256;
            int rr = idx >> 2, part = idx & 3;
            int brow = ((rr >> 5) << 8) + c0 + (rr & 31);   // gate*256 + c0 + j'
            uint32_t dst = (uint32_t)__cvta_generic_to_shared(&Bsb[rr * 20 + part * 4]);
            cpa16(dst, Bp + (size_t)brow * Kc + k0 + part * 8, 16);
        }
    };

    loadTile(0, 0);
    cpa_commit();

    for (int t = 0; t < nt; t++) {
        if (t + 1 < nt) loadTile(t + 1, (t + 1) & 1);
        cpa_commit();
        cpa_wait1();
        __syncthreads();

        const int st = t & 1;
        const uint32_t aST = sbase + st * 2560 * 4;
        const uint32_t bST = sbase + (5120 + st * 2560) * 4;
#pragma unroll
        for (int kk = 0; kk < 2; kk++) {
            uint32_t a[2][4], b[8][2];
#pragma unroll
            for (int mi = 0; mi < 2; mi++) {
                int mr = wm * 32 + mi * 16;
                ldsm4(a[mi], aST + ((mr + aRow) * 20 + kk * 8 + aCol) * 4);
            }
#pragma unroll
            for (int np = 0; np < 4; np++) {
                uint32_t bb[4];
                int nr = wn * 64 + np * 16;
                ldsm4(bb, bST + ((nr + bRow) * 20 + kk * 8 + bCol) * 4);
                b[np * 2][0]     = bb[0]; b[np * 2][1]     = bb[1];
                b[np * 2 + 1][0] = bb[2]; b[np * 2 + 1][1] = bb[3];
            }
#pragma unroll
            for (int mi = 0; mi < 2; mi++)
#pragma unroll
                for (int ni = 0; ni < 8; ni++)
                    mma16h(acc[mi][ni], a[mi], b[ni]);
        }
        __syncthreads();
    }

    // ---- fused epilogue: two 64-row passes through smem ----
    const float* bs = d_bsum + (size_t)dir * H4;
    float* lc   = d_lc[dir];
    __half* lhw = d_lhh[1 - pb][dir];
    const int t_idx = dir ? (4 - s) : s;
    float* aout = (dir ? d_ab : d_af) + t_idx * NN;

#pragma unroll
    for (int p = 0; p < 2; p++) {
        __syncthreads();
        if ((wm >> 1) == p) {
#pragma unroll
            for (int mi = 0; mi < 2; mi++)
#pragma unroll
                for (int half_ = 0; half_ < 2; half_++) {
                    int rloc = (wm & 1) * 32 + mi * 16 + gid + half_ * 8;
#pragma unroll
                    for (int ni = 0; ni < 8; ni++) {
                        int col = wn * 64 + ni * 8 + tig * 2;
                        gbuf[rloc * 133 + col]     = acc[mi][ni][half_ * 2 + 0];
                        gbuf[rloc * 133 + col + 1] = acc[mi][ni][half_ * 2 + 1];
                    }
                }
        }
        __syncthreads();

        int rr = tid >> 2;                 // 0..63
        int n  = row0 + p * 64 + rr;
        bool valid = n < NN;
        float part = 0.f;
        if (valid) {
            int jb = (tid & 3) * 8;
#pragma unroll
            for (int q = 0; q < 8; q++) {
                int jl = jb + q;           // 0..31
                int j  = c0 + jl;          // 0..255
                float gi = gbuf[rr * 133 +  0 + jl] + bs[0 * H + j];
                float gf = gbuf[rr * 133 + 32 + jl] + bs[1 * H + j];
                float gg = gbuf[rr * 133 + 64 + jl] + bs[2 * H + j];
                float go = gbuf[rr * 133 + 96 + jl] + bs[3 * H + j];
                size_t ix = (size_t)n * H + j;
                float cprev = (K2 > 0) ? lc[ix] : 0.f;
                float cc = sigf(gf) * cprev + sigf(gi) * tanhfast(gg);
                lc[ix] = cc;
                float hh = sigf(go) * tanhfast(cc);
                lhw[ix] = __float2half_rn(hh);
                part = fmaf(hh, attw[dir * H + j], part);
            }
        }
        part += __shfl_down_sync(0xffffffffu, part, 2);
        part += __shfl_down_sync(0xffffffffu, part, 1);
        if (valid && (tid & 3) == 0) atomicAdd(&aout[n], part);
    }
}

// ---------------- small kernels ----------------
__global__ void k_zero02(float* p0, float* p1, int n) {
    int i = blockIdx.x * blockDim.x + threadIdx.x;
    if (i < n) { p0[i] = 0.f; p1[i] = 0.f; }
}
__global__ void k_zeroi(int* p, int n) {
    int i = blockIdx.x * blockDim.x + threadIdx.x;
    if (i < n) p[i] = 0;
}
__global__ void k_zerog() {   // zero hg + cnt in one launch
    int i = blockIdx.x * blockDim.x + threadIdx.x;
    if (i < NB * C) d_hg[i] = 0.f;
    if (i < NB)     d_cnt[i] = 0.f;
}

__global__ void k_degi(const int* __restrict__ dst) {
    int e = blockIdx.x * blockDim.x + threadIdx.x;
    if (e < NE) atomicAdd(&d_indeg[dst[e]], 1);
}

__global__ void k_scan() {
    const int T = 1024;
    __shared__ int buf[T];
    __shared__ int carry_s;
    int t = threadIdx.x;
    if (t == 0) carry_s = 0;
    __syncthreads();
    for (int base = 0; base < NN; base += T) {
        int v = (base + t < NN) ? d_indeg[base + t] : 0;
        buf[t] = v;
        __syncthreads();
        for (int off = 1; off < T; off <<= 1) {
            int add = (t >= off) ? buf[t - off] : 0;
            __syncthreads();
            buf[t] += add;
            __syncthreads();
        }
        int carry = carry_s;
        __syncthreads();
        if (base + t < NN) {
            d_rowptr[base + t] = carry + buf[t] - v;
            d_curp[base + t]   = carry + buf[t] - v;
        }
        if (t == T - 1) carry_s = carry + buf[t];
        __syncthreads();
    }
    if (t == 0) d_rowptr[NN] = carry_s;
}

__global__ void k_place(const int* __restrict__ src, const int* __restrict__ dst) {
    int e = blockIdx.x * blockDim.x + threadIdx.x;
    if (e >= NE) return;
    int slot = atomicAdd(&d_curp[dst[e]], 1);
    d_eid[slot]  = e;
    d_esrc[slot] = src[e];
}

// gT(half): [l][c][k*128+f] from g; rootT(half): [l][c][f]
__global__ void k_gt_h(const float* __restrict__ g, const float* __restrict__ root) {
    int i = blockIdx.x * blockDim.x + threadIdx.x;
    if (i < LL * C * KG * C) {
        int l   = i >> 17;
        int rem = i & 131071;
        int cR  = rem >> 10;
        int kf  = rem & 1023;
        int k = kf >> 7, f = kf & 127;
        d_gth[i] = __float2half_rn(g[((size_t)(l * 128 + f)) * 1024 + k * 128 + cR]);
    }
    if (i < LL * C * C) {
        int l = i >> 14;
        int c = (i >> 7) & 127;
        int f = i & 127;
        d_rooth[i] = __float2half_rn(root[((size_t)(l * 128 + f)) * 128 + c]);
    }
}

// half LSTM/MLP weights, fused biases, x->half
__global__ void k_prep(const float* __restrict__ wih, const float* __restrict__ whh,
                       const float* __restrict__ bih, const float* __restrict__ bhh,
                       const float* __restrict__ x,
                       const float* __restrict__ p1w, const float* __restrict__ p2w) {
    int i = blockIdx.x * blockDim.x + threadIdx.x;
    if (i < NN * C)       d_hlth[0][i] = __float2half_rn(x[i]);
    if (i < 2 * H4 * C)   d_wihh[i] = __float2half_rn(wih[i]);
    if (i < 2 * H4 * H)   d_whhh[i] = __float2half_rn(whh[i]);
    if (i < 2 * H4)       d_bsum[i] = bih[i] + bhh[i];
    if (i < NHID * C)  {
        int n = i / C, c = i % C;
        d_p1wh[i] = __float2half_rn(p1w[(size_t)c * NHID + n]);
    }
    if (i < NOUT * NHID) {
        int n = i / NHID, k = i % NHID;
        d_p2wh[i] = __float2half_rn(p2w[(size_t)k * NOUT + n]);
    }
}

// all-layer gaussian weights, CSR-slot ordered (runs AFTER k_place)
__global__ void k_ewall(const float* __restrict__ ea,
                        const float* __restrict__ mu,
                        const float* __restrict__ sg) {
    int p = blockIdx.x * blockDim.x + threadIdx.x;
    if (p >= NE) return;
    int e = d_eid[p];
    float a0 = ea[e * 2 + 0], a1 = ea[e * 2 + 1];
#pragma unroll
    for (int l = 0; l < LL; l++) {
        const float* mul = mu + l * KG * 2;
        const float* sgl = sg + l * KG * 2;
#pragma unroll
        for (int k = 0; k < KG; k++) {
            float dx = a0 - mul[k * 2 + 0];
            float dy = a1 - mul[k * 2 + 1];
            float s0 = sgl[k * 2 + 0], s1 = sgl[k * 2 + 1];
            float w = __expf(-0.5f * (__fdividef(dx * dx, 1e-15f + s0 * s0) +
                                      __fdividef(dy * dy, 1e-15f + s1 * s1)));
            d_ewh[l][(size_t)p * KG + k] = __float2half_rn(w);
        }
    }
}

// S accumulation (warp per node); ew is CSR-sequential; 2x unrolled edges
__global__ void k_sacc(const __half* __restrict__ hinh, int layer) {
    if (blockIdx.x == 0 && threadIdx.x < C) {
        d_bns[threadIdx.x] = 0.f;
        d_bnq[threadIdx.x] = 0.f;
    }
    int n = (blockIdx.x * blockDim.x + threadIdx.x) >> 5;
    int l = threadIdx.x & 31;
    if (n >= NN) return;
    const __half* ewl = d_ewh[layer];
    const __half2* h2b = (const __half2*)hinh;
    int beg = d_rowptr[n], end = d_rowptr[n + 1];
    float acc[KG][4];
#pragma unroll
    for (int k = 0; k < KG; k++)
#pragma unroll
        for (int q = 0; q < 4; q++) acc[k][q] = 0.f;

    int p = beg;
    for (; p + 2 <= end; p += 2) {
        int s0 = d_esrc[p], s1 = d_esrc[p + 1];
        float wv0 = (l < KG) ? __half2float(ewl[(size_t)p * KG + l]) : 0.f;
        float wv1 = (l < KG) ? __half2float(ewl[(size_t)(p + 1) * KG + l]) : 0.f;
        const __half2* ha = h2b + (size_t)s0 * 64;
        const __half2* hb = h2b + (size_t)s1 * 64;
        float2 a0 = __half22float2(ha[l]);
        float2 a1 = __half22float2(ha[l + 32]);
        float2 b0 = __half22float2(hb[l]);
        float2 b1 = __half22float2(hb[l + 32]);
#pragma unroll
        for (int k = 0; k < KG; k++) {
            float wk0 = __shfl_sync(0xffffffffu, wv0, k);
            float wk1 = __shfl_sync(0xffffffffu, wv1, k);
            acc[k][0] = fmaf(wk0, a0.x, fmaf(wk1, b0.x, acc[k][0]));
            acc[k][1] = fmaf(wk0, a0.y, fmaf(wk1, b0.y, acc[k][1]));
            acc[k][2] = fmaf(wk0, a1.x, fmaf(wk1, b1.x, acc[k][2]));
            acc[k][3] = fmaf(wk0, a1.y, fmaf(wk1, b1.y, acc[k][3]));
        }
    }
    if (p < end) {
        int s0 = d_esrc[p];
        float wv0 = (l < KG) ? __half2float(ewl[(size_t)p * KG + l]) : 0.f;
        const __half2* ha = h2b + (size_t)s0 * 64;
        float2 a0 = __half22float2(ha[l]);
        float2 a1 = __half22float2(ha[l + 32]);
#pragma unroll
        for (int k = 0; k < KG; k++) {
            float wk0 = __shfl_sync(0xffffffffu, wv0, k);
            acc[k][0] = fmaf(wk0, a0.x, acc[k][0]);
            acc[k][1] = fmaf(wk0, a0.y, acc[k][1]);
            acc[k][2] = fmaf(wk0, a1.x, acc[k][2]);
            acc[k][3] = fmaf(wk0, a1.y, acc[k][3]);
        }
    }
    float inv = __fdividef(1.f, fmaxf((float)(end - beg), 1.f));
    __half2* Sp2 = (__half2*)&d_Sh[(size_t)n * (KG * C)];
#pragma unroll
    for (int k = 0; k < KG; k++) {
        Sp2[k * 64 + l]      = __floats2half2_rn(acc[k][0] * inv, acc[k][1] * inv);
        Sp2[k * 64 + 32 + l] = __floats2half2_rn(acc[k][2] * inv, acc[k][3] * inv);
    }
}

// BN apply: reads half GEMM output, writes half activation copy
__global__ void k_bnapp(const float* __restrict__ gamma,
                        const float* __restrict__ beta,
                        __half* __restrict__ out_hlt, int relu) {
    int i = blockIdx.x * blockDim.x + threadIdx.x;
    if (i >= NN * C) return;
    int c = i % C;
    float mean = d_bns[c] / (float)NN;
    float var  = d_bnq[c] / (float)NN - mean * mean;
    float v = (__half2float(d_hh[i]) - mean) * rsqrtf(var + 1e-5f) * gamma[c] + beta[c];
    if (relu) v = fmaxf(v, 0.f);
    out_hlt[i] = __float2half_rn(v);
}

// fused: attention softmax + weighted node rep + pool + graph count
__global__ void k_nreppool(const float* __restrict__ x,
                           const int* __restrict__ batch) {
    int n = blockIdx.x;
    int c = threadIdx.x;
    __shared__ float p[5];
    __shared__ int gidx;
    if (c == 0) {
        float a[5], m = -1e30f;
#pragma unroll
        for (int t = 0; t < 5; t++) {
            a[t] = d_af[t * NN + n] + d_ab[t * NN + n];
            m = fmaxf(m, a[t]);
        }
        float s = 0.f;
#pragma unroll
        for (int t = 0; t < 5; t++) { a[t] = __expf(a[t] - m); s += a[t]; }
        float invs = __fdividef(1.f, s);
#pragma unroll
        for (int t = 0; t < 5; t++) p[t] = a[t] * invs;
        gidx = batch[n];
        atomicAdd(&d_cnt[gidx], 1.f);
    }
    __syncthreads();
    float r = p[0] * x[(size_t)n * C + c];
#pragma unroll
    for (int t = 1; t < 5; t++)
        r = fmaf(p[t], __half2float(d_hlth[t][(size_t)n * C + c]), r);
    atomicAdd(&d_hg[(size_t)gidx * C + c], r);
}

__global__ void k_pdiv() {
    int i = blockIdx.x * blockDim.x + threadIdx.x;
    if (i >= NB * C) return;
    float v = d_hg[i] / fmaxf(d_cnt[i / C], 1.f);
    d_hgh[i] = __float2half_rn(v);
}

__global__ void k_ln(const float* __restrict__ g, const float* __restrict__ b,
                     float* __restrict__ out) {
    int row = blockIdx.x, t = threadIdx.x;
    __shared__ float sm[NOUT];
    float v = d_z2[(size_t)row * NOUT + t];
    sm[t] = v;
    __syncthreads();
    for (int o = NOUT / 2; o > 0; o >>= 1) {
        if (t < o) sm[t] += sm[t + o];
        __syncthreads();
    }
    float mean = sm[0] / (float)NOUT;
    __syncthreads();
    float dv = v - mean;
    sm[t] = dv * dv;
    __syncthreads();
    for (int o = NOUT / 2; o > 0; o >>= 1) {
        if (t < o) sm[t] += sm[t + o];
        __syncthreads();
    }
    float var = sm[0] / (float)NOUT;
    out[(size_t)row * NOUT + t] = dv * rsqrtf(var + 1e-5f) * g[t] + b[t];
}

// ---------------- host ----------------
static float* symf(const void* s) {
    void* p = nullptr;
    cudaGetSymbolAddress(&p, s);
    return (float*)p;
}
static __half* symh(const void* s) {
    void* p = nullptr;
    cudaGetSymbolAddress(&p, s);
    return (__half*)p;
}
static int* symi(const void* s) {
    void* p = nullptr;
    cudaGetSymbolAddress(&p, s);
    return (int*)p;
}

extern "C" void kernel_launch(void* const* d_in, const int* in_sizes, int n_in,
                              void* d_out, int out_size) {
    const float* x     = (const float*)d_in[0];
    const int*   ei    = (const int*)d_in[1];
    const int*   src   = ei;
    const int*   dst   = ei + NE;
    const float* ea    = (const float*)d_in[2];
    const int*   batch = (const int*)d_in[3];
    const float* g     = (const float*)d_in[4];
    const float* root  = (const float*)d_in[5];
    const float* bias  = (const float*)d_in[6];
    const float* mu    = (const float*)d_in[7];
    const float* sigma = (const float*)d_in[8];
    const float* bng   = (const float*)d_in[9];
    const float* bnb   = (const float*)d_in[10];
    const float* wih   = (const float*)d_in[11];
    const float* whh   = (const float*)d_in[12];
    const float* bih   = (const float*)d_in[13];
    const float* bhh   = (const float*)d_in[14];
    const float* attw  = (const float*)d_in[15];
    const float* p1w   = (const float*)d_in[17];
    const float* p1b   = (const float*)d_in[18];
    const float* p2w   = (const float*)d_in[19];
    const float* p2b   = (const float*)d_in[20];
    const float* lng   = (const float*)d_in[21];
    const float* lnb   = (const float*)d_in[22];
    float* out = (float*)d_out;

    __half* hh    = symh(d_hh);
    __half* hlth  = symh(d_hlth);
    __half* Sh    = symh(d_Sh);
    __half* gth   = symh(d_gth);
    __half* rooth = symh(d_rooth);
    float*  af    = symf(d_af);
    float*  ab    = symf(d_ab);
    __half* hgh   = symh(d_hgh);
    __half* z1h   = symh(d_z1h);
    float*  z2    = symf(d_z2);
    __half* p1wh  = symh(d_p1wh);
    __half* p2wh  = symh(d_p2wh);
    int* indeg    = symi(d_indeg);

    const int TPB = 256;
    const dim3 blk(TPB);
    const int gridNC = (NN * C + TPB - 1) / TPB;
    const int rowsN  = (NN + 127) / 128;
    const int TLSTM_SMEM = 40960;

    static int smem_set = 0;
    if (!smem_set) {
        cudaFuncSetAttribute(tlstm, cudaFuncAttributeMaxDynamicSharedMemorySize,
                             TLSTM_SMEM);
        smem_set = 1;
    }

    // -------- CSR build + weight prep (ewall AFTER place: CSR-slot order) --
    k_zeroi<<<(NN + TPB - 1) / TPB, blk>>>(indeg, NN);
    k_degi<<<(NE + TPB - 1) / TPB, blk>>>(dst);
    k_scan<<<1, 1024>>>();
    k_place<<<(NE + TPB - 1) / TPB, blk>>>(src, dst);
    k_gt_h<<<(LL * C * KG * C + TPB - 1) / TPB, blk>>>(g, root);
    k_prep<<<(NN * C + TPB - 1) / TPB, blk>>>(wih, whh, bih, bhh, x, p1w, p2w);
    k_ewall<<<(NE + TPB - 1) / TPB, blk>>>(ea, mu, sigma);

    // -------- GMMConv layers (BN stats fused in GEMM epilogue) --------
    for (int i = 0; i < LL; i++) {
        k_sacc<<<(NN * 32 + TPB - 1) / TPB, blk>>>(hlth + (size_t)i * NN * C, i);
        GH gl = {Sh, gth + (size_t)i * C * KG * C,
                 hlth + (size_t)i * NN * C, rooth + (size_t)i * C * C,
                 hh, bias + i * C, KG * C, C};
        tgemm_h<false, true, true><<<dim3(1, rowsN), blk>>>(gl, NN, C);
        k_bnapp<<<gridNC, blk>>>(bng + i * C, bnb + i * C,
                                 hlth + (size_t)(i + 1) * NN * C,
                                 (i < LL - 1) ? 1 : 0);
    }

    // -------- bidirectional LSTM JumpingKnowledge (fused fp16 GEMM+cell) --
    k_zero02<<<(5 * NN + TPB - 1) / TPB, blk>>>(af, ab, 5 * NN);
    for (int s = 0; s < 5; s++) {
        int tf = s, tb = 4 - s;
        const __half* xf = hlth + (size_t)tf * NN * C;
        const __half* xb = hlth + (size_t)tb * NN * C;
        tlstm<<<dim3(H / 32, rowsN, 2), blk, TLSTM_SMEM>>>(xf, xb, attw,
                                                           (s > 0) ? H : 0, s);
    }

    // global mean pool (fused attention mix + scatter + count)
    k_zerog<<<(NB * C + TPB - 1) / TPB, blk>>>();
    k_nreppool<<<NN, C>>>(x, batch);
    k_pdiv<<<(NB * C + TPB - 1) / TPB, blk>>>();

    // MLP + LayerNorm (fp16 GEMMs)
    GH gp1 = {hgh, p1wh, nullptr, nullptr, z1h, p1b, C, 0};
    tgemm_h<true, true, false><<<dim3(NHID / 128, NB / 128), blk>>>(gp1, NB, NHID);
    GH gp2 = {z1h, p2wh, nullptr, nullptr, z2, p2b, NHID, 0};
    tgemm_h<false, false, false><<<dim3(NOUT / 128, NB / 128), blk>>>(gp2, NB, NOUT);
    k_ln<<<NB, NOUT>>>(lng, lnb, out);
}

// round 16
// speedup vs baseline: 1.9306x; 1.0013x over previous
#include <cuda_runtime.h>
#include <cuda_fp16.h>
#include <math.h>
#include <stdint.h>

// ---------------- problem constants ----------------
namespace {
constexpr int NN   = 30000;   // nodes
constexpr int NE   = 480000;  // edges
constexpr int C    = 128;     // channels (= F)
constexpr int KG   = 8;       // gaussians
constexpr int LL   = 4;       // layers
constexpr int H    = 256;     // LSTM hidden
constexpr int H4   = 1024;    // 4*H
constexpr int NHID = 512;
constexpr int NOUT = 256;
constexpr int NB   = 1024;    // graphs
}

// ---------------- scratch (device globals; no allocations allowed) -------
__device__ __align__(256) __half d_hh[NN * C];           // GMM GEMM out (half)
__device__ __align__(256) __half d_hlth[5][NN * C];      // half x,h1..h4
__device__ __align__(256) __half d_Sh[NN * KG * C];
__device__ __align__(256) __half d_gth[LL * C * KG * C]; // [l][c][k*128+f]
__device__ __align__(256) __half d_rooth[LL * C * C];    // [l][c][f]
__device__ __align__(256) __half d_ewh[LL][NE * KG];     // CSR-slot ordered
__device__ __align__(256) float  d_bns[C];
__device__ __align__(256) float  d_bnq[C];
__device__ __align__(256) __half d_lhh[2][2][NN * H];    // [pingpong][dir]
__device__ __align__(256) float  d_lc[2][NN * H];
__device__ __align__(256) float  d_af[5 * NN];
__device__ __align__(256) float  d_ab[5 * NN];
__device__ __align__(256) float  d_cnt[NB];
__device__ __align__(256) float  d_hg[NB * C];
__device__ __align__(256) __half d_hgh[NB * C];
__device__ __align__(256) __half d_z1h[NB * NHID];
__device__ __align__(256) float  d_z2[NB * NOUT];
// half LSTM weights ([n][k] layout) + fused biases, half MLP weights
__device__ __align__(256) __half d_wihh[2 * H4 * C];
__device__ __align__(256) __half d_whhh[2 * H4 * H];
__device__ __align__(256) float  d_bsum[2 * H4];
__device__ __align__(256) __half d_p1wh[NHID * C];       // [n][k]
__device__ __align__(256) __half d_p2wh[NOUT * NHID];    // [n][k]
// CSR scratch
__device__ __align__(256) int d_indeg[NN];
__device__ __align__(256) int d_rowptr[NN + 1];
__device__ __align__(256) int d_curp[NN];
__device__ __align__(256) int d_eid[NE];
__device__ __align__(256) int d_esrc[NE];

// ---------------- helpers ----------------
__device__ __forceinline__ void mma16h(float* c, const uint32_t* a, const uint32_t* b) {
    asm volatile(
        "mma.sync.aligned.m16n8k16.row.col.f32.f16.f16.f32 "
        "{%0,%1,%2,%3}, {%4,%5,%6,%7}, {%8,%9}, {%0,%1,%2,%3};"
        : "+f"(c[0]), "+f"(c[1]), "+f"(c[2]), "+f"(c[3])
        : "r"(a[0]), "r"(a[1]), "r"(a[2]), "r"(a[3]), "r"(b[0]), "r"(b[1]));
}
__device__ __forceinline__ void ldsm4(uint32_t* r, uint32_t saddr) {
    asm volatile("ldmatrix.sync.aligned.m8n8.x4.shared.b16 {%0,%1,%2,%3}, [%4];"
                 : "=r"(r[0]), "=r"(r[1]), "=r"(r[2]), "=r"(r[3])
                 : "r"(saddr));
}
__device__ __forceinline__ void cpa16(uint32_t sdst, const void* gsrc, int srcsz) {
    asm volatile("cp.async.ca.shared.global [%0], [%1], 16, %2;\n"
                 :: "r"(sdst), "l"(gsrc), "r"(srcsz));
}
__device__ __forceinline__ void cpa_commit() { asm volatile("cp.async.commit_group;\n"); }
__device__ __forceinline__ void cpa_wait1()  { asm volatile("cp.async.wait_group 1;\n"); }
__device__ __forceinline__ void cpa_wait2()  { asm volatile("cp.async.wait_group 2;\n"); }
__device__ __forceinline__ float sigf(float x) {
    return __fdividef(1.f, 1.f + __expf(-x));
}
__device__ __forceinline__ float tanhfast(float x) {
    float t = __expf(-2.f * fabsf(x));
    float r = __fdividef(1.f - t, 1.f + t);
    return copysignf(r, x);
}

// ---------------- FP16 tensor GEMM (cp.async 2-stage, dual-K, TB form) ----
struct GH {
    const __half* A;
    const __half* B;
    const __half* A2;
    const __half* B2;
    void* Cm;            // float* or __half* (OUTH)
    const float* bias;   // nullptr -> none
    int Kd;
    int Kd2;
};

template <bool RELU_, bool OUTH, bool BN>
__global__ __launch_bounds__(256) void tgemm_h(GH ga, int M, int Nm)
{
    __shared__ uint32_t As[2][2560];   // [row][20]
    __shared__ uint32_t Bs[2][2560];

    const __half* __restrict__ A  = ga.A;
    const __half* __restrict__ B  = ga.B;
    const __half* __restrict__ A2 = ga.A2;
    const __half* __restrict__ B2 = ga.B2;
    const float* __restrict__ bias = ga.bias;
    const int Kd = ga.Kd, Kd2 = ga.Kd2;

    const int tid  = threadIdx.x;
    const int lane = tid & 31;
    const int wid  = tid >> 5;
    const int wm   = wid & 3;
    const int wn   = wid >> 2;
    const int gid  = lane >> 2;
    const int tig  = lane & 3;
    const int row0 = blockIdx.y * 128, col0 = blockIdx.x * 128;

    const int nt1 = Kd >> 5;
    const int nt  = nt1 + (Kd2 >> 5);

    const int aRow = (lane & 7) + ((lane >> 3) & 1) * 8;
    const int aCol = (lane >> 4) * 4;
    const int bRow = (lane & 7) + (lane >> 4) * 8;
    const int bCol = ((lane >> 3) & 1) * 4;
    const uint32_t asb = (uint32_t)__cvta_generic_to_shared(&As[0][0]);
    const uint32_t bsb = (uint32_t)__cvta_generic_to_shared(&Bs[0][0]);

    float acc[2][8][4];
#pragma unroll
    for (int mi = 0; mi < 2; mi++)
#pragma unroll
        for (int ni = 0; ni < 8; ni++)
#pragma unroll
            for (int r = 0; r < 4; r++) acc[mi][ni][r] = 0.f;

    auto loadTile = [&](int t, int st) {
        const __half* Ap; const __half* Bp; int Kc, k0;
        if (t < nt1) { Ap = A;  Bp = B;  Kc = Kd;  k0 = t << 5; }
        else         { Ap = A2; Bp = B2; Kc = Kd2; k0 = (t - nt1) << 5; }
#pragma unroll
        for (int it = 0; it < 2; it++) {
            int idx = tid + it * 256;
            int rr = idx >> 2, part = idx & 3;
            int gr = row0 + rr;
            uint32_t dst = (uint32_t)__cvta_generic_to_shared(&As[st][rr * 20 + part * 4]);
            cpa16(dst, Ap + (size_t)gr * Kc + k0 + part * 8, gr < M ? 16 : 0);
        }
#pragma unroll
        for (int it = 0; it < 2; it++) {
            int idx = tid + it * 256;
            int rr = idx >> 2, part = idx & 3;
            uint32_t dst = (uint32_t)__cvta_generic_to_shared(&Bs[st][rr * 20 + part * 4]);
            cpa16(dst, Bp + (size_t)(col0 + rr) * Kc + k0 + part * 8, 16);
        }
    };

    loadTile(0, 0);
    cpa_commit();

    for (int t = 0; t < nt; t++) {
        if (t + 1 < nt) loadTile(t + 1, (t + 1) & 1);
        cpa_commit();
        cpa_wait1();
        __syncthreads();

        const int st = t & 1;
        const uint32_t aST = asb + st * 2560 * 4;
        const uint32_t bST = bsb + st * 2560 * 4;
#pragma unroll
        for (int kk = 0; kk < 2; kk++) {
            uint32_t a[2][4], b[8][2];
#pragma unroll
            for (int mi = 0; mi < 2; mi++) {
                int mr = wm * 32 + mi * 16;
                ldsm4(a[mi], aST + ((mr + aRow) * 20 + kk * 8 + aCol) * 4);
            }
#pragma unroll
            for (int np = 0; np < 4; np++) {
                uint32_t bb[4];
                int nr = wn * 64 + np * 16;
                ldsm4(bb, bST + ((nr + bRow) * 20 + kk * 8 + bCol) * 4);
                b[np * 2][0]     = bb[0]; b[np * 2][1]     = bb[1];
                b[np * 2 + 1][0] = bb[2]; b[np * 2 + 1][1] = bb[3];
            }
#pragma unroll
            for (int mi = 0; mi < 2; mi++)
#pragma unroll
                for (int ni = 0; ni < 8; ni++)
                    mma16h(acc[mi][ni], a[mi], b[ni]);
        }
        __syncthreads();
    }

    float cs[8][2], cq[8][2];
    if (BN) {
#pragma unroll
        for (int ni = 0; ni < 8; ni++) {
            cs[ni][0] = cs[ni][1] = 0.f;
            cq[ni][0] = cq[ni][1] = 0.f;
        }
    }

#pragma unroll
    for (int mi = 0; mi < 2; mi++) {
#pragma unroll
        for (int half_ = 0; half_ < 2; half_++) {
            int r = row0 + wm * 32 + mi * 16 + gid + half_ * 8;
            if (r >= M) continue;
#pragma unroll
            for (int ni = 0; ni < 8; ni++) {
                int cI = col0 + wn * 64 + ni * 8 + tig * 2;
                float v0 = acc[mi][ni][half_ * 2 + 0];
                float v1 = acc[mi][ni][half_ * 2 + 1];
                if (bias) { v0 += bias[cI]; v1 += bias[cI + 1]; }
                if (RELU_) { v0 = fmaxf(v0, 0.f); v1 = fmaxf(v1, 0.f); }
                if (OUTH) {
                    __half2* cp = (__half2*)((__half*)ga.Cm + (size_t)r * Nm + cI);
                    *cp = __floats2half2_rn(v0, v1);
                } else {
                    float* cp = (float*)ga.Cm + (size_t)r * Nm + cI;
                    cp[0] = v0; cp[1] = v1;
                }
                if (BN) {
                    cs[ni][0] += v0; cq[ni][0] += v0 * v0;
                    cs[ni][1] += v1; cq[ni][1] += v1 * v1;
                }
            }
        }
    }

    if (BN) {
#pragma unroll
        for (int off = 16; off >= 4; off >>= 1) {
#pragma unroll
            for (int ni = 0; ni < 8; ni++) {
#pragma unroll
                for (int sub = 0; sub < 2; sub++) {
                    cs[ni][sub] += __shfl_down_sync(0xffffffffu, cs[ni][sub], off);
                    cq[ni][sub] += __shfl_down_sync(0xffffffffu, cq[ni][sub], off);
                }
            }
        }
        float* bnb = (float*)As;
        if (gid == 0) {
#pragma unroll
            for (int ni = 0; ni < 8; ni++)
#pragma unroll
                for (int sub = 0; sub < 2; sub++) {
                    int slot = (((wid << 2) | tig) * 8 + ni) * 4 + sub * 2;
                    bnb[slot]     = cs[ni][sub];
                    bnb[slot + 1] = cq[ni][sub];
                }
        }
        __syncthreads();
        int colL = tid >> 1, stat = tid & 1;
        int wn_ = colL >> 6, r_ = colL & 63;
        int ni_ = r_ >> 3, q_ = r_ & 7, tig_ = q_ >> 1, sub_ = q_ & 1;
        float v = 0.f;
#pragma unroll
        for (int wm_ = 0; wm_ < 4; wm_++) {
            int wid_ = wn_ * 4 + wm_;
            v += bnb[(((wid_ << 2) | tig_) * 8 + ni_) * 4 + sub_ * 2 + stat];
        }
        atomicAdd(stat ? &d_bnq[col0 + colL] : &d_bns[col0 + colL], v);
    }
}

// ---------------- fused LSTM step (FP16): 3-stage cp.async ---------------
// dynamic smem 61440B: A stages at st*2560, B stages at 7680+st*2560.
__global__ __launch_bounds__(256) void tlstm(
    const __half* __restrict__ xf, const __half* __restrict__ xb,
    const float* __restrict__ attw, int K2, int s)
{
    extern __shared__ uint32_t sraw[];   // 15360 words = 61440 B
    float* gbuf = (float*)sraw;          // epilogue reuse: [64][133] = 34KB

    const int dir  = blockIdx.z;
    const int c0   = blockIdx.x * 32;
    const int row0 = blockIdx.y * 128;
    const int pb   = s & 1;

    const __half* A  = dir ? xb : xf;
    const __half* B  = d_wihh + (size_t)dir * H4 * C;
    const __half* A2 = d_lhh[pb][dir];
    const __half* B2 = d_whhh + (size_t)dir * H4 * H;

    const int tid  = threadIdx.x;
    const int lane = tid & 31;
    const int wid  = tid >> 5;
    const int wm   = wid & 3;
    const int wn   = wid >> 2;
    const int gid  = lane >> 2;
    const int tig  = lane & 3;

    const int nt1 = C >> 5;              // 4
    const int nt  = nt1 + (K2 >> 5);     // 4 or 12

    const int aRow = (lane & 7) + ((lane >> 3) & 1) * 8;
    const int aCol = (lane >> 4) * 4;
    const int bRow = (lane & 7) + (lane >> 4) * 8;
    const int bCol = ((lane >> 3) & 1) * 4;
    const uint32_t sbase = (uint32_t)__cvta_generic_to_shared(sraw);

    float acc[2][8][4];
#pragma unroll
    for (int mi = 0; mi < 2; mi++)
#pragma unroll
        for (int ni = 0; ni < 8; ni++)
#pragma unroll
            for (int r = 0; r < 4; r++) acc[mi][ni][r] = 0.f;

    auto loadTile = [&](int t, int st) {
        const __half* Ap; const __half* Bp; int Kc, k0;
        if (t < nt1) { Ap = A;  Bp = B;  Kc = C; k0 = t << 5; }
        else         { Ap = A2; Bp = B2; Kc = H; k0 = (t - nt1) << 5; }
        uint32_t* Asb = sraw + st * 2560;
        uint32_t* Bsb = sraw + 7680 + st * 2560;
#pragma unroll
        for (int it = 0; it < 2; it++) {
            int idx = tid + it * 256;
            int rr = idx >> 2, part = idx & 3;
            int gr = row0 + rr;
            uint32_t dst = (uint32_t)__cvta_generic_to_shared(&Asb[rr * 20 + part * 4]);
            cpa16(dst, Ap + (size_t)gr * Kc + k0 + part * 8, gr < NN ? 16 : 0);
        }
#pragma unroll
        for (int it = 0; it < 2; it++) {
            int idx = tid + it * 256;
            int rr = idx >> 2, part = idx & 3;
            int brow = ((rr >> 5) << 8) + c0 + (rr & 31);   // gate*256 + c0 + j'
            uint32_t dst = (uint32_t)__cvta_generic_to_shared(&Bsb[rr * 20 + part * 4]);
            cpa16(dst, Bp + (size_t)brow * Kc + k0 + part * 8, 16);
        }
    };

    loadTile(0, 0);
    cpa_commit();
    loadTile(1, 1);
    cpa_commit();

    for (int t = 0; t < nt; t++) {
        if (t + 2 < nt) loadTile(t + 2, (t + 2) % 3);
        cpa_commit();
        cpa_wait2();
        __syncthreads();

        const int st = t % 3;
        const uint32_t aST = sbase + st * 2560 * 4;
        const uint32_t bST = sbase + (7680 + st * 2560) * 4;
#pragma unroll
        for (int kk = 0; kk < 2; kk++) {
            uint32_t a[2][4], b[8][2];
#pragma unroll
            for (int mi = 0; mi < 2; mi++) {
                int mr = wm * 32 + mi * 16;
                ldsm4(a[mi], aST + ((mr + aRow) * 20 + kk * 8 + aCol) * 4);
            }
#pragma unroll
            for (int np = 0; np < 4; np++) {
                uint32_t bb[4];
                int nr = wn * 64 + np * 16;
                ldsm4(bb, bST + ((nr + bRow) * 20 + kk * 8 + bCol) * 4);
                b[np * 2][0]     = bb[0]; b[np * 2][1]     = bb[1];
                b[np * 2 + 1][0] = bb[2]; b[np * 2 + 1][1] = bb[3];
            }
#pragma unroll
            for (int mi = 0; mi < 2; mi++)
#pragma unroll
                for (int ni = 0; ni < 8; ni++)
                    mma16h(acc[mi][ni], a[mi], b[ni]);
        }
        __syncthreads();
    }

    // ---- fused epilogue: two 64-row passes through smem ----
    const float* bs = d_bsum + (size_t)dir * H4;
    float* lc   = d_lc[dir];
    __half* lhw = d_lhh[1 - pb][dir];
    const int t_idx = dir ? (4 - s) : s;
    float* aout = (dir ? d_ab : d_af) + t_idx * NN;

#pragma unroll
    for (int p = 0; p < 2; p++) {
        __syncthreads();
        if ((wm >> 1) == p) {
#pragma unroll
            for (int mi = 0; mi < 2; mi++)
#pragma unroll
                for (int half_ = 0; half_ < 2; half_++) {
                    int rloc = (wm & 1) * 32 + mi * 16 + gid + half_ * 8;
#pragma unroll
                    for (int ni = 0; ni < 8; ni++) {
                        int col = wn * 64 + ni * 8 + tig * 2;
                        gbuf[rloc * 133 + col]     = acc[mi][ni][half_ * 2 + 0];
                        gbuf[rloc * 133 + col + 1] = acc[mi][ni][half_ * 2 + 1];
                    }
                }
        }
        __syncthreads();

        int rr = tid >> 2;                 // 0..63
        int n  = row0 + p * 64 + rr;
        bool valid = n < NN;
        float part = 0.f;
        if (valid) {
            int jb = (tid & 3) * 8;
#pragma unroll
            for (int q = 0; q < 8; q++) {
                int jl = jb + q;           // 0..31
                int j  = c0 + jl;          // 0..255
                float gi = gbuf[rr * 133 +  0 + jl] + bs[0 * H + j];
                float gf = gbuf[rr * 133 + 32 + jl] + bs[1 * H + j];
                float gg = gbuf[rr * 133 + 64 + jl] + bs[2 * H + j];
                float go = gbuf[rr * 133 + 96 + jl] + bs[3 * H + j];
                size_t ix = (size_t)n * H + j;
                float cprev = (K2 > 0) ? lc[ix] : 0.f;
                float cc = sigf(gf) * cprev + sigf(gi) * tanhfast(gg);
                lc[ix] = cc;
                float hh = sigf(go) * tanhfast(cc);
                lhw[ix] = __float2half_rn(hh);
                part = fmaf(hh, attw[dir * H + j], part);
            }
        }
        part += __shfl_down_sync(0xffffffffu, part, 2);
        part += __shfl_down_sync(0xffffffffu, part, 1);
        if (valid && (tid & 3) == 0) atomicAdd(&aout[n], part);
    }
}

// ---------------- small kernels ----------------
__global__ void k_zero02(float* p0, float* p1, int n) {
    int i = blockIdx.x * blockDim.x + threadIdx.x;
    if (i < n) { p0[i] = 0.f; p1[i] = 0.f; }
}
__global__ void k_zeroi(int* p, int n) {
    int i = blockIdx.x * blockDim.x + threadIdx.x;
    if (i < n) p[i] = 0;
}
__global__ void k_zerog() {
    int i = blockIdx.x * blockDim.x + threadIdx.x;
    if (i < NB * C) d_hg[i] = 0.f;
    if (i < NB)     d_cnt[i] = 0.f;
}

__global__ void k_degi(const int* __restrict__ dst) {
    int e = blockIdx.x * blockDim.x + threadIdx.x;
    if (e < NE) atomicAdd(&d_indeg[dst[e]], 1);
}

__global__ void k_scan() {
    const int T = 1024;
    __shared__ int buf[T];
    __shared__ int carry_s;
    int t = threadIdx.x;
    if (t == 0) carry_s = 0;
    __syncthreads();
    for (int base = 0; base < NN; base += T) {
        int v = (base + t < NN) ? d_indeg[base + t] : 0;
        buf[t] = v;
        __syncthreads();
        for (int off = 1; off < T; off <<= 1) {
            int add = (t >= off) ? buf[t - off] : 0;
            __syncthreads();
            buf[t] += add;
            __syncthreads();
        }
        int carry = carry_s;
        __syncthreads();
        if (base + t < NN) {
            d_rowptr[base + t] = carry + buf[t] - v;
            d_curp[base + t]   = carry + buf[t] - v;
        }
        if (t == T - 1) carry_s = carry + buf[t];
        __syncthreads();
    }
    if (t == 0) d_rowptr[NN] = carry_s;
}

__global__ void k_place(const int* __restrict__ src, const int* __restrict__ dst) {
    int e = blockIdx.x * blockDim.x + threadIdx.x;
    if (e >= NE) return;
    int slot = atomicAdd(&d_curp[dst[e]], 1);
    d_eid[slot]  = e;
    d_esrc[slot] = src[e];
}

__global__ void k_gt_h(const float* __restrict__ g, const float* __restrict__ root) {
    int i = blockIdx.x * blockDim.x + threadIdx.x;
    if (i < LL * C * KG * C) {
        int l   = i >> 17;
        int rem = i & 131071;
        int cR  = rem >> 10;
        int kf  = rem & 1023;
        int k = kf >> 7, f = kf & 127;
        d_gth[i] = __float2half_rn(g[((size_t)(l * 128 + f)) * 1024 + k * 128 + cR]);
    }
    if (i < LL * C * C) {
        int l = i >> 14;
        int c = (i >> 7) & 127;
        int f = i & 127;
        d_rooth[i] = __float2half_rn(root[((size_t)(l * 128 + f)) * 128 + c]);
    }
}

__global__ void k_prep(const float* __restrict__ wih, const float* __restrict__ whh,
                       const float* __restrict__ bih, const float* __restrict__ bhh,
                       const float* __restrict__ x,
                       const float* __restrict__ p1w, const float* __restrict__ p2w) {
    int i = blockIdx.x * blockDim.x + threadIdx.x;
    if (i < NN * C)       d_hlth[0][i] = __float2half_rn(x[i]);
    if (i < 2 * H4 * C)   d_wihh[i] = __float2half_rn(wih[i]);
    if (i < 2 * H4 * H)   d_whhh[i] = __float2half_rn(whh[i]);
    if (i < 2 * H4)       d_bsum[i] = bih[i] + bhh[i];
    if (i < NHID * C)  {
        int n = i / C, c = i % C;
        d_p1wh[i] = __float2half_rn(p1w[(size_t)c * NHID + n]);
    }
    if (i < NOUT * NHID) {
        int n = i / NHID, k = i % NHID;
        d_p2wh[i] = __float2half_rn(p2w[(size_t)k * NOUT + n]);
    }
}

// all-layer gaussian weights, CSR-slot ordered (runs AFTER k_place)
__global__ void k_ewall(const float* __restrict__ ea,
                        const float* __restrict__ mu,
                        const float* __restrict__ sg) {
    int p = blockIdx.x * blockDim.x + threadIdx.x;
    if (p >= NE) return;
    int e = d_eid[p];
    float a0 = ea[e * 2 + 0], a1 = ea[e * 2 + 1];
#pragma unroll
    for (int l = 0; l < LL; l++) {
        const float* mul = mu + l * KG * 2;
        const float* sgl = sg + l * KG * 2;
#pragma unroll
        for (int k = 0; k < KG; k++) {
            float dx = a0 - mul[k * 2 + 0];
            float dy = a1 - mul[k * 2 + 1];
            float s0 = sgl[k * 2 + 0], s1 = sgl[k * 2 + 1];
            float w = __expf(-0.5f * (__fdividef(dx * dx, 1e-15f + s0 * s0) +
                                      __fdividef(dy * dy, 1e-15f + s1 * s1)));
            d_ewh[l][(size_t)p * KG + k] = __float2half_rn(w);
        }
    }
}

// S accumulation (warp per node); ew CSR-sequential; 4x unrolled edges
__global__ void k_sacc(const __half* __restrict__ hinh, int layer) {
    if (blockIdx.x == 0 && threadIdx.x < C) {
        d_bns[threadIdx.x] = 0.f;
        d_bnq[threadIdx.x] = 0.f;
    }
    int n = (blockIdx.x * blockDim.x + threadIdx.x) >> 5;
    int l = threadIdx.x & 31;
    if (n >= NN) return;
    const __half* ewl = d_ewh[layer];
    const __half2* h2b = (const __half2*)hinh;
    int beg = d_rowptr[n], end = d_rowptr[n + 1];
    float acc[KG][4];
#pragma unroll
    for (int k = 0; k < KG; k++)
#pragma unroll
        for (int q = 0; q < 4; q++) acc[k][q] = 0.f;

    int p = beg;
    for (; p + 4 <= end; p += 4) {
        int s0 = d_esrc[p], s1 = d_esrc[p + 1], s2 = d_esrc[p + 2], s3 = d_esrc[p + 3];
        float w0 = (l < KG) ? __half2float(ewl[(size_t)p * KG + l]) : 0.f;
        float w1 = (l < KG) ? __half2float(ewl[(size_t)(p + 1) * KG + l]) : 0.f;
        float w2 = (l < KG) ? __half2float(ewl[(size_t)(p + 2) * KG + l]) : 0.f;
        float w3 = (l < KG) ? __half2float(ewl[(size_t)(p + 3) * KG + l]) : 0.f;
        const __half2* ha = h2b + (size_t)s0 * 64;
        const __half2* hb = h2b + (size_t)s1 * 64;
        const __half2* hc = h2b + (size_t)s2 * 64;
        const __half2* hd = h2b + (size_t)s3 * 64;
        float2 a0 = __half22float2(ha[l]), a1 = __half22float2(ha[l + 32]);
        float2 b0 = __half22float2(hb[l]), b1 = __half22float2(hb[l + 32]);
        float2 c0 = __half22float2(hc[l]), c1 = __half22float2(hc[l + 32]);
        float2 e0 = __half22float2(hd[l]), e1 = __half22float2(hd[l + 32]);
#pragma unroll
        for (int k = 0; k < KG; k++) {
            float k0 = __shfl_sync(0xffffffffu, w0, k);
            float k1 = __shfl_sync(0xffffffffu, w1, k);
            float k2 = __shfl_sync(0xffffffffu, w2, k);
            float k3 = __shfl_sync(0xffffffffu, w3, k);
            acc[k][0] = fmaf(k0, a0.x, fmaf(k1, b0.x, fmaf(k2, c0.x, fmaf(k3, e0.x, acc[k][0]))));
            acc[k][1] = fmaf(k0, a0.y, fmaf(k1, b0.y, fmaf(k2, c0.y, fmaf(k3, e0.y, acc[k][1]))));
            acc[k][2] = fmaf(k0, a1.x, fmaf(k1, b1.x, fmaf(k2, c1.x, fmaf(k3, e1.x, acc[k][2]))));
            acc[k][3] = fmaf(k0, a1.y, fmaf(k1, b1.y, fmaf(k2, c1.y, fmaf(k3, e1.y, acc[k][3]))));
        }
    }
    for (; p < end; p++) {
        int s0 = d_esrc[p];
        float w0 = (l < KG) ? __half2float(ewl[(size_t)p * KG + l]) : 0.f;
        const __half2* ha = h2b + (size_t)s0 * 64;
        float2 a0 = __half22float2(ha[l]);
        float2 a1 = __half22float2(ha[l + 32]);
#pragma unroll
        for (int k = 0; k < KG; k++) {
            float k0 = __shfl_sync(0xffffffffu, w0, k);
            acc[k][0] = fmaf(k0, a0.x, acc[k][0]);
            acc[k][1] = fmaf(k0, a0.y, acc[k][1]);
            acc[k][2] = fmaf(k0, a1.x, acc[k][2]);
            acc[k][3] = fmaf(k0, a1.y, acc[k][3]);
        }
    }
    float inv = __fdividef(1.f, fmaxf((float)(end - beg), 1.f));
    __half2* Sp2 = (__half2*)&d_Sh[(size_t)n * (KG * C)];
#pragma unroll
    for (int k = 0; k < KG; k++) {
        Sp2[k * 64 + l]      = __floats2half2_rn(acc[k][0] * inv, acc[k][1] * inv);
        Sp2[k * 64 + 32 + l] = __floats2half2_rn(acc[k][2] * inv, acc[k][3] * inv);
    }
}

// BN apply (half2-vectorized): reads half GEMM output, writes half copy
__global__ void k_bnapp(const float* __restrict__ gamma,
                        const float* __restrict__ beta,
                        __half* __restrict__ out_hlt, int relu) {
    int i = blockIdx.x * blockDim.x + threadIdx.x;   // over NN*64 half2
    if (i >= NN * (C / 2)) return;
    int c2 = i & 63;
    int c = c2 * 2;
    float m0 = d_bns[c]     / (float)NN;
    float m1 = d_bns[c + 1] / (float)NN;
    float v0 = d_bnq[c]     / (float)NN - m0 * m0;
    float v1 = d_bnq[c + 1] / (float)NN - m1 * m1;
    float2 hv = __half22float2(((const __half2*)d_hh)[i]);
    float r0 = (hv.x - m0) * rsqrtf(v0 + 1e-5f) * gamma[c]     + beta[c];
    float r1 = (hv.y - m1) * rsqrtf(v1 + 1e-5f) * gamma[c + 1] + beta[c + 1];
    if (relu) { r0 = fmaxf(r0, 0.f); r1 = fmaxf(r1, 0.f); }
    ((__half2*)out_hlt)[i] = __floats2half2_rn(r0, r1);
}

// fused: attention softmax + weighted node rep + pool + graph count
__global__ void k_nreppool(const float* __restrict__ x,
                           const int* __restrict__ batch) {
    int n = blockIdx.x;
    int c = threadIdx.x;
    __shared__ float p[5];
    __shared__ int gidx;
    if (c == 0) {
        float a[5], m = -1e30f;
#pragma unroll
        for (int t = 0; t < 5; t++) {
            a[t] = d_af[t * NN + n] + d_ab[t * NN + n];
            m = fmaxf(m, a[t]);
        }
        float s = 0.f;
#pragma unroll
        for (int t = 0; t < 5; t++) { a[t] = __expf(a[t] - m); s += a[t]; }
        float invs = __fdividef(1.f, s);
#pragma unroll
        for (int t = 0; t < 5; t++) p[t] = a[t] * invs;
        gidx = batch[n];
        atomicAdd(&d_cnt[gidx], 1.f);
    }
    __syncthreads();
    float r = p[0] * x[(size_t)n * C + c];
#pragma unroll
    for (int t = 1; t < 5; t++)
        r = fmaf(p[t], __half2float(d_hlth[t][(size_t)n * C + c]), r);
    atomicAdd(&d_hg[(size_t)gidx * C + c], r);
}

__global__ void k_pdiv() {
    int i = blockIdx.x * blockDim.x + threadIdx.x;
    if (i >= NB * C) return;
    float v = d_hg[i] / fmaxf(d_cnt[i / C], 1.f);
    d_hgh[i] = __float2half_rn(v);
}

__global__ void k_ln(const float* __restrict__ g, const float* __restrict__ b,
                     float* __restrict__ out) {
    int row = blockIdx.x, t = threadIdx.x;
    __shared__ float sm[NOUT];
    float v = d_z2[(size_t)row * NOUT + t];
    sm[t] = v;
    __syncthreads();
    for (int o = NOUT / 2; o > 0; o >>= 1) {
        if (t < o) sm[t] += sm[t + o];
        __syncthreads();
    }
    float mean = sm[0] / (float)NOUT;
    __syncthreads();
    float dv = v - mean;
    sm[t] = dv * dv;
    __syncthreads();
    for (int o = NOUT / 2; o > 0; o >>= 1) {
        if (t < o) sm[t] += sm[t + o];
        __syncthreads();
    }
    float var = sm[0] / (float)NOUT;
    out[(size_t)row * NOUT + t] = dv * rsqrtf(var + 1e-5f) * g[t] + b[t];
}

// ---------------- host ----------------
static float* symf(const void* s) {
    void* p = nullptr;
    cudaGetSymbolAddress(&p, s);
    return (float*)p;
}
static __half* symh(const void* s) {
    void* p = nullptr;
    cudaGetSymbolAddress(&p, s);
    return (__half*)p;
}
static int* symi(const void* s) {
    void* p = nullptr;
    cudaGetSymbolAddress(&p, s);
    return (int*)p;
}

extern "C" void kernel_launch(void* const* d_in, const int* in_sizes, int n_in,
                              void* d_out, int out_size) {
    const float* x     = (const float*)d_in[0];
    const int*   ei    = (const int*)d_in[1];
    const int*   src   = ei;
    const int*   dst   = ei + NE;
    const float* ea    = (const float*)d_in[2];
    const int*   batch = (const int*)d_in[3];
    const float* g     = (const float*)d_in[4];
    const float* root  = (const float*)d_in[5];
    const float* bias  = (const float*)d_in[6];
    const float* mu    = (const float*)d_in[7];
    const float* sigma = (const float*)d_in[8];
    const float* bng   = (const float*)d_in[9];
    const float* bnb   = (const float*)d_in[10];
    const float* wih   = (const float*)d_in[11];
    const float* whh   = (const float*)d_in[12];
    const float* bih   = (const float*)d_in[13];
    const float* bhh   = (const float*)d_in[14];
    const float* attw  = (const float*)d_in[15];
    const float* p1w   = (const float*)d_in[17];
    const float* p1b   = (const float*)d_in[18];
    const float* p2w   = (const float*)d_in[19];
    const float* p2b   = (const float*)d_in[20];
    const float* lng   = (const float*)d_in[21];
    const float* lnb   = (const float*)d_in[22];
    float* out = (float*)d_out;

    __half* hh    = symh(d_hh);
    __half* hlth  = symh(d_hlth);
    __half* Sh    = symh(d_Sh);
    __half* gth   = symh(d_gth);
    __half* rooth = symh(d_rooth);
    float*  af    = symf(d_af);
    float*  ab    = symf(d_ab);
    __half* hgh   = symh(d_hgh);
    __half* z1h   = symh(d_z1h);
    float*  z2    = symf(d_z2);
    __half* p1wh  = symh(d_p1wh);
    __half* p2wh  = symh(d_p2wh);
    int* indeg    = symi(d_indeg);

    const int TPB = 256;
    const dim3 blk(TPB);
    const int gridNC = (NN * C + TPB - 1) / TPB;
    const int rowsN  = (NN + 127) / 128;
    const int TLSTM_SMEM = 61440;

    static int smem_set = 0;
    if (!smem_set) {
        cudaFuncSetAttribute(tlstm, cudaFuncAttributeMaxDynamicSharedMemorySize,
                             TLSTM_SMEM);
        smem_set = 1;
    }

    // -------- CSR build + weight prep (ewall AFTER place: CSR-slot order) --
    k_zeroi<<<(NN + TPB - 1) / TPB, blk>>>(indeg, NN);
    k_degi<<<(NE + TPB - 1) / TPB, blk>>>(dst);
    k_scan<<<1, 1024>>>();
    k_place<<<(NE + TPB - 1) / TPB, blk>>>(src, dst);
    k_gt_h<<<(LL * C * KG * C + TPB - 1) / TPB, blk>>>(g, root);
    k_prep<<<(NN * C + TPB - 1) / TPB, blk>>>(wih, whh, bih, bhh, x, p1w, p2w);
    k_ewall<<<(NE + TPB - 1) / TPB, blk>>>(ea, mu, sigma);

    // -------- GMMConv layers (BN stats fused in GEMM epilogue) --------
    for (int i = 0; i < LL; i++) {
        k_sacc<<<(NN * 32 + TPB - 1) / TPB, blk>>>(hlth + (size_t)i * NN * C, i);
        GH gl = {Sh, gth + (size_t)i * C * KG * C,
                 hlth + (size_t)i * NN * C, rooth + (size_t)i * C * C,
                 hh, bias + i * C, KG * C, C};
        tgemm_h<false, true, true><<<dim3(1, rowsN), blk>>>(gl, NN, C);
        k_bnapp<<<(NN * (C / 2) + TPB - 1) / TPB, blk>>>(
            bng + i * C, bnb + i * C,
            hlth + (size_t)(i + 1) * NN * C, (i < LL - 1) ? 1 : 0);
    }

    // -------- bidirectional LSTM JumpingKnowledge (fused fp16 GEMM+cell) --
    k_zero02<<<(5 * NN + TPB - 1) / TPB, blk>>>(af, ab, 5 * NN);
    for (int s = 0; s < 5; s++) {
        int tf = s, tb = 4 - s;
        const __half* xf = hlth + (size_t)tf * NN * C;
        const __half* xb = hlth + (size_t)tb * NN * C;
        tlstm<<<dim3(H / 32, rowsN, 2), blk, TLSTM_SMEM>>>(xf, xb, attw,
                                                           (s > 0) ? H : 0, s);
    }

    // global mean pool (fused attention mix + scatter + count)
    k_zerog<<<(NB * C + TPB - 1) / TPB, blk>>>();
    k_nreppool<<<NN, C>>>(x, batch);
    k_pdiv<<<(NB * C + TPB - 1) / TPB, blk>>>();

    // MLP + LayerNorm (fp16 GEMMs)
    GH gp1 = {hgh, p1wh, nullptr, nullptr, z1h, p1b, C, 0};
    tgemm_h<true, true, false><<<dim3(NHID / 128, NB / 128), blk>>>(gp1, NB, NHID);
    GH gp2 = {z1h, p2wh, nullptr, nullptr, z2, p2b, NHID, 0};
    tgemm_h<false, false, false><<<dim3(NOUT / 128, NB / 128), blk>>>(gp2, NB, NOUT);
    k_ln<<<NB, NOUT>>>(lng, lnb, out);
}